// round 1
// baseline (speedup 1.0000x reference)
#include <cuda_runtime.h>
#include <math.h>

// ---------------------------------------------------------------------------
// Problem constants
// ---------------------------------------------------------------------------
#define NTOK   4096      // B*S
#define DDIM   256
#define DLF    768
#define ADIM   128
#define DSUM   1536
#define HIDD   64

typedef unsigned long long ull;

// ---------------------------------------------------------------------------
// f32x2 packed-FMA helpers (Blackwell: FFMA2 only reachable via PTX)
// ---------------------------------------------------------------------------
__device__ __forceinline__ ull pack2(float lo, float hi) {
    ull r; asm("mov.b64 %0, {%1,%2};" : "=l"(r) : "f"(lo), "f"(hi)); return r;
}
__device__ __forceinline__ void unpack2(ull p, float& lo, float& hi) {
    asm("mov.b64 {%0,%1}, %2;" : "=f"(lo), "=f"(hi) : "l"(p));
}
__device__ __forceinline__ ull ffma2(ull a, ull b, ull c) {
    ull d; asm("fma.rn.f32x2 %0, %1, %2, %3;" : "=l"(d) : "l"(a), "l"(b), "l"(c)); return d;
}
__device__ __forceinline__ float gelu_f(float v) {
    return 0.5f * v * (1.0f + erff(v * 0.70710678118654752440f));
}

// ---------------------------------------------------------------------------
// Scratch (single __device__ symbol; offsets in floats, all float4-aligned)
// ---------------------------------------------------------------------------
#define OFF_ADAPT   0u            // 4096*128
#define OFF_AM      524288u       // 128
#define OFF_PART    524416u       // 32*128
#define OFF_GATE    528512u       // 4096*5
#define OFF_WDYN    548992u       // 256*1536
#define OFF_BCAT    942208u       // 1536
#define OFF_MIX     943744u       // 4096*1536
#define OFF_TPSI    7235200u      // 4096*64
#define OFF_KA      7497344u      // 4096*256
#define OFF_CONCAT  8545920u      // 4096*1536
#define OFF_RESID   14837376u     // 4096*1536
#define OFF_H       21128832u     // 4096*64
#define OFF_COMB    21390976u     // 4096*1536
#define SCRATCH_FLOATS 27682432u

__device__ float g_scratch[SCRATCH_FLOATS];

// ---------------------------------------------------------------------------
// Generic tiled SGEMM: C[M,N] = A[M,K] @ B[K,N] + bias[N]  (optional GELU)
// Requires M%64==0, N%64==0, K%16==0 (true for every call here).
// BM=BN=64, BK=16, 256 threads, 4x4 micro-tile per thread, f32x2 FMAs.
// ---------------------------------------------------------------------------
template <bool GELU>
__global__ void __launch_bounds__(256)
sgemm_kernel(const float* __restrict__ A, const float* __restrict__ B,
             const float* __restrict__ bias, float* __restrict__ C,
             int M, int N, int K)
{
    __shared__ float As[16][65];   // padded, stored k-major -> [kk][m]
    __shared__ float Bs[16][64];   // [kk][n]

    const int tid = threadIdx.x;
    const int bm  = blockIdx.y << 6;
    const int bn  = blockIdx.x << 6;

    const int lar = tid >> 2;          // A-load row 0..63
    const int lak = (tid & 3) << 2;    // A-load k 0,4,8,12
    const int lbk = tid >> 4;          // B-load k 0..15
    const int lbc = (tid & 15) << 2;   // B-load col 0..60

    const int tm = (tid >> 4) << 2;    // micro-tile row 0..60
    const int tn = (tid & 15) << 2;    // micro-tile col 0..60

    ull acc[4][2];
#pragma unroll
    for (int i = 0; i < 4; i++) { acc[i][0] = 0ull; acc[i][1] = 0ull; }

    const float* Ap = A + (size_t)(bm + lar) * K + lak;
    const float* Bp = B + (size_t)lbk * N + bn + lbc;

    for (int k0 = 0; k0 < K; k0 += 16) {
        float4 a4 = *(const float4*)(Ap + k0);
        float4 b4 = *(const float4*)(Bp + (size_t)k0 * N);
        As[lak + 0][lar] = a4.x;
        As[lak + 1][lar] = a4.y;
        As[lak + 2][lar] = a4.z;
        As[lak + 3][lar] = a4.w;
        *(float4*)&Bs[lbk][lbc] = b4;
        __syncthreads();
#pragma unroll
        for (int kk = 0; kk < 16; kk++) {
            float4 bv = *(const float4*)&Bs[kk][tn];
            ull b01 = pack2(bv.x, bv.y);
            ull b23 = pack2(bv.z, bv.w);
#pragma unroll
            for (int i = 0; i < 4; i++) {
                float av = As[kk][tm + i];
                ull aa = pack2(av, av);
                acc[i][0] = ffma2(aa, b01, acc[i][0]);
                acc[i][1] = ffma2(aa, b23, acc[i][1]);
            }
        }
        __syncthreads();
    }

    float4 bb = *(const float4*)(bias + bn + tn);
#pragma unroll
    for (int i = 0; i < 4; i++) {
        float x0, x1, x2, x3;
        unpack2(acc[i][0], x0, x1);
        unpack2(acc[i][1], x2, x3);
        x0 += bb.x; x1 += bb.y; x2 += bb.z; x3 += bb.w;
        if (GELU) { x0 = gelu_f(x0); x1 = gelu_f(x1); x2 = gelu_f(x2); x3 = gelu_f(x3); }
        *(float4*)&C[(size_t)(bm + tm + i) * N + bn + tn] = make_float4(x0, x1, x2, x3);
    }
}

// ---------------------------------------------------------------------------
// am = mean over tokens of adapt  (deterministic two-stage reduction)
// ---------------------------------------------------------------------------
__global__ void colsum_part_kernel(const float* __restrict__ adapt, float* __restrict__ part)
{
    const int j = threadIdx.x;        // 0..127
    const int b = blockIdx.x;         // 0..31
    float s = 0.f;
#pragma unroll 8
    for (int r = 0; r < 128; r++) s += adapt[(size_t)(b * 128 + r) * ADIM + j];
    part[b * ADIM + j] = s;
}
__global__ void colsum_fin_kernel(const float* __restrict__ part, float* __restrict__ am)
{
    const int j = threadIdx.x;
    float s = 0.f;
#pragma unroll
    for (int b = 0; b < 32; b++) s += part[b * ADIM + j];
    am[j] = s * (1.0f / (float)NTOK);
}

// ---------------------------------------------------------------------------
// Dynamic weights: Wdyn[k, col] for col in [0,1536):
//   [0,256)   tok   : Wt  + am@Wt_a + bt_a
//   [256,512) chan  : Wc  + am@Wc_a + bc_a
//   [512+256e)expert: We_e + am@We_a_e + be_a_e
// grid 1536 x 256 threads; one thread per element; coalesced over col.
// ---------------------------------------------------------------------------
__global__ void dynw_kernel(const float* __restrict__ Wt,  const float* __restrict__ Wt_a, const float* __restrict__ bt_a,
                            const float* __restrict__ Wc,  const float* __restrict__ Wc_a, const float* __restrict__ bc_a,
                            const float* __restrict__ We,  const float* __restrict__ We_a, const float* __restrict__ be_a,
                            const float* __restrict__ am,  float* __restrict__ Wdyn)
{
    __shared__ float ams[ADIM];
    const int tid = threadIdx.x;
    if (tid < ADIM) ams[tid] = am[tid];
    __syncthreads();

    const int idx = blockIdx.x * 256 + tid;      // 0 .. 256*1536-1
    const int k   = idx / DSUM;
    const int col = idx - k * DSUM;

    const float *Wa, *ba, *base;
    int m;
    if (col < 256)      { m = k * 256 + col;          base = Wt;               Wa = Wt_a;                 ba = bt_a; }
    else if (col < 512) { m = k * 256 + (col - 256);  base = Wc;               Wa = Wc_a;                 ba = bc_a; }
    else {
        int e  = (col - 512) >> 8;
        int jj = (col - 512) & 255;
        m = k * 256 + jj;
        base = We + e * 65536;
        Wa   = We_a + e * 8388608;
        ba   = be_a + e * 65536;
    }
    float acc = base[m] + ba[m];
#pragma unroll 8
    for (int a = 0; a < ADIM; a++) acc = fmaf(ams[a], Wa[a * 65536 + m], acc);
    Wdyn[idx] = acc;
}

__global__ void bcat_kernel(const float* __restrict__ bt, const float* __restrict__ bc,
                            const float* __restrict__ be, float* __restrict__ bcat)
{
    int c = blockIdx.x * 256 + threadIdx.x;
    if (c >= DSUM) return;
    if (c < 256)      bcat[c] = bt[c];
    else if (c < 512) bcat[c] = bc[c - 256];
    else              bcat[c] = be[c - 512];   // be is [4,256] flat
}

// ---------------------------------------------------------------------------
// gate = softmax(adapt @ Wg + bg)  — one warp per token
// ---------------------------------------------------------------------------
__global__ void gate_kernel(const float* __restrict__ adapt, const float* __restrict__ Wg,
                            const float* __restrict__ bg, float* __restrict__ gate)
{
    __shared__ float wgs[ADIM * 5];
    __shared__ float bgs[5];
    const int tid = threadIdx.x;
    for (int i = tid; i < ADIM * 5; i += 256) wgs[i] = Wg[i];
    if (tid < 5) bgs[tid] = bg[tid];
    __syncthreads();

    const int warp = tid >> 5, lane = tid & 31;
    const int n = (blockIdx.x << 3) + warp;

    float4 a4 = *(const float4*)(adapt + (size_t)n * ADIM + lane * 4);
    float av[4] = { a4.x, a4.y, a4.z, a4.w };
    float l[5] = { 0, 0, 0, 0, 0 };
#pragma unroll
    for (int q = 0; q < 4; q++) {
        int a = lane * 4 + q;
#pragma unroll
        for (int j = 0; j < 5; j++) l[j] = fmaf(av[q], wgs[a * 5 + j], l[j]);
    }
#pragma unroll
    for (int off = 16; off; off >>= 1)
#pragma unroll
        for (int j = 0; j < 5; j++) l[j] += __shfl_xor_sync(0xffffffffu, l[j], off);

    if (lane == 0) {
        float mx = l[0];
#pragma unroll
        for (int j = 0; j < 5; j++) { l[j] += bgs[j]; }
        mx = fmaxf(fmaxf(fmaxf(l[0], l[1]), fmaxf(l[2], l[3])), l[4]);
        float s = 0.f;
#pragma unroll
        for (int j = 0; j < 5; j++) { l[j] = __expf(l[j] - mx); s += l[j]; }
        float inv = 1.0f / s;
#pragma unroll
        for (int j = 0; j < 5; j++) gate[n * 5 + j] = l[j] * inv;
    }
}

// ---------------------------------------------------------------------------
// Fused KA expert stage 1:
//   tpsi[n, j] = gelu( sum_{d,h} gelu(x[n,d]*Wphi[d,h]+bphi[d,h]) * Wpsi1[d*64+h, j] + bpsi1[j] )
// 16 tokens per block; loops d, never materializing phi in global memory.
// ---------------------------------------------------------------------------
__global__ void __launch_bounds__(256)
ka_kernel(const float* __restrict__ xf, const float* __restrict__ Wphi,
          const float* __restrict__ bphi, const float* __restrict__ Wpsi1,
          const float* __restrict__ bpsi1, float* __restrict__ tpsi)
{
    __shared__ float xs[16 * 256];     // x tile
    __shared__ float ph[16 * 65];      // phi for current d (padded)
    __shared__ float ws[64 * 64];      // Wpsi1 slab for current d

    const int tid  = threadIdx.x;
    const int base = blockIdx.x << 4;  // token base

    // stage x tile (4096 floats)
    {
        const float4* src = (const float4*)(xf + (size_t)base * 256);
        float4* dst = (float4*)xs;
#pragma unroll
        for (int r = 0; r < 4; r++) dst[tid + r * 256] = src[tid + r * 256];
    }
    __syncthreads();

    const int jq  = tid & 15;          // output quad (j = 4*jq)
    const int tok = tid >> 4;          // 0..15
    const int hph = tid & 63;          // phi h
    const int tq  = tid >> 6;          // 0..3 (phi token group)

    ull acc0 = 0ull, acc1 = 0ull;

    for (int d = 0; d < 256; d++) {
        // phi for this d: 16 tokens x 64 h
        float wp = __ldg(Wphi + (d << 6) + hph);
        float bp = __ldg(bphi + (d << 6) + hph);
#pragma unroll
        for (int ii = 0; ii < 4; ii++) {
            int t = (tq << 2) + ii;
            float v = fmaf(xs[(t << 8) + d], wp, bp);
            ph[t * 65 + hph] = gelu_f(v);
        }
        // stage Wpsi1 rows [d*64 .. d*64+63]
        {
            const float4* wsrc = (const float4*)(Wpsi1 + (size_t)d * 4096);
            float4* wdst = (float4*)ws;
#pragma unroll
            for (int r = 0; r < 4; r++) wdst[tid + r * 256] = wsrc[tid + r * 256];
        }
        __syncthreads();
#pragma unroll
        for (int h = 0; h < 64; h++) {
            float4 w4 = *(const float4*)&ws[(h << 6) + (jq << 2)];
            ull w01 = pack2(w4.x, w4.y);
            ull w23 = pack2(w4.z, w4.w);
            float p = ph[tok * 65 + h];
            ull pp = pack2(p, p);
            acc0 = ffma2(pp, w01, acc0);
            acc1 = ffma2(pp, w23, acc1);
        }
        __syncthreads();
    }

    float x0, x1, x2, x3;
    unpack2(acc0, x0, x1);
    unpack2(acc1, x2, x3);
    float4 b4 = *(const float4*)(bpsi1 + (jq << 2));
    x0 = gelu_f(x0 + b4.x); x1 = gelu_f(x1 + b4.y);
    x2 = gelu_f(x2 + b4.z); x3 = gelu_f(x3 + b4.w);
    *(float4*)(tpsi + (size_t)(base + tok) * HIDD + (jq << 2)) = make_float4(x0, x1, x2, x3);
}

// ---------------------------------------------------------------------------
// concat[n] = [tok, chan, moe, lf];  moe = sum_e gate_e*eo_e + gate_4*ka
// mix layout per token: [tok(256) | chan(256) | eo0..eo3 (4x256)]
// ---------------------------------------------------------------------------
__global__ void concat_kernel(const float* __restrict__ mix, const float* __restrict__ gate,
                              const float* __restrict__ ka, const float* __restrict__ lf,
                              float* __restrict__ concat)
{
    const int n = blockIdx.x;
    const int t = threadIdx.x;      // 0..383 (float4 lanes over 1536)
    __shared__ float g[5];
    if (t < 5) g[t] = gate[n * 5 + t];
    __syncthreads();

    const float4* mx = (const float4*)(mix + (size_t)n * DSUM);
    float4 out;
    if (t < 128) {
        out = mx[t];                                // tok / chan passthrough
    } else if (t < 192) {
        int dq = t - 128;                           // 0..63 over D
        float4 e0 = mx[128 + dq], e1 = mx[192 + dq], e2 = mx[256 + dq], e3 = mx[320 + dq];
        float4 k4 = ((const float4*)(ka + (size_t)n * DDIM))[dq];
        out.x = g[0]*e0.x + g[1]*e1.x + g[2]*e2.x + g[3]*e3.x + g[4]*k4.x;
        out.y = g[0]*e0.y + g[1]*e1.y + g[2]*e2.y + g[3]*e3.y + g[4]*k4.y;
        out.z = g[0]*e0.z + g[1]*e1.z + g[2]*e2.z + g[3]*e3.z + g[4]*k4.z;
        out.w = g[0]*e0.w + g[1]*e1.w + g[2]*e2.w + g[3]*e3.w + g[4]*k4.w;
    } else {
        out = ((const float4*)(lf + (size_t)n * DLF))[t - 192];
    }
    ((float4*)(concat + (size_t)n * DSUM))[t] = out;
}

// ---------------------------------------------------------------------------
// combine: cw = softmax(h @ W2 + b2); comb = cw[sec]*concat + resid
// one warp per token
// ---------------------------------------------------------------------------
__global__ void combine_kernel(const float* __restrict__ h, const float* __restrict__ W2,
                               const float* __restrict__ b2, const float* __restrict__ concat,
                               const float* __restrict__ resid, float* __restrict__ comb)
{
    __shared__ float w2s[256];
    const int tid = threadIdx.x;
    w2s[tid] = W2[tid];
    __syncthreads();

    const int warp = tid >> 5, lane = tid & 31;
    const int n = (blockIdx.x << 3) + warp;

    float2 hv = *(const float2*)(h + (size_t)n * HIDD + lane * 2);
    const int a0 = lane * 2, a1 = lane * 2 + 1;
    float l0 = hv.x * w2s[a0*4+0] + hv.y * w2s[a1*4+0];
    float l1 = hv.x * w2s[a0*4+1] + hv.y * w2s[a1*4+1];
    float l2 = hv.x * w2s[a0*4+2] + hv.y * w2s[a1*4+2];
    float l3 = hv.x * w2s[a0*4+3] + hv.y * w2s[a1*4+3];
#pragma unroll
    for (int off = 16; off; off >>= 1) {
        l0 += __shfl_xor_sync(0xffffffffu, l0, off);
        l1 += __shfl_xor_sync(0xffffffffu, l1, off);
        l2 += __shfl_xor_sync(0xffffffffu, l2, off);
        l3 += __shfl_xor_sync(0xffffffffu, l3, off);
    }
    l0 += __ldg(b2 + 0); l1 += __ldg(b2 + 1); l2 += __ldg(b2 + 2); l3 += __ldg(b2 + 3);
    float mx = fmaxf(fmaxf(l0, l1), fmaxf(l2, l3));
    float e0 = __expf(l0 - mx), e1 = __expf(l1 - mx), e2 = __expf(l2 - mx), e3 = __expf(l3 - mx);
    float inv = 1.0f / (e0 + e1 + e2 + e3);
    float cw0 = e0 * inv, cw1 = e1 * inv, cw2 = e2 * inv, cw3 = e3 * inv;

    const float4* cc = (const float4*)(concat + (size_t)n * DSUM);
    const float4* rr = (const float4*)(resid  + (size_t)n * DSUM);
    float4* oo = (float4*)(comb + (size_t)n * DSUM);
#pragma unroll
    for (int q = 0; q < 12; q++) {
        int c4 = lane + (q << 5);     // 0..383
        float w = (c4 < 64) ? cw0 : (c4 < 128) ? cw1 : (c4 < 192) ? cw2 : cw3;
        float4 cv = cc[c4], rv = rr[c4];
        oo[c4] = make_float4(fmaf(w, cv.x, rv.x), fmaf(w, cv.y, rv.y),
                             fmaf(w, cv.z, rv.z), fmaf(w, cv.w, rv.w));
    }
}

// ---------------------------------------------------------------------------
// Host launcher
// ---------------------------------------------------------------------------
extern "C" void kernel_launch(void* const* d_in, const int* in_sizes, int n_in,
                              void* d_out, int out_size)
{
    (void)in_sizes; (void)n_in; (void)out_size;

    const float* x      = (const float*)d_in[0];
    const float* lf     = (const float*)d_in[1];
    const float* W_feat = (const float*)d_in[2];
    const float* b_feat = (const float*)d_in[3];
    const float* Wt     = (const float*)d_in[4];
    const float* bt     = (const float*)d_in[5];
    const float* Wt_a   = (const float*)d_in[6];
    const float* bt_a   = (const float*)d_in[7];
    const float* Wc     = (const float*)d_in[8];
    const float* bc     = (const float*)d_in[9];
    const float* Wc_a   = (const float*)d_in[10];
    const float* bc_a   = (const float*)d_in[11];
    const float* We     = (const float*)d_in[12];
    const float* be     = (const float*)d_in[13];
    const float* We_a   = (const float*)d_in[14];
    const float* be_a   = (const float*)d_in[15];
    const float* Wg     = (const float*)d_in[16];
    const float* bg     = (const float*)d_in[17];
    const float* Wphi   = (const float*)d_in[18];
    const float* bphi   = (const float*)d_in[19];
    const float* Wpsi1  = (const float*)d_in[20];
    const float* bpsi1  = (const float*)d_in[21];
    const float* Wpsi2  = (const float*)d_in[22];
    const float* bpsi2  = (const float*)d_in[23];
    const float* Wres   = (const float*)d_in[24];
    const float* bres   = (const float*)d_in[25];
    const float* W1     = (const float*)d_in[26];
    const float* b1     = (const float*)d_in[27];
    const float* W2     = (const float*)d_in[28];
    const float* b2     = (const float*)d_in[29];
    const float* Wo     = (const float*)d_in[30];
    const float* bo     = (const float*)d_in[31];
    float* out = (float*)d_out;

    float* s = nullptr;
    cudaGetSymbolAddress((void**)&s, g_scratch);
    float* adapt  = s + OFF_ADAPT;
    float* am     = s + OFF_AM;
    float* part   = s + OFF_PART;
    float* gate   = s + OFF_GATE;
    float* Wdyn   = s + OFF_WDYN;
    float* bcat   = s + OFF_BCAT;
    float* mix    = s + OFF_MIX;
    float* tpsi   = s + OFF_TPSI;
    float* ka     = s + OFF_KA;
    float* concat = s + OFF_CONCAT;
    float* resid  = s + OFF_RESID;
    float* hbuf   = s + OFF_H;
    float* comb   = s + OFF_COMB;

    // 1. adapt = x @ W_feat + b_feat          [4096,128]
    sgemm_kernel<false><<<dim3(ADIM / 64, NTOK / 64), 256>>>(x, W_feat, b_feat, adapt, NTOK, ADIM, DDIM);
    // 2. am = mean(adapt, axis=0)
    colsum_part_kernel<<<32, 128>>>(adapt, part);
    colsum_fin_kernel<<<1, 128>>>(part, am);
    // 3. dynamic weights (tok|chan|4 experts) -> [256,1536], plus bias concat
    dynw_kernel<<<DSUM, 256>>>(Wt, Wt_a, bt_a, Wc, Wc_a, bc_a, We, We_a, be_a, am, Wdyn);
    bcat_kernel<<<6, 256>>>(bt, bc, be, bcat);
    // 4. gate softmax
    gate_kernel<<<NTOK / 8, 256>>>(adapt, Wg, bg, gate);
    // 5. mix = x @ Wdyn + bcat                [4096,1536]
    sgemm_kernel<false><<<dim3(DSUM / 64, NTOK / 64), 256>>>(x, Wdyn, bcat, mix, NTOK, DSUM, DDIM);
    // 6. KA stage 1 (fused phi -> psi1 -> gelu)  [4096,64]
    ka_kernel<<<NTOK / 16, 256>>>(x, Wphi, bphi, Wpsi1, bpsi1, tpsi);
    // 7. ka = tpsi @ Wpsi2 + bpsi2            [4096,256]
    sgemm_kernel<false><<<dim3(DDIM / 64, NTOK / 64), 256>>>(tpsi, Wpsi2, bpsi2, ka, NTOK, DDIM, HIDD);
    // 8. concat = [tok, chan, moe, lf]        [4096,1536]
    concat_kernel<<<NTOK, 384>>>(mix, gate, ka, lf, concat);
    // 9. residual = concat @ Wres + bres      [4096,1536]  (biggest GEMM)
    sgemm_kernel<false><<<dim3(DSUM / 64, NTOK / 64), 256>>>(concat, Wres, bres, resid, NTOK, DSUM, DSUM);
    // 10. h = gelu(concat @ W1 + b1)          [4096,64]
    sgemm_kernel<true><<<dim3(HIDD / 64, NTOK / 64), 256>>>(concat, W1, b1, hbuf, NTOK, HIDD, DSUM);
    // 11. combine: cw softmax + weighted concat + residual
    combine_kernel<<<NTOK / 8, 256>>>(hbuf, W2, b2, concat, resid, comb);
    // 12. out = comb @ Wo + bo                [4096,256]
    sgemm_kernel<false><<<dim3(DDIM / 64, NTOK / 64), 256>>>(comb, Wo, bo, out, NTOK, DDIM, DSUM);
}

// round 2
// speedup vs baseline: 1.4019x; 1.4019x over previous
#include <cuda_runtime.h>
#include <math.h>

// ---------------------------------------------------------------------------
// Problem constants
// ---------------------------------------------------------------------------
#define NTOK   4096      // B*S
#define DDIM   256
#define DLF    768
#define ADIM   128
#define DSUM   1536
#define HIDD   64

typedef unsigned long long ull;

// ---------------------------------------------------------------------------
// f32x2 packed-FMA helpers
// ---------------------------------------------------------------------------
__device__ __forceinline__ ull pack2(float lo, float hi) {
    ull r; asm("mov.b64 %0, {%1,%2};" : "=l"(r) : "f"(lo), "f"(hi)); return r;
}
__device__ __forceinline__ void unpack2(ull p, float& lo, float& hi) {
    asm("mov.b64 {%0,%1}, %2;" : "=f"(lo), "=f"(hi) : "l"(p));
}
__device__ __forceinline__ ull ffma2(ull a, ull b, ull c) {
    ull d; asm("fma.rn.f32x2 %0, %1, %2, %3;" : "=l"(d) : "l"(a), "l"(b), "l"(c)); return d;
}
__device__ __forceinline__ float gelu_f(float v) {
    return 0.5f * v * (1.0f + erff(v * 0.70710678118654752440f));
}

// ---------------------------------------------------------------------------
// Scratch
// ---------------------------------------------------------------------------
#define OFF_ADAPT   0u            // 4096*128
#define OFF_AM      524288u       // 128
#define OFF_PART    524416u       // 32*128
#define OFF_GATE    528512u       // 4096*5
#define OFF_WDYN    548992u       // 256*1536
#define OFF_BCAT    942208u       // 1536
#define OFF_MIX     943744u       // 4096*1536
#define OFF_TPSI    7235200u      // 4096*64
#define OFF_KA      7497344u      // 4096*256
#define OFF_CONCAT  8545920u      // 4096*1536
#define OFF_RESID   14837376u     // 4096*1536
#define OFF_H       21128832u     // 4096*64
#define OFF_COMB    21390976u     // 4096*1536
#define OFF_KAPART  27682432u     // 2*4096*64
#define SCRATCH_FLOATS 28206720u

__device__ float g_scratch[SCRATCH_FLOATS];

// ---------------------------------------------------------------------------
// Templated tiled SGEMM: C[M,N] = A[M,K] @ B[K,N] + bias[N] (optional GELU)
// BM,BN in {64,128}; BK=16; 256 threads. Micro-tile = (BM/16)x(BN/16) split
// into 4-wide quads at offsets {0,64}. Requires M%BM==0, N%BN==0, K%16==0.
// ---------------------------------------------------------------------------
template <int BM, int BN, bool GELU>
__global__ void __launch_bounds__(256, 2)
sgemm_t(const float* __restrict__ A, const float* __restrict__ B,
        const float* __restrict__ bias, float* __restrict__ C,
        int M, int N, int K)
{
    constexpr int RQ = BM / 64;     // row quads per thread
    constexpr int CQ = BN / 64;     // col quads per thread
    __shared__ float As[16][BM + 4];   // k-major, padded (row bytes %16 == 0)
    __shared__ float Bs[16][BN];

    const int tid = threadIdx.x;
    const int bm  = blockIdx.y * BM;
    const int bn  = blockIdx.x * BN;

    const int ar = tid >> 2;            // A-load row (and +64)
    const int ak = (tid & 3) << 2;      // A-load k base
    const int bk = tid >> 4;            // B-load k
    const int bc = (tid & 15) << 2;     // B-load col base (and +64)

    const int tr = (tid >> 4) << 2;     // micro-tile row quad base
    const int tc = (tid & 15) << 2;     // micro-tile col quad base

    ull acc[RQ][4][2 * CQ];
#pragma unroll
    for (int q = 0; q < RQ; q++)
#pragma unroll
        for (int i = 0; i < 4; i++)
#pragma unroll
            for (int j = 0; j < 2 * CQ; j++) acc[q][i][j] = 0ull;

    for (int k0 = 0; k0 < K; k0 += 16) {
#pragma unroll
        for (int q = 0; q < RQ; q++) {
            float4 a4 = *(const float4*)(A + (size_t)(bm + ar + 64 * q) * K + k0 + ak);
            As[ak + 0][ar + 64 * q] = a4.x;
            As[ak + 1][ar + 64 * q] = a4.y;
            As[ak + 2][ar + 64 * q] = a4.z;
            As[ak + 3][ar + 64 * q] = a4.w;
        }
#pragma unroll
        for (int p = 0; p < CQ; p++) {
            *(float4*)&Bs[bk][bc + 64 * p] =
                *(const float4*)(B + (size_t)(k0 + bk) * N + bn + bc + 64 * p);
        }
        __syncthreads();
#pragma unroll
        for (int kk = 0; kk < 16; kk++) {
            ull bp[CQ][2];
#pragma unroll
            for (int p = 0; p < CQ; p++) {
                float4 bv = *(const float4*)&Bs[kk][tc + 64 * p];
                bp[p][0] = pack2(bv.x, bv.y);
                bp[p][1] = pack2(bv.z, bv.w);
            }
#pragma unroll
            for (int q = 0; q < RQ; q++) {
                float4 av = *(const float4*)&As[kk][tr + 64 * q];
                float aa[4] = { av.x, av.y, av.z, av.w };
#pragma unroll
                for (int i = 0; i < 4; i++) {
                    ull ap = pack2(aa[i], aa[i]);
#pragma unroll
                    for (int p = 0; p < CQ; p++) {
                        acc[q][i][2 * p + 0] = ffma2(ap, bp[p][0], acc[q][i][2 * p + 0]);
                        acc[q][i][2 * p + 1] = ffma2(ap, bp[p][1], acc[q][i][2 * p + 1]);
                    }
                }
            }
        }
        __syncthreads();
    }

#pragma unroll
    for (int p = 0; p < CQ; p++) {
        float4 bb = *(const float4*)(bias + bn + tc + 64 * p);
#pragma unroll
        for (int q = 0; q < RQ; q++)
#pragma unroll
            for (int i = 0; i < 4; i++) {
                float x0, x1, x2, x3;
                unpack2(acc[q][i][2 * p + 0], x0, x1);
                unpack2(acc[q][i][2 * p + 1], x2, x3);
                x0 += bb.x; x1 += bb.y; x2 += bb.z; x3 += bb.w;
                if (GELU) { x0 = gelu_f(x0); x1 = gelu_f(x1); x2 = gelu_f(x2); x3 = gelu_f(x3); }
                *(float4*)&C[(size_t)(bm + tr + i + 64 * q) * N + bn + tc + 64 * p] =
                    make_float4(x0, x1, x2, x3);
            }
    }
}

// ---------------------------------------------------------------------------
// am = mean over tokens of adapt (deterministic two-stage reduction)
// ---------------------------------------------------------------------------
__global__ void colsum_part_kernel(const float* __restrict__ adapt, float* __restrict__ part)
{
    const int j = threadIdx.x;
    const int b = blockIdx.x;
    float s = 0.f;
#pragma unroll 8
    for (int r = 0; r < 128; r++) s += adapt[(size_t)(b * 128 + r) * ADIM + j];
    part[b * ADIM + j] = s;
}
__global__ void colsum_fin_kernel(const float* __restrict__ part, float* __restrict__ am)
{
    const int j = threadIdx.x;
    float s = 0.f;
#pragma unroll
    for (int b = 0; b < 32; b++) s += part[b * ADIM + j];
    am[j] = s * (1.0f / (float)NTOK);
}

// ---------------------------------------------------------------------------
// Dynamic weights (float4-vectorized, memory-bound): Wdyn[k, col], col in [0,1536)
// ---------------------------------------------------------------------------
__global__ void dynw_kernel(const float* __restrict__ Wt,  const float* __restrict__ Wt_a, const float* __restrict__ bt_a,
                            const float* __restrict__ Wc,  const float* __restrict__ Wc_a, const float* __restrict__ bc_a,
                            const float* __restrict__ We,  const float* __restrict__ We_a, const float* __restrict__ be_a,
                            const float* __restrict__ am,  float* __restrict__ Wdyn)
{
    __shared__ float ams[ADIM];
    const int tid = threadIdx.x;
    if (tid < ADIM) ams[tid] = am[tid];
    __syncthreads();

    const int idx4 = blockIdx.x * 256 + tid;      // 0 .. 98303 (float4 over 256x1536)
    const int k    = idx4 / 384;
    const int c4   = (idx4 - k * 384) * 4;

    const float *Wa, *ba, *base;
    int m;
    if (c4 < 256)      { m = k * 256 + c4;          base = Wt; Wa = Wt_a; ba = bt_a; }
    else if (c4 < 512) { m = k * 256 + (c4 - 256);  base = Wc; Wa = Wc_a; ba = bc_a; }
    else {
        int e  = (c4 - 512) >> 8;
        int jj = (c4 - 512) & 255;
        m = k * 256 + jj;
        base = We + e * 65536;
        Wa   = We_a + (size_t)e * 8388608u;
        ba   = be_a + e * 65536;
    }
    float4 acc = *(const float4*)(base + m);
    float4 b4  = *(const float4*)(ba + m);
    acc.x += b4.x; acc.y += b4.y; acc.z += b4.z; acc.w += b4.w;
#pragma unroll 4
    for (int a = 0; a < ADIM; a++) {
        float s = ams[a];
        float4 w = *(const float4*)(Wa + (size_t)a * 65536 + m);
        acc.x = fmaf(s, w.x, acc.x);
        acc.y = fmaf(s, w.y, acc.y);
        acc.z = fmaf(s, w.z, acc.z);
        acc.w = fmaf(s, w.w, acc.w);
    }
    *(float4*)(Wdyn + (size_t)idx4 * 4) = acc;
}

__global__ void bcat_kernel(const float* __restrict__ bt, const float* __restrict__ bc,
                            const float* __restrict__ be, float* __restrict__ bcat)
{
    int c = blockIdx.x * 256 + threadIdx.x;
    if (c >= DSUM) return;
    if (c < 256)      bcat[c] = bt[c];
    else if (c < 512) bcat[c] = bc[c - 256];
    else              bcat[c] = be[c - 512];
}

// ---------------------------------------------------------------------------
// gate = softmax(adapt @ Wg + bg) — one warp per token
// ---------------------------------------------------------------------------
__global__ void gate_kernel(const float* __restrict__ adapt, const float* __restrict__ Wg,
                            const float* __restrict__ bg, float* __restrict__ gate)
{
    __shared__ float wgs[ADIM * 5];
    __shared__ float bgs[5];
    const int tid = threadIdx.x;
    for (int i = tid; i < ADIM * 5; i += 256) wgs[i] = Wg[i];
    if (tid < 5) bgs[tid] = bg[tid];
    __syncthreads();

    const int warp = tid >> 5, lane = tid & 31;
    const int n = (blockIdx.x << 3) + warp;

    float4 a4 = *(const float4*)(adapt + (size_t)n * ADIM + lane * 4);
    float av[4] = { a4.x, a4.y, a4.z, a4.w };
    float l[5] = { 0, 0, 0, 0, 0 };
#pragma unroll
    for (int q = 0; q < 4; q++) {
        int a = lane * 4 + q;
#pragma unroll
        for (int j = 0; j < 5; j++) l[j] = fmaf(av[q], wgs[a * 5 + j], l[j]);
    }
#pragma unroll
    for (int off = 16; off; off >>= 1)
#pragma unroll
        for (int j = 0; j < 5; j++) l[j] += __shfl_xor_sync(0xffffffffu, l[j], off);

    if (lane == 0) {
#pragma unroll
        for (int j = 0; j < 5; j++) l[j] += bgs[j];
        float mx = fmaxf(fmaxf(fmaxf(l[0], l[1]), fmaxf(l[2], l[3])), l[4]);
        float s = 0.f;
#pragma unroll
        for (int j = 0; j < 5; j++) { l[j] = __expf(l[j] - mx); s += l[j]; }
        float inv = 1.0f / s;
#pragma unroll
        for (int j = 0; j < 5; j++) gate[n * 5 + j] = l[j] * inv;
    }
}

// ---------------------------------------------------------------------------
// KA expert, stage 1 partials:
//   part[half][n][j] = sum_{d in half, h} gelu(x[n,d]*Wphi[d,h]+bphi[d,h]) * Wpsi1[d*64+h, j]
// Block: 64 tokens x 128-d half. 128 blocks, 256 threads.
// ---------------------------------------------------------------------------
__global__ void __launch_bounds__(256)
ka_part_kernel(const float* __restrict__ xf, const float* __restrict__ Wphi,
               const float* __restrict__ bphi, const float* __restrict__ Wpsi1,
               float* __restrict__ part)
{
    __shared__ float xs[32][65];     // 32 d x 64 tok (transposed chunk)
    __shared__ float ph[64][68];     // 64 h x 64 tok (padded for float4)
    __shared__ float ws[64 * 64];    // Wpsi1 slab for current d

    const int tid   = threadIdx.x;
    const int ttile = blockIdx.x >> 1;
    const int half  = blockIdx.x & 1;
    const int t0    = ttile << 6;
    const int dbase = half << 7;

    const int tr = (tid >> 4) << 2;  // token quad base
    const int tc = (tid & 15) << 2;  // col quad base
    const int h  = tid & 63;
    const int tg = (tid >> 6) << 4;  // phi token base

    const int xtok = tid >> 2;       // 0..63
    const int xdq  = (tid & 3) << 3; // 0,8,16,24

    ull acc[4][2];
#pragma unroll
    for (int i = 0; i < 4; i++) { acc[i][0] = 0ull; acc[i][1] = 0ull; }

    for (int chunk = 0; chunk < 4; chunk++) {
        const int d0 = dbase + (chunk << 5);
        // stage xs (transposed)
        {
            const float* xp = xf + (size_t)(t0 + xtok) * 256 + d0 + xdq;
            float4 v0 = *(const float4*)(xp);
            float4 v1 = *(const float4*)(xp + 4);
            xs[xdq + 0][xtok] = v0.x; xs[xdq + 1][xtok] = v0.y;
            xs[xdq + 2][xtok] = v0.z; xs[xdq + 3][xtok] = v0.w;
            xs[xdq + 4][xtok] = v1.x; xs[xdq + 5][xtok] = v1.y;
            xs[xdq + 6][xtok] = v1.z; xs[xdq + 7][xtok] = v1.w;
        }
        __syncthreads();

        for (int dd = 0; dd < 32; dd++) {
            const int d = d0 + dd;
            // phi for this d
            float wp = __ldg(Wphi + (d << 6) + h);
            float bp = __ldg(bphi + (d << 6) + h);
#pragma unroll
            for (int t2 = 0; t2 < 16; t2++) {
                int t = tg + t2;
                ph[h][t] = gelu_f(fmaf(xs[dd][t], wp, bp));
            }
            // stage Wpsi1 slab for this d
            {
                const float4* wsrc = (const float4*)(Wpsi1 + ((size_t)d << 12));
                float4* wdst = (float4*)ws;
#pragma unroll
                for (int r = 0; r < 4; r++) wdst[tid + (r << 8)] = wsrc[tid + (r << 8)];
            }
            __syncthreads();
#pragma unroll
            for (int hh = 0; hh < 64; hh++) {
                float4 pv = *(const float4*)&ph[hh][tr];
                float4 wv = *(const float4*)&ws[(hh << 6) + tc];
                ull w01 = pack2(wv.x, wv.y);
                ull w23 = pack2(wv.z, wv.w);
                float pa[4] = { pv.x, pv.y, pv.z, pv.w };
#pragma unroll
                for (int i = 0; i < 4; i++) {
                    ull pp = pack2(pa[i], pa[i]);
                    acc[i][0] = ffma2(pp, w01, acc[i][0]);
                    acc[i][1] = ffma2(pp, w23, acc[i][1]);
                }
            }
            __syncthreads();
        }
    }

    float* pout = part + ((size_t)half * NTOK + t0) * HIDD;
#pragma unroll
    for (int i = 0; i < 4; i++) {
        float x0, x1, x2, x3;
        unpack2(acc[i][0], x0, x1);
        unpack2(acc[i][1], x2, x3);
        *(float4*)(pout + (size_t)(tr + i) * HIDD + tc) = make_float4(x0, x1, x2, x3);
    }
}

// tpsi = gelu(part0 + part1 + bpsi1)
__global__ void ka_finish_kernel(const float* __restrict__ part,
                                 const float* __restrict__ bpsi1,
                                 float* __restrict__ tpsi)
{
    const int idx = blockIdx.x * 256 + threadIdx.x;   // float4 index, 65536 total
    const int jq = idx & 15;
    float4 a = ((const float4*)part)[idx];
    float4 b = ((const float4*)part)[65536 + idx];
    float4 bb = ((const float4*)bpsi1)[jq];
    float4 o;
    o.x = gelu_f(a.x + b.x + bb.x);
    o.y = gelu_f(a.y + b.y + bb.y);
    o.z = gelu_f(a.z + b.z + bb.z);
    o.w = gelu_f(a.w + b.w + bb.w);
    ((float4*)tpsi)[idx] = o;
}

// ---------------------------------------------------------------------------
// concat[n] = [tok, chan, moe, lf];  moe = sum_e gate_e*eo_e + gate_4*ka
// ---------------------------------------------------------------------------
__global__ void concat_kernel(const float* __restrict__ mix, const float* __restrict__ gate,
                              const float* __restrict__ ka, const float* __restrict__ lf,
                              float* __restrict__ concat)
{
    const int n = blockIdx.x;
    const int t = threadIdx.x;
    __shared__ float g[5];
    if (t < 5) g[t] = gate[n * 5 + t];
    __syncthreads();

    const float4* mx = (const float4*)(mix + (size_t)n * DSUM);
    float4 out;
    if (t < 128) {
        out = mx[t];
    } else if (t < 192) {
        int dq = t - 128;
        float4 e0 = mx[128 + dq], e1 = mx[192 + dq], e2 = mx[256 + dq], e3 = mx[320 + dq];
        float4 k4 = ((const float4*)(ka + (size_t)n * DDIM))[dq];
        out.x = g[0]*e0.x + g[1]*e1.x + g[2]*e2.x + g[3]*e3.x + g[4]*k4.x;
        out.y = g[0]*e0.y + g[1]*e1.y + g[2]*e2.y + g[3]*e3.y + g[4]*k4.y;
        out.z = g[0]*e0.z + g[1]*e1.z + g[2]*e2.z + g[3]*e3.z + g[4]*k4.z;
        out.w = g[0]*e0.w + g[1]*e1.w + g[2]*e2.w + g[3]*e3.w + g[4]*k4.w;
    } else {
        out = ((const float4*)(lf + (size_t)n * DLF))[t - 192];
    }
    ((float4*)(concat + (size_t)n * DSUM))[t] = out;
}

// ---------------------------------------------------------------------------
// combine: cw = softmax(h @ W2 + b2); comb = cw[sec]*concat + resid
// ---------------------------------------------------------------------------
__global__ void combine_kernel(const float* __restrict__ h, const float* __restrict__ W2,
                               const float* __restrict__ b2, const float* __restrict__ concat,
                               const float* __restrict__ resid, float* __restrict__ comb)
{
    __shared__ float w2s[256];
    const int tid = threadIdx.x;
    w2s[tid] = W2[tid];
    __syncthreads();

    const int warp = tid >> 5, lane = tid & 31;
    const int n = (blockIdx.x << 3) + warp;

    float2 hv = *(const float2*)(h + (size_t)n * HIDD + lane * 2);
    const int a0 = lane * 2, a1 = lane * 2 + 1;
    float l0 = hv.x * w2s[a0*4+0] + hv.y * w2s[a1*4+0];
    float l1 = hv.x * w2s[a0*4+1] + hv.y * w2s[a1*4+1];
    float l2 = hv.x * w2s[a0*4+2] + hv.y * w2s[a1*4+2];
    float l3 = hv.x * w2s[a0*4+3] + hv.y * w2s[a1*4+3];
#pragma unroll
    for (int off = 16; off; off >>= 1) {
        l0 += __shfl_xor_sync(0xffffffffu, l0, off);
        l1 += __shfl_xor_sync(0xffffffffu, l1, off);
        l2 += __shfl_xor_sync(0xffffffffu, l2, off);
        l3 += __shfl_xor_sync(0xffffffffu, l3, off);
    }
    l0 += __ldg(b2 + 0); l1 += __ldg(b2 + 1); l2 += __ldg(b2 + 2); l3 += __ldg(b2 + 3);
    float mx = fmaxf(fmaxf(l0, l1), fmaxf(l2, l3));
    float e0 = __expf(l0 - mx), e1 = __expf(l1 - mx), e2 = __expf(l2 - mx), e3 = __expf(l3 - mx);
    float inv = 1.0f / (e0 + e1 + e2 + e3);
    float cw0 = e0 * inv, cw1 = e1 * inv, cw2 = e2 * inv, cw3 = e3 * inv;

    const float4* cc = (const float4*)(concat + (size_t)n * DSUM);
    const float4* rr = (const float4*)(resid  + (size_t)n * DSUM);
    float4* oo = (float4*)(comb + (size_t)n * DSUM);
#pragma unroll
    for (int q = 0; q < 12; q++) {
        int c4 = lane + (q << 5);
        float w = (c4 < 64) ? cw0 : (c4 < 128) ? cw1 : (c4 < 192) ? cw2 : cw3;
        float4 cv = cc[c4], rv = rr[c4];
        oo[c4] = make_float4(fmaf(w, cv.x, rv.x), fmaf(w, cv.y, rv.y),
                             fmaf(w, cv.z, rv.z), fmaf(w, cv.w, rv.w));
    }
}

// ---------------------------------------------------------------------------
// Host launcher
// ---------------------------------------------------------------------------
extern "C" void kernel_launch(void* const* d_in, const int* in_sizes, int n_in,
                              void* d_out, int out_size)
{
    (void)in_sizes; (void)n_in; (void)out_size;

    const float* x      = (const float*)d_in[0];
    const float* lf     = (const float*)d_in[1];
    const float* W_feat = (const float*)d_in[2];
    const float* b_feat = (const float*)d_in[3];
    const float* Wt     = (const float*)d_in[4];
    const float* bt     = (const float*)d_in[5];
    const float* Wt_a   = (const float*)d_in[6];
    const float* bt_a   = (const float*)d_in[7];
    const float* Wc     = (const float*)d_in[8];
    const float* bc     = (const float*)d_in[9];
    const float* Wc_a   = (const float*)d_in[10];
    const float* bc_a   = (const float*)d_in[11];
    const float* We     = (const float*)d_in[12];
    const float* be     = (const float*)d_in[13];
    const float* We_a   = (const float*)d_in[14];
    const float* be_a   = (const float*)d_in[15];
    const float* Wg     = (const float*)d_in[16];
    const float* bg     = (const float*)d_in[17];
    const float* Wphi   = (const float*)d_in[18];
    const float* bphi   = (const float*)d_in[19];
    const float* Wpsi1  = (const float*)d_in[20];
    const float* bpsi1  = (const float*)d_in[21];
    const float* Wpsi2  = (const float*)d_in[22];
    const float* bpsi2  = (const float*)d_in[23];
    const float* Wres   = (const float*)d_in[24];
    const float* bres   = (const float*)d_in[25];
    const float* W1     = (const float*)d_in[26];
    const float* b1     = (const float*)d_in[27];
    const float* W2     = (const float*)d_in[28];
    const float* b2     = (const float*)d_in[29];
    const float* Wo     = (const float*)d_in[30];
    const float* bo     = (const float*)d_in[31];
    float* out = (float*)d_out;

    float* s = nullptr;
    cudaGetSymbolAddress((void**)&s, g_scratch);
    float* adapt  = s + OFF_ADAPT;
    float* am     = s + OFF_AM;
    float* part   = s + OFF_PART;
    float* gate   = s + OFF_GATE;
    float* Wdyn   = s + OFF_WDYN;
    float* bcat   = s + OFF_BCAT;
    float* mix    = s + OFF_MIX;
    float* tpsi   = s + OFF_TPSI;
    float* ka     = s + OFF_KA;
    float* concat = s + OFF_CONCAT;
    float* resid  = s + OFF_RESID;
    float* hbuf   = s + OFF_H;
    float* comb   = s + OFF_COMB;
    float* kapart = s + OFF_KAPART;

    // 1. adapt = x @ W_feat + b_feat          [4096,128]
    sgemm_t<64, 64, false><<<dim3(ADIM / 64, NTOK / 64), 256>>>(x, W_feat, b_feat, adapt, NTOK, ADIM, DDIM);
    // 2. am = mean(adapt, axis=0)
    colsum_part_kernel<<<32, 128>>>(adapt, part);
    colsum_fin_kernel<<<1, 128>>>(part, am);
    // 3. dynamic weights + bias concat
    dynw_kernel<<<384, 256>>>(Wt, Wt_a, bt_a, Wc, Wc_a, bc_a, We, We_a, be_a, am, Wdyn);
    bcat_kernel<<<6, 256>>>(bt, bc, be, bcat);
    // 4. gate softmax
    gate_kernel<<<NTOK / 8, 256>>>(adapt, Wg, bg, gate);
    // 5. mix = x @ Wdyn + bcat                [4096,1536]
    sgemm_t<128, 128, false><<<dim3(DSUM / 128, NTOK / 128), 256>>>(x, Wdyn, bcat, mix, NTOK, DSUM, DDIM);
    // 6. KA stage 1 (fused phi -> psi1 partials, then finish)
    ka_part_kernel<<<128, 256>>>(x, Wphi, bphi, Wpsi1, kapart);
    ka_finish_kernel<<<256, 256>>>(kapart, bpsi1, tpsi);
    // 7. ka = tpsi @ Wpsi2 + bpsi2            [4096,256]
    sgemm_t<64, 64, false><<<dim3(DDIM / 64, NTOK / 64), 256>>>(tpsi, Wpsi2, bpsi2, ka, NTOK, DDIM, HIDD);
    // 8. concat = [tok, chan, moe, lf]        [4096,1536]
    concat_kernel<<<NTOK, 384>>>(mix, gate, ka, lf, concat);
    // 9. residual = concat @ Wres + bres      [4096,1536]
    sgemm_t<128, 128, false><<<dim3(DSUM / 128, NTOK / 128), 256>>>(concat, Wres, bres, resid, NTOK, DSUM, DSUM);
    // 10. h = gelu(concat @ W1 + b1)          [4096,64]
    sgemm_t<64, 64, true><<<dim3(HIDD / 64, NTOK / 64), 256>>>(concat, W1, b1, hbuf, NTOK, HIDD, DSUM);
    // 11. combine
    combine_kernel<<<NTOK / 8, 256>>>(hbuf, W2, b2, concat, resid, comb);
    // 12. out = comb @ Wo + bo                [4096,256]
    sgemm_t<64, 128, false><<<dim3(DDIM / 128, NTOK / 64), 256>>>(comb, Wo, bo, out, NTOK, DDIM, DSUM);
}

// round 5
// speedup vs baseline: 1.5474x; 1.1038x over previous
#include <cuda_runtime.h>
#include <cuda_bf16.h>
#include <math.h>
#include <stdint.h>

// ---------------------------------------------------------------------------
// Problem constants
// ---------------------------------------------------------------------------
#define NTOK   4096      // B*S
#define DDIM   256
#define DLF    768
#define ADIM   128
#define DSUM   1536
#define HIDD   64

typedef unsigned long long ull;

// ---------------------------------------------------------------------------
// f32x2 packed-FMA helpers (KA kernel)
// ---------------------------------------------------------------------------
__device__ __forceinline__ ull pack2(float lo, float hi) {
    ull r; asm("mov.b64 %0, {%1,%2};" : "=l"(r) : "f"(lo), "f"(hi)); return r;
}
__device__ __forceinline__ void unpack2(ull p, float& lo, float& hi) {
    asm("mov.b64 {%0,%1}, %2;" : "=f"(lo), "=f"(hi) : "l"(p));
}
__device__ __forceinline__ ull ffma2(ull a, ull b, ull c) {
    ull d; asm("fma.rn.f32x2 %0, %1, %2, %3;" : "=l"(d) : "l"(a), "l"(b), "l"(c)); return d;
}
__device__ __forceinline__ float gelu_f(float v) {
    return 0.5f * v * (1.0f + erff(v * 0.70710678118654752440f));
}
__device__ __forceinline__ uint32_t smem_to_u32(const void* p) {
    uint32_t a;
    asm("{ .reg .u64 t; cvta.to.shared.u64 t, %1; cvt.u32.u64 %0, t; }" : "=r"(a) : "l"(p));
    return a;
}
#define SMEM_SWIZZLE_128B(o) ((o) ^ (((o) >> 3) & 0x70))

__device__ __forceinline__ void ldsm_x4(uint32_t addr, uint32_t& r0, uint32_t& r1,
                                        uint32_t& r2, uint32_t& r3) {
    asm volatile("ldmatrix.sync.aligned.m8n8.x4.shared.b16 {%0,%1,%2,%3}, [%4];"
                 : "=r"(r0), "=r"(r1), "=r"(r2), "=r"(r3) : "r"(addr));
}
__device__ __forceinline__ void mma16816(float& c0, float& c1, float& c2, float& c3,
                                         uint32_t a0, uint32_t a1, uint32_t a2, uint32_t a3,
                                         uint32_t b0, uint32_t b1) {
    asm volatile("mma.sync.aligned.m16n8k16.row.col.f32.bf16.bf16.f32 "
                 "{%0,%1,%2,%3}, {%4,%5,%6,%7}, {%8,%9}, {%0,%1,%2,%3};"
                 : "+f"(c0), "+f"(c1), "+f"(c2), "+f"(c3)
                 : "r"(a0), "r"(a1), "r"(a2), "r"(a3), "r"(b0), "r"(b1));
}

// ---------------------------------------------------------------------------
// Scratch (fp32 region then bf16 region)
// ---------------------------------------------------------------------------
#define OFF_ADAPT   0u
#define OFF_AM      524288u
#define OFF_PART    524416u
#define OFF_GATE    528512u
#define OFF_WDYN    548992u
#define OFF_BCAT    942208u
#define OFF_MIX     943744u
#define OFF_TPSI    7235200u
#define OFF_KA      7497344u
#define OFF_CONCAT  8545920u
#define OFF_RESID   14837376u
#define OFF_H       21128832u
#define OFF_COMB    21390976u
#define OFF_KAPART  27682432u
#define OFF_BF16    28206720u          // start of bf16 region (float units)

// bf16 offsets (in bf16 elements from bf16 base)
#define BF_XH   0u
#define BF_XL   1048576u
#define BF_WFH  2097152u
#define BF_WFL  2129920u
#define BF_WDH  2162688u
#define BF_WDL  2555904u
#define BF_TPH  2949120u
#define BF_TPL  3211264u
#define BF_WPH  3473408u
#define BF_WPL  3489792u
#define BF_CATH 3506176u
#define BF_CATL 9797632u
#define BF_WRH  16089088u
#define BF_WRL  18448384u
#define BF_W1H  20807680u
#define BF_W1L  20905984u
#define BF_CBH  21004288u
#define BF_CBL  27295744u
#define BF_WOH  33587200u
#define BF_WOL  33980416u

#define SCRATCH_FLOATS (28206720u + 17186816u)
__device__ float g_scratch[SCRATCH_FLOATS];

// ---------------------------------------------------------------------------
// split: fp32 [n] -> bf16 hi, lo   (n multiple of 1024; 4 elems/thread)
// ---------------------------------------------------------------------------
__global__ void split_kernel(const float* __restrict__ src,
                             __nv_bfloat16* __restrict__ hi,
                             __nv_bfloat16* __restrict__ lo)
{
    const int i = blockIdx.x * 256 + threadIdx.x;
    float4 v = ((const float4*)src)[i];
    __nv_bfloat16 hx = __float2bfloat16(v.x), hy = __float2bfloat16(v.y);
    __nv_bfloat16 hz = __float2bfloat16(v.z), hw = __float2bfloat16(v.w);
    __nv_bfloat162* hp = (__nv_bfloat162*)hi;
    __nv_bfloat162* lp = (__nv_bfloat162*)lo;
    hp[2*i]   = __nv_bfloat162(hx, hy);
    hp[2*i+1] = __nv_bfloat162(hz, hw);
    lp[2*i]   = __nv_bfloat162(__float2bfloat16(v.x - __bfloat162float(hx)),
                               __float2bfloat16(v.y - __bfloat162float(hy)));
    lp[2*i+1] = __nv_bfloat162(__float2bfloat16(v.z - __bfloat162float(hz)),
                               __float2bfloat16(v.w - __bfloat162float(hw)));
}

// ---------------------------------------------------------------------------
// transpose+split: W [K,N] fp32 -> th, tl [N,K] bf16   (K,N multiples of 32)
// ---------------------------------------------------------------------------
__global__ void tsplit_kernel(const float* __restrict__ W,
                              __nv_bfloat16* __restrict__ th,
                              __nv_bfloat16* __restrict__ tl,
                              int K, int N)
{
    __shared__ float t[32][33];
    const int kb = blockIdx.y * 32, nb = blockIdx.x * 32;
    const int tx = threadIdx.x, ty = threadIdx.y;
#pragma unroll
    for (int j = 0; j < 32; j += 8)
        t[ty + j][tx] = W[(size_t)(kb + ty + j) * N + nb + tx];
    __syncthreads();
#pragma unroll
    for (int j = 0; j < 32; j += 8) {
        float v = t[tx][ty + j];
        __nv_bfloat16 h = __float2bfloat16(v);
        th[(size_t)(nb + ty + j) * K + kb + tx] = h;
        tl[(size_t)(nb + ty + j) * K + kb + tx] = __float2bfloat16(v - __bfloat162float(h));
    }
}

// ---------------------------------------------------------------------------
// HMMA bf16 3-split GEMM:  C[M,N] = A[M,K] @ B[K,N] + bias (optional GELU)
// A as (Ahi, Alo) [M,K]; B transposed as (BThi, BTlo) [N,K]. fp32 accumulate.
// Logical K' = 3K via chunks (hi,hi),(hi,lo),(lo,hi). CTA 128 x BN, BK=64,
// 256 threads = 8 warps (2 m x 4 n), warp tile 64 x BN/4, mma m16n8k16.
// M%128==0, N%BN==0, K%64==0.
// ---------------------------------------------------------------------------
template <int BN, bool GELU>
__global__ void __launch_bounds__(256)
gemm_hmma(const __nv_bfloat16* __restrict__ Ahi, const __nv_bfloat16* __restrict__ Alo,
          const __nv_bfloat16* __restrict__ BThi, const __nv_bfloat16* __restrict__ BTlo,
          const float* __restrict__ bias, float* __restrict__ C,
          int M, int N, int K)
{
    constexpr int ASZ = 128 * 128;          // bytes per A tile (128 x 64 bf16)
    constexpr int BSZ = BN * 128;           // bytes per B tile
    constexpr int WTN = BN / 4;             // warp tile N
    constexpr int NF  = WTN / 8;            // n fragments per warp (4 or 2)

    extern __shared__ char smem_raw[];
    const uint32_t base = smem_to_u32(smem_raw);
    const uint32_t tile0 = (base + 1023) & ~1023u;
    char* tilep = smem_raw + (tile0 - base);

    const int tid = threadIdx.x;
    const int wid = tid >> 5, lane = tid & 31;
    const int wm = wid & 1, wn = wid >> 1;
    const int bm = blockIdx.y * 128;
    const int bn = blockIdx.x * BN;
    const int KC = K >> 6;
    const int NC = 3 * KC;

    float acc[4][NF][4];
#pragma unroll
    for (int mf = 0; mf < 4; mf++)
#pragma unroll
        for (int nf = 0; nf < NF; nf++)
#pragma unroll
            for (int i = 0; i < 4; i++) acc[mf][nf][i] = 0.f;

    auto stage = [&](int c, int b) {
        const int blk = c / KC;
        const int k0  = (c - blk * KC) << 6;
        const __nv_bfloat16* Asrc = ((blk < 2) ? Ahi : Alo) + (size_t)bm * K + k0;
        const __nv_bfloat16* Bsrc = ((blk == 1) ? BTlo : BThi) + (size_t)bn * K + k0;
        char* ab = tilep + b * (ASZ + BSZ);
        char* bb = ab + ASZ;
#pragma unroll
        for (int i = 0; i < 4; i++) {
            int u = i * 256 + tid;               // 1024 units of 16B
            int row = u >> 3, seg = u & 7;
            uint4 v = *(const uint4*)(Asrc + (size_t)row * K + seg * 8);
            uint32_t off = row * 128 + seg * 16;
            *(uint4*)(ab + SMEM_SWIZZLE_128B(off)) = v;
        }
#pragma unroll
        for (int i = 0; i < BN / 32; i++) {      // BN*8 units
            int u = i * 256 + tid;
            int row = u >> 3, seg = u & 7;
            uint4 v = *(const uint4*)(Bsrc + (size_t)row * K + seg * 8);
            uint32_t off = row * 128 + seg * 16;
            *(uint4*)(bb + SMEM_SWIZZLE_128B(off)) = v;
        }
    };

    auto compute = [&](int b) {
        const uint32_t ab = tile0 + b * (ASZ + BSZ);
        const uint32_t bb = ab + ASZ;
#pragma unroll
        for (int k16 = 0; k16 < 4; k16++) {
            uint32_t ar[4][4];
#pragma unroll
            for (int mf = 0; mf < 4; mf++) {
                int row = wm * 64 + mf * 16 + (lane & 15);
                uint32_t off = row * 128 + k16 * 32 + ((lane >> 4) << 4);
                ldsm_x4(ab + SMEM_SWIZZLE_128B(off), ar[mf][0], ar[mf][1], ar[mf][2], ar[mf][3]);
            }
            uint32_t br[NF][2];
#pragma unroll
            for (int nb = 0; nb < NF / 2; nb++) {
                int grp = lane >> 3;
                int n = wn * WTN + nb * 16 + ((grp >> 1) << 3) + (lane & 7);
                uint32_t off = n * 128 + k16 * 32 + ((grp & 1) << 4);
                ldsm_x4(bb + SMEM_SWIZZLE_128B(off),
                        br[2*nb][0], br[2*nb][1], br[2*nb+1][0], br[2*nb+1][1]);
            }
#pragma unroll
            for (int mf = 0; mf < 4; mf++)
#pragma unroll
                for (int nf = 0; nf < NF; nf++)
                    mma16816(acc[mf][nf][0], acc[mf][nf][1], acc[mf][nf][2], acc[mf][nf][3],
                             ar[mf][0], ar[mf][1], ar[mf][2], ar[mf][3],
                             br[nf][0], br[nf][1]);
        }
    };

    stage(0, 0);
    __syncthreads();
    for (int c = 0; c < NC; c++) {
        if (c + 1 < NC) stage(c + 1, (c + 1) & 1);
        compute(c & 1);
        __syncthreads();
    }

    // epilogue
#pragma unroll
    for (int nf = 0; nf < NF; nf++) {
        int col = bn + wn * WTN + nf * 8 + ((lane & 3) << 1);
        float2 bv = *(const float2*)(bias + col);
#pragma unroll
        for (int mf = 0; mf < 4; mf++) {
            int row = bm + wm * 64 + mf * 16 + (lane >> 2);
            float x0 = acc[mf][nf][0] + bv.x;
            float x1 = acc[mf][nf][1] + bv.y;
            float x2 = acc[mf][nf][2] + bv.x;
            float x3 = acc[mf][nf][3] + bv.y;
            if (GELU) { x0 = gelu_f(x0); x1 = gelu_f(x1); x2 = gelu_f(x2); x3 = gelu_f(x3); }
            *(float2*)&C[(size_t)row * N + col]       = make_float2(x0, x1);
            *(float2*)&C[(size_t)(row + 8) * N + col] = make_float2(x2, x3);
        }
    }
}

// ---------------------------------------------------------------------------
// am = mean over tokens of adapt (deterministic two-stage reduction)
// ---------------------------------------------------------------------------
__global__ void colsum_part_kernel(const float* __restrict__ adapt, float* __restrict__ part)
{
    const int j = threadIdx.x;
    const int b = blockIdx.x;
    float s = 0.f;
#pragma unroll 8
    for (int r = 0; r < 128; r++) s += adapt[(size_t)(b * 128 + r) * ADIM + j];
    part[b * ADIM + j] = s;
}
__global__ void colsum_fin_kernel(const float* __restrict__ part, float* __restrict__ am)
{
    const int j = threadIdx.x;
    float s = 0.f;
#pragma unroll
    for (int b = 0; b < 32; b++) s += part[b * ADIM + j];
    am[j] = s * (1.0f / (float)NTOK);
}

// ---------------------------------------------------------------------------
// Dynamic weights (float4-vectorized, memory-bound)
// ---------------------------------------------------------------------------
__global__ void dynw_kernel(const float* __restrict__ Wt,  const float* __restrict__ Wt_a, const float* __restrict__ bt_a,
                            const float* __restrict__ Wc,  const float* __restrict__ Wc_a, const float* __restrict__ bc_a,
                            const float* __restrict__ We,  const float* __restrict__ We_a, const float* __restrict__ be_a,
                            const float* __restrict__ am,  float* __restrict__ Wdyn)
{
    __shared__ float ams[ADIM];
    const int tid = threadIdx.x;
    if (tid < ADIM) ams[tid] = am[tid];
    __syncthreads();

    const int idx4 = blockIdx.x * 256 + tid;
    const int k    = idx4 / 384;
    const int c4   = (idx4 - k * 384) * 4;

    const float *Wa, *ba, *base;
    int m;
    if (c4 < 256)      { m = k * 256 + c4;          base = Wt; Wa = Wt_a; ba = bt_a; }
    else if (c4 < 512) { m = k * 256 + (c4 - 256);  base = Wc; Wa = Wc_a; ba = bc_a; }
    else {
        int e  = (c4 - 512) >> 8;
        int jj = (c4 - 512) & 255;
        m = k * 256 + jj;
        base = We + e * 65536;
        Wa   = We_a + (size_t)e * 8388608u;
        ba   = be_a + e * 65536;
    }
    float4 acc = *(const float4*)(base + m);
    float4 b4  = *(const float4*)(ba + m);
    acc.x += b4.x; acc.y += b4.y; acc.z += b4.z; acc.w += b4.w;
#pragma unroll 4
    for (int a = 0; a < ADIM; a++) {
        float s = ams[a];
        float4 w = *(const float4*)(Wa + (size_t)a * 65536 + m);
        acc.x = fmaf(s, w.x, acc.x);
        acc.y = fmaf(s, w.y, acc.y);
        acc.z = fmaf(s, w.z, acc.z);
        acc.w = fmaf(s, w.w, acc.w);
    }
    *(float4*)(Wdyn + (size_t)idx4 * 4) = acc;
}

__global__ void bcat_kernel(const float* __restrict__ bt, const float* __restrict__ bc,
                            const float* __restrict__ be, float* __restrict__ bcat)
{
    int c = blockIdx.x * 256 + threadIdx.x;
    if (c >= DSUM) return;
    if (c < 256)      bcat[c] = bt[c];
    else if (c < 512) bcat[c] = bc[c - 256];
    else              bcat[c] = be[c - 512];
}

// ---------------------------------------------------------------------------
// gate = softmax(adapt @ Wg + bg) — one warp per token
// ---------------------------------------------------------------------------
__global__ void gate_kernel(const float* __restrict__ adapt, const float* __restrict__ Wg,
                            const float* __restrict__ bg, float* __restrict__ gate)
{
    __shared__ float wgs[ADIM * 5];
    __shared__ float bgs[5];
    const int tid = threadIdx.x;
    for (int i = tid; i < ADIM * 5; i += 256) wgs[i] = Wg[i];
    if (tid < 5) bgs[tid] = bg[tid];
    __syncthreads();

    const int warp = tid >> 5, lane = tid & 31;
    const int n = (blockIdx.x << 3) + warp;

    float4 a4 = *(const float4*)(adapt + (size_t)n * ADIM + lane * 4);
    float av[4] = { a4.x, a4.y, a4.z, a4.w };
    float l[5] = { 0, 0, 0, 0, 0 };
#pragma unroll
    for (int q = 0; q < 4; q++) {
        int a = lane * 4 + q;
#pragma unroll
        for (int j = 0; j < 5; j++) l[j] = fmaf(av[q], wgs[a * 5 + j], l[j]);
    }
#pragma unroll
    for (int off = 16; off; off >>= 1)
#pragma unroll
        for (int j = 0; j < 5; j++) l[j] += __shfl_xor_sync(0xffffffffu, l[j], off);

    if (lane == 0) {
#pragma unroll
        for (int j = 0; j < 5; j++) l[j] += bgs[j];
        float mx = fmaxf(fmaxf(fmaxf(l[0], l[1]), fmaxf(l[2], l[3])), l[4]);
        float s = 0.f;
#pragma unroll
        for (int j = 0; j < 5; j++) { l[j] = __expf(l[j] - mx); s += l[j]; }
        float inv = 1.0f / s;
#pragma unroll
        for (int j = 0; j < 5; j++) gate[n * 5 + j] = l[j] * inv;
    }
}

// ---------------------------------------------------------------------------
// KA expert stage-1 partials (FFMA2 path)
// ---------------------------------------------------------------------------
__global__ void __launch_bounds__(256)
ka_part_kernel(const float* __restrict__ xf, const float* __restrict__ Wphi,
               const float* __restrict__ bphi, const float* __restrict__ Wpsi1,
               float* __restrict__ part)
{
    __shared__ float xs[32][65];
    __shared__ float ph[64][68];
    __shared__ float ws[64 * 64];

    const int tid   = threadIdx.x;
    const int ttile = blockIdx.x >> 1;
    const int half  = blockIdx.x & 1;
    const int t0    = ttile << 6;
    const int dbase = half << 7;

    const int tr = (tid >> 4) << 2;
    const int tc = (tid & 15) << 2;
    const int h  = tid & 63;
    const int tg = (tid >> 6) << 4;

    const int xtok = tid >> 2;
    const int xdq  = (tid & 3) << 3;

    ull acc[4][2];
#pragma unroll
    for (int i = 0; i < 4; i++) { acc[i][0] = 0ull; acc[i][1] = 0ull; }

    for (int chunk = 0; chunk < 4; chunk++) {
        const int d0 = dbase + (chunk << 5);
        {
            const float* xp = xf + (size_t)(t0 + xtok) * 256 + d0 + xdq;
            float4 v0 = *(const float4*)(xp);
            float4 v1 = *(const float4*)(xp + 4);
            xs[xdq + 0][xtok] = v0.x; xs[xdq + 1][xtok] = v0.y;
            xs[xdq + 2][xtok] = v0.z; xs[xdq + 3][xtok] = v0.w;
            xs[xdq + 4][xtok] = v1.x; xs[xdq + 5][xtok] = v1.y;
            xs[xdq + 6][xtok] = v1.z; xs[xdq + 7][xtok] = v1.w;
        }
        __syncthreads();

        for (int dd = 0; dd < 32; dd++) {
            const int d = d0 + dd;
            float wp = __ldg(Wphi + (d << 6) + h);
            float bp = __ldg(bphi + (d << 6) + h);
#pragma unroll
            for (int t2 = 0; t2 < 16; t2++) {
                int t = tg + t2;
                ph[h][t] = gelu_f(fmaf(xs[dd][t], wp, bp));
            }
            {
                const float4* wsrc = (const float4*)(Wpsi1 + ((size_t)d << 12));
                float4* wdst = (float4*)ws;
#pragma unroll
                for (int r = 0; r < 4; r++) wdst[tid + (r << 8)] = wsrc[tid + (r << 8)];
            }
            __syncthreads();
#pragma unroll
            for (int hh = 0; hh < 64; hh++) {
                float4 pv = *(const float4*)&ph[hh][tr];
                float4 wv = *(const float4*)&ws[(hh << 6) + tc];
                ull w01 = pack2(wv.x, wv.y);
                ull w23 = pack2(wv.z, wv.w);
                float pa[4] = { pv.x, pv.y, pv.z, pv.w };
#pragma unroll
                for (int i = 0; i < 4; i++) {
                    ull pp = pack2(pa[i], pa[i]);
                    acc[i][0] = ffma2(pp, w01, acc[i][0]);
                    acc[i][1] = ffma2(pp, w23, acc[i][1]);
                }
            }
            __syncthreads();
        }
    }

    float* pout = part + ((size_t)half * NTOK + t0) * HIDD;
#pragma unroll
    for (int i = 0; i < 4; i++) {
        float x0, x1, x2, x3;
        unpack2(acc[i][0], x0, x1);
        unpack2(acc[i][1], x2, x3);
        *(float4*)(pout + (size_t)(tr + i) * HIDD + tc) = make_float4(x0, x1, x2, x3);
    }
}

__global__ void ka_finish_kernel(const float* __restrict__ part,
                                 const float* __restrict__ bpsi1,
                                 float* __restrict__ tpsi)
{
    const int idx = blockIdx.x * 256 + threadIdx.x;
    const int jq = idx & 15;
    float4 a = ((const float4*)part)[idx];
    float4 b = ((const float4*)part)[65536 + idx];
    float4 bb = ((const float4*)bpsi1)[jq];
    float4 o;
    o.x = gelu_f(a.x + b.x + bb.x);
    o.y = gelu_f(a.y + b.y + bb.y);
    o.z = gelu_f(a.z + b.z + bb.z);
    o.w = gelu_f(a.w + b.w + bb.w);
    ((float4*)tpsi)[idx] = o;
}

// ---------------------------------------------------------------------------
// concat[n] = [tok, chan, moe, lf]
// ---------------------------------------------------------------------------
__global__ void concat_kernel(const float* __restrict__ mix, const float* __restrict__ gate,
                              const float* __restrict__ ka, const float* __restrict__ lf,
                              float* __restrict__ concat)
{
    const int n = blockIdx.x;
    const int t = threadIdx.x;
    __shared__ float g[5];
    if (t < 5) g[t] = gate[n * 5 + t];
    __syncthreads();

    const float4* mx = (const float4*)(mix + (size_t)n * DSUM);
    float4 out;
    if (t < 128) {
        out = mx[t];
    } else if (t < 192) {
        int dq = t - 128;
        float4 e0 = mx[128 + dq], e1 = mx[192 + dq], e2 = mx[256 + dq], e3 = mx[320 + dq];
        float4 k4 = ((const float4*)(ka + (size_t)n * DDIM))[dq];
        out.x = g[0]*e0.x + g[1]*e1.x + g[2]*e2.x + g[3]*e3.x + g[4]*k4.x;
        out.y = g[0]*e0.y + g[1]*e1.y + g[2]*e2.y + g[3]*e3.y + g[4]*k4.y;
        out.z = g[0]*e0.z + g[1]*e1.z + g[2]*e2.z + g[3]*e3.z + g[4]*k4.z;
        out.w = g[0]*e0.w + g[1]*e1.w + g[2]*e2.w + g[3]*e3.w + g[4]*k4.w;
    } else {
        out = ((const float4*)(lf + (size_t)n * DLF))[t - 192];
    }
    ((float4*)(concat + (size_t)n * DSUM))[t] = out;
}

// ---------------------------------------------------------------------------
// combine: cw = softmax(h @ W2 + b2); comb = cw[sec]*concat + resid
// ---------------------------------------------------------------------------
__global__ void combine_kernel(const float* __restrict__ h, const float* __restrict__ W2,
                               const float* __restrict__ b2, const float* __restrict__ concat,
                               const float* __restrict__ resid, float* __restrict__ comb)
{
    __shared__ float w2s[256];
    const int tid = threadIdx.x;
    w2s[tid] = W2[tid];
    __syncthreads();

    const int warp = tid >> 5, lane = tid & 31;
    const int n = (blockIdx.x << 3) + warp;

    float2 hv = *(const float2*)(h + (size_t)n * HIDD + lane * 2);
    const int a0 = lane * 2, a1 = lane * 2 + 1;
    float l0 = hv.x * w2s[a0*4+0] + hv.y * w2s[a1*4+0];
    float l1 = hv.x * w2s[a0*4+1] + hv.y * w2s[a1*4+1];
    float l2 = hv.x * w2s[a0*4+2] + hv.y * w2s[a1*4+2];
    float l3 = hv.x * w2s[a0*4+3] + hv.y * w2s[a1*4+3];
#pragma unroll
    for (int off = 16; off; off >>= 1) {
        l0 += __shfl_xor_sync(0xffffffffu, l0, off);
        l1 += __shfl_xor_sync(0xffffffffu, l1, off);
        l2 += __shfl_xor_sync(0xffffffffu, l2, off);
        l3 += __shfl_xor_sync(0xffffffffu, l3, off);
    }
    l0 += __ldg(b2 + 0); l1 += __ldg(b2 + 1); l2 += __ldg(b2 + 2); l3 += __ldg(b2 + 3);
    float mx = fmaxf(fmaxf(l0, l1), fmaxf(l2, l3));
    float e0 = __expf(l0 - mx), e1 = __expf(l1 - mx), e2 = __expf(l2 - mx), e3 = __expf(l3 - mx);
    float inv = 1.0f / (e0 + e1 + e2 + e3);
    float cw0 = e0 * inv, cw1 = e1 * inv, cw2 = e2 * inv, cw3 = e3 * inv;

    const float4* cc = (const float4*)(concat + (size_t)n * DSUM);
    const float4* rr = (const float4*)(resid  + (size_t)n * DSUM);
    float4* oo = (float4*)(comb + (size_t)n * DSUM);
#pragma unroll
    for (int q = 0; q < 12; q++) {
        int c4 = lane + (q << 5);
        float w = (c4 < 64) ? cw0 : (c4 < 128) ? cw1 : (c4 < 192) ? cw2 : cw3;
        float4 cv = cc[c4], rv = rr[c4];
        oo[c4] = make_float4(fmaf(w, cv.x, rv.x), fmaf(w, cv.y, rv.y),
                             fmaf(w, cv.z, rv.z), fmaf(w, cv.w, rv.w));
    }
}

// ---------------------------------------------------------------------------
// Host launcher
// ---------------------------------------------------------------------------
extern "C" void kernel_launch(void* const* d_in, const int* in_sizes, int n_in,
                              void* d_out, int out_size)
{
    (void)in_sizes; (void)n_in; (void)out_size;

    const float* x      = (const float*)d_in[0];
    const float* lf     = (const float*)d_in[1];
    const float* W_feat = (const float*)d_in[2];
    const float* b_feat = (const float*)d_in[3];
    const float* Wt     = (const float*)d_in[4];
    const float* bt     = (const float*)d_in[5];
    const float* Wt_a   = (const float*)d_in[6];
    const float* bt_a   = (const float*)d_in[7];
    const float* Wc     = (const float*)d_in[8];
    const float* bc     = (const float*)d_in[9];
    const float* Wc_a   = (const float*)d_in[10];
    const float* bc_a   = (const float*)d_in[11];
    const float* We     = (const float*)d_in[12];
    const float* be     = (const float*)d_in[13];
    const float* We_a   = (const float*)d_in[14];
    const float* be_a   = (const float*)d_in[15];
    const float* Wg     = (const float*)d_in[16];
    const float* bg     = (const float*)d_in[17];
    const float* Wphi   = (const float*)d_in[18];
    const float* bphi   = (const float*)d_in[19];
    const float* Wpsi1  = (const float*)d_in[20];
    const float* bpsi1  = (const float*)d_in[21];
    const float* Wpsi2  = (const float*)d_in[22];
    const float* bpsi2  = (const float*)d_in[23];
    const float* Wres   = (const float*)d_in[24];
    const float* bres   = (const float*)d_in[25];
    const float* W1     = (const float*)d_in[26];
    const float* b1     = (const float*)d_in[27];
    const float* W2     = (const float*)d_in[28];
    const float* b2     = (const float*)d_in[29];
    const float* Wo     = (const float*)d_in[30];
    const float* bo     = (const float*)d_in[31];
    float* out = (float*)d_out;

    float* s = nullptr;
    cudaGetSymbolAddress((void**)&s, g_scratch);
    float* adapt  = s + OFF_ADAPT;
    float* am     = s + OFF_AM;
    float* part   = s + OFF_PART;
    float* gate   = s + OFF_GATE;
    float* Wdyn   = s + OFF_WDYN;
    float* bcat   = s + OFF_BCAT;
    float* mix    = s + OFF_MIX;
    float* tpsi   = s + OFF_TPSI;
    float* ka     = s + OFF_KA;
    float* concat = s + OFF_CONCAT;
    float* resid  = s + OFF_RESID;
    float* hbuf   = s + OFF_H;
    float* comb   = s + OFF_COMB;
    float* kapart = s + OFF_KAPART;

    __nv_bfloat16* bb = (__nv_bfloat16*)(s + OFF_BF16);
    __nv_bfloat16 *xh = bb + BF_XH,   *xl = bb + BF_XL;
    __nv_bfloat16 *wfh = bb + BF_WFH, *wfl = bb + BF_WFL;
    __nv_bfloat16 *wdh = bb + BF_WDH, *wdl = bb + BF_WDL;
    __nv_bfloat16 *tph = bb + BF_TPH, *tpl = bb + BF_TPL;
    __nv_bfloat16 *wph = bb + BF_WPH, *wpl = bb + BF_WPL;
    __nv_bfloat16 *cth = bb + BF_CATH, *ctl = bb + BF_CATL;
    __nv_bfloat16 *wrh = bb + BF_WRH, *wrl = bb + BF_WRL;
    __nv_bfloat16 *w1h = bb + BF_W1H, *w1l = bb + BF_W1L;
    __nv_bfloat16 *cbh = bb + BF_CBH, *cbl = bb + BF_CBL;
    __nv_bfloat16 *woh = bb + BF_WOH, *wol = bb + BF_WOL;

    const int SM128 = 2 * (16384 + 16384) + 1024;   // 66560
    const int SM64  = 2 * (16384 + 8192) + 1024;    // 50176
    cudaFuncSetAttribute(gemm_hmma<128, false>, cudaFuncAttributeMaxDynamicSharedMemorySize, SM128);
    cudaFuncSetAttribute(gemm_hmma<64, true>,  cudaFuncAttributeMaxDynamicSharedMemorySize, SM64);

    // --- input splits / weight transposes (independent of intermediates)
    split_kernel<<<1024, 256>>>(x, xh, xl);
    tsplit_kernel<<<dim3(ADIM/32, DDIM/32), dim3(32,8)>>>(W_feat, wfh, wfl, DDIM, ADIM);
    tsplit_kernel<<<dim3(DDIM/32, HIDD/32), dim3(32,8)>>>(Wpsi2, wph, wpl, HIDD, DDIM);
    tsplit_kernel<<<dim3(DSUM/32, DSUM/32), dim3(32,8)>>>(Wres, wrh, wrl, DSUM, DSUM);
    tsplit_kernel<<<dim3(HIDD/32, DSUM/32), dim3(32,8)>>>(W1, w1h, w1l, DSUM, HIDD);
    tsplit_kernel<<<dim3(DDIM/32, DSUM/32), dim3(32,8)>>>(Wo, woh, wol, DSUM, DDIM);

    // 1. adapt = x @ W_feat + b_feat          [4096,128]
    gemm_hmma<128, false><<<dim3(1, 32), 256, SM128>>>(xh, xl, wfh, wfl, b_feat, adapt, NTOK, ADIM, DDIM);
    // 2. am
    colsum_part_kernel<<<32, 128>>>(adapt, part);
    colsum_fin_kernel<<<1, 128>>>(part, am);
    // 3. dynamic weights + transpose-split + bias concat
    dynw_kernel<<<384, 256>>>(Wt, Wt_a, bt_a, Wc, Wc_a, bc_a, We, We_a, be_a, am, Wdyn);
    tsplit_kernel<<<dim3(DSUM/32, DDIM/32), dim3(32,8)>>>(Wdyn, wdh, wdl, DDIM, DSUM);
    bcat_kernel<<<6, 256>>>(bt, bc, be, bcat);
    // 4. gate softmax
    gate_kernel<<<NTOK / 8, 256>>>(adapt, Wg, bg, gate);
    // 5. mix = x @ Wdyn + bcat                [4096,1536]
    gemm_hmma<128, false><<<dim3(12, 32), 256, SM128>>>(xh, xl, wdh, wdl, bcat, mix, NTOK, DSUM, DDIM);
    // 6. KA stage 1
    ka_part_kernel<<<128, 256>>>(x, Wphi, bphi, Wpsi1, kapart);
    ka_finish_kernel<<<256, 256>>>(kapart, bpsi1, tpsi);
    // 7. ka = tpsi @ Wpsi2 + bpsi2            [4096,256]
    split_kernel<<<256, 256>>>(tpsi, tph, tpl);
    gemm_hmma<128, false><<<dim3(2, 32), 256, SM128>>>(tph, tpl, wph, wpl, bpsi2, ka, NTOK, DDIM, HIDD);
    // 8. concat
    concat_kernel<<<NTOK, 384>>>(mix, gate, ka, lf, concat);
    split_kernel<<<6144, 256>>>(concat, cth, ctl);
    // 9. residual = concat @ Wres + bres      [4096,1536]
    gemm_hmma<128, false><<<dim3(12, 32), 256, SM128>>>(cth, ctl, wrh, wrl, bres, resid, NTOK, DSUM, DSUM);
    // 10. h = gelu(concat @ W1 + b1)          [4096,64]
    gemm_hmma<64, true><<<dim3(1, 32), 256, SM64>>>(cth, ctl, w1h, w1l, b1, hbuf, NTOK, HIDD, DSUM);
    // 11. combine
    combine_kernel<<<NTOK / 8, 256>>>(hbuf, W2, b2, concat, resid, comb);
    split_kernel<<<6144, 256>>>(comb, cbh, cbl);
    // 12. out = comb @ Wo + bo                [4096,256]
    gemm_hmma<128, false><<<dim3(2, 32), 256, SM128>>>(cbh, cbl, woh, wol, bo, out, NTOK, DDIM, DSUM);
}

// round 6
// speedup vs baseline: 1.9313x; 1.2481x over previous
#include <cuda_runtime.h>
#include <cuda_bf16.h>
#include <math.h>
#include <stdint.h>

// ---------------------------------------------------------------------------
// Problem constants
// ---------------------------------------------------------------------------
#define NTOK   4096      // B*S
#define DDIM   256
#define DLF    768
#define ADIM   128
#define DSUM   1536
#define HIDD   64

typedef unsigned long long ull;

// ---------------------------------------------------------------------------
// helpers
// ---------------------------------------------------------------------------
__device__ __forceinline__ ull pack2(float lo, float hi) {
    ull r; asm("mov.b64 %0, {%1,%2};" : "=l"(r) : "f"(lo), "f"(hi)); return r;
}
__device__ __forceinline__ void unpack2(ull p, float& lo, float& hi) {
    asm("mov.b64 {%0,%1}, %2;" : "=f"(lo), "=f"(hi) : "l"(p));
}
__device__ __forceinline__ ull ffma2(ull a, ull b, ull c) {
    ull d; asm("fma.rn.f32x2 %0, %1, %2, %3;" : "=l"(d) : "l"(a), "l"(b), "l"(c)); return d;
}
__device__ __forceinline__ float gelu_f(float v) {
    return 0.5f * v * (1.0f + erff(v * 0.70710678118654752440f));
}
__device__ __forceinline__ uint32_t smem_to_u32(const void* p) {
    uint32_t a;
    asm("{ .reg .u64 t; cvta.to.shared.u64 t, %1; cvt.u32.u64 %0, t; }" : "=r"(a) : "l"(p));
    return a;
}
#define SMEM_SWIZZLE_128B(o) ((o) ^ (((o) >> 3) & 0x70))

__device__ __forceinline__ void cp_async16(uint32_t saddr, const void* gptr) {
    asm volatile("cp.async.cg.shared.global [%0], [%1], 16;" :: "r"(saddr), "l"(gptr));
}
#define CP_COMMIT() asm volatile("cp.async.commit_group;" ::: "memory")
#define CP_WAIT1()  asm volatile("cp.async.wait_group 1;"  ::: "memory")

__device__ __forceinline__ void ldsm_x4(uint32_t addr, uint32_t& r0, uint32_t& r1,
                                        uint32_t& r2, uint32_t& r3) {
    asm volatile("ldmatrix.sync.aligned.m8n8.x4.shared.b16 {%0,%1,%2,%3}, [%4];"
                 : "=r"(r0), "=r"(r1), "=r"(r2), "=r"(r3) : "r"(addr));
}
__device__ __forceinline__ void mma16816(float& c0, float& c1, float& c2, float& c3,
                                         uint32_t a0, uint32_t a1, uint32_t a2, uint32_t a3,
                                         uint32_t b0, uint32_t b1) {
    asm volatile("mma.sync.aligned.m16n8k16.row.col.f32.bf16.bf16.f32 "
                 "{%0,%1,%2,%3}, {%4,%5,%6,%7}, {%8,%9}, {%0,%1,%2,%3};"
                 : "+f"(c0), "+f"(c1), "+f"(c2), "+f"(c3)
                 : "r"(a0), "r"(a1), "r"(a2), "r"(a3), "r"(b0), "r"(b1));
}

__device__ __forceinline__ void split_store(float v, __nv_bfloat16* hi, __nv_bfloat16* lo) {
    __nv_bfloat16 h = __float2bfloat16(v);
    *hi = h;
    *lo = __float2bfloat16(v - __bfloat162float(h));
}

// ---------------------------------------------------------------------------
// Scratch (fp32 region then bf16 region)
// ---------------------------------------------------------------------------
#define OFF_ADAPT   0u
#define OFF_AM      524288u
#define OFF_PART    524416u
#define OFF_GATE    528512u
#define OFF_WDYN    548992u
#define OFF_BCAT    942208u
#define OFF_MIX     943744u
#define OFF_KA      7497344u
#define OFF_CONCAT  8545920u
#define OFF_RESID   14837376u
#define OFF_H       21128832u
#define OFF_KAPART  27682432u
#define OFF_BF16    28206720u          // start of bf16 region (float units)

// bf16 offsets (in bf16 elements from bf16 base)
#define BF_XH   0u
#define BF_XL   1048576u
#define BF_WFH  2097152u
#define BF_WFL  2129920u
#define BF_WDH  2162688u
#define BF_WDL  2555904u
#define BF_TPH  2949120u
#define BF_TPL  3211264u
#define BF_WPH  3473408u
#define BF_WPL  3489792u
#define BF_CATH 3506176u
#define BF_CATL 9797632u
#define BF_WRH  16089088u
#define BF_WRL  18448384u
#define BF_W1H  20807680u
#define BF_W1L  20905984u
#define BF_CBH  21004288u
#define BF_CBL  27295744u
#define BF_WOH  33587200u
#define BF_WOL  33980416u

#define SCRATCH_FLOATS (28206720u + 17186816u)
__device__ float g_scratch[SCRATCH_FLOATS];

// ---------------------------------------------------------------------------
// split: fp32 [n] -> bf16 hi, lo
// ---------------------------------------------------------------------------
__global__ void split_kernel(const float* __restrict__ src,
                             __nv_bfloat16* __restrict__ hi,
                             __nv_bfloat16* __restrict__ lo)
{
    const int i = blockIdx.x * 256 + threadIdx.x;
    float4 v = ((const float4*)src)[i];
    __nv_bfloat16 hx = __float2bfloat16(v.x), hy = __float2bfloat16(v.y);
    __nv_bfloat16 hz = __float2bfloat16(v.z), hw = __float2bfloat16(v.w);
    __nv_bfloat162* hp = (__nv_bfloat162*)hi;
    __nv_bfloat162* lp = (__nv_bfloat162*)lo;
    hp[2*i]   = __nv_bfloat162(hx, hy);
    hp[2*i+1] = __nv_bfloat162(hz, hw);
    lp[2*i]   = __nv_bfloat162(__float2bfloat16(v.x - __bfloat162float(hx)),
                               __float2bfloat16(v.y - __bfloat162float(hy)));
    lp[2*i+1] = __nv_bfloat162(__float2bfloat16(v.z - __bfloat162float(hz)),
                               __float2bfloat16(v.w - __bfloat162float(hw)));
}

// ---------------------------------------------------------------------------
// transpose+split: W [K,N] fp32 -> th, tl [N,K] bf16
// ---------------------------------------------------------------------------
__global__ void tsplit_kernel(const float* __restrict__ W,
                              __nv_bfloat16* __restrict__ th,
                              __nv_bfloat16* __restrict__ tl,
                              int K, int N)
{
    __shared__ float t[32][33];
    const int kb = blockIdx.y * 32, nb = blockIdx.x * 32;
    const int tx = threadIdx.x, ty = threadIdx.y;
#pragma unroll
    for (int j = 0; j < 32; j += 8)
        t[ty + j][tx] = W[(size_t)(kb + ty + j) * N + nb + tx];
    __syncthreads();
#pragma unroll
    for (int j = 0; j < 32; j += 8) {
        float v = t[tx][ty + j];
        __nv_bfloat16 h = __float2bfloat16(v);
        th[(size_t)(nb + ty + j) * K + kb + tx] = h;
        tl[(size_t)(nb + ty + j) * K + kb + tx] = __float2bfloat16(v - __bfloat162float(h));
    }
}

// ---------------------------------------------------------------------------
// HMMA bf16 3-split GEMM with cp.async 3-stage pipeline.
// C[M,N] = A[M,K] @ B[K,N] + bias (optional GELU)
// A as (Ahi, Alo) [M,K]; B transposed as (BThi, BTlo) [N,K]. fp32 accumulate.
// Logical chunks: (hi,hi),(hi,lo),(lo,hi) over K in steps of 64.
// CTA 128 x BN, 256 threads = 8 warps (2m x 4n), warp tile 64 x BN/4.
// ---------------------------------------------------------------------------
template <int BN, bool GELU>
__global__ void __launch_bounds__(256, 2)
gemm_hmma(const __nv_bfloat16* __restrict__ Ahi, const __nv_bfloat16* __restrict__ Alo,
          const __nv_bfloat16* __restrict__ BThi, const __nv_bfloat16* __restrict__ BTlo,
          const float* __restrict__ bias, float* __restrict__ C,
          int M, int N, int K)
{
    constexpr int ASZ = 128 * 128;          // bytes per A chunk tile
    constexpr int BSZ = BN * 128;           // bytes per B chunk tile
    constexpr int STG = ASZ + BSZ;
    constexpr int WTN = BN / 4;             // warp tile N
    constexpr int NF  = WTN / 8;            // n fragments per warp

    extern __shared__ char smem_raw[];
    const uint32_t tile0 = (smem_to_u32(smem_raw) + 1023) & ~1023u;

    const int tid = threadIdx.x;
    const int wid = tid >> 5, lane = tid & 31;
    const int wm = wid & 1, wn = wid >> 1;
    const int bm = blockIdx.y * 128;
    const int bn = blockIdx.x * BN;
    const int KC = K >> 6;
    const int NC = 3 * KC;

    float acc[4][NF][4];
#pragma unroll
    for (int mf = 0; mf < 4; mf++)
#pragma unroll
        for (int nf = 0; nf < NF; nf++)
#pragma unroll
            for (int i = 0; i < 4; i++) acc[mf][nf][i] = 0.f;

    auto stage = [&](int c) {
        const int buf = c % 3;
        const int blk = c / KC;
        const int k0  = (c - blk * KC) << 6;
        const __nv_bfloat16* Asrc = ((blk < 2) ? Ahi : Alo) + (size_t)bm * K + k0;
        const __nv_bfloat16* Bsrc = ((blk == 1) ? BTlo : BThi) + (size_t)bn * K + k0;
        const uint32_t ab = tile0 + buf * STG;
        const uint32_t bb = ab + ASZ;
#pragma unroll
        for (int i = 0; i < 4; i++) {                       // A: 1024 x 16B
            int u = i * 256 + tid;
            int row = u >> 3, seg = u & 7;
            uint32_t off = row * 128 + seg * 16;
            cp_async16(ab + SMEM_SWIZZLE_128B(off), Asrc + (size_t)row * K + seg * 8);
        }
#pragma unroll
        for (int i = 0; i < BN / 32; i++) {                 // B: BN*8 x 16B
            int u = i * 256 + tid;
            int row = u >> 3, seg = u & 7;
            uint32_t off = row * 128 + seg * 16;
            cp_async16(bb + SMEM_SWIZZLE_128B(off), Bsrc + (size_t)row * K + seg * 8);
        }
    };

    auto compute = [&](int buf) {
        const uint32_t ab = tile0 + buf * STG;
        const uint32_t bb = ab + ASZ;
#pragma unroll
        for (int k16 = 0; k16 < 4; k16++) {
            uint32_t ar[4][4];
#pragma unroll
            for (int mf = 0; mf < 4; mf++) {
                int row = wm * 64 + mf * 16 + (lane & 15);
                uint32_t off = row * 128 + k16 * 32 + ((lane >> 4) << 4);
                ldsm_x4(ab + SMEM_SWIZZLE_128B(off), ar[mf][0], ar[mf][1], ar[mf][2], ar[mf][3]);
            }
            uint32_t br[NF][2];
#pragma unroll
            for (int nb = 0; nb < NF / 2; nb++) {
                int grp = lane >> 3;
                int n = wn * WTN + nb * 16 + ((grp >> 1) << 3) + (lane & 7);
                uint32_t off = n * 128 + k16 * 32 + ((grp & 1) << 4);
                ldsm_x4(bb + SMEM_SWIZZLE_128B(off),
                        br[2*nb][0], br[2*nb][1], br[2*nb+1][0], br[2*nb+1][1]);
            }
#pragma unroll
            for (int mf = 0; mf < 4; mf++)
#pragma unroll
                for (int nf = 0; nf < NF; nf++)
                    mma16816(acc[mf][nf][0], acc[mf][nf][1], acc[mf][nf][2], acc[mf][nf][3],
                             ar[mf][0], ar[mf][1], ar[mf][2], ar[mf][3],
                             br[nf][0], br[nf][1]);
        }
    };

    // 3-stage cp.async pipeline
    stage(0); CP_COMMIT();
    if (NC > 1) stage(1);
    CP_COMMIT();
    for (int c = 0; c < NC; c++) {
        CP_WAIT1();
        __syncthreads();
        if (c + 2 < NC) stage(c + 2);
        CP_COMMIT();
        compute(c % 3);
    }

    // epilogue
#pragma unroll
    for (int nf = 0; nf < NF; nf++) {
        int col = bn + wn * WTN + nf * 8 + ((lane & 3) << 1);
        float2 bv = *(const float2*)(bias + col);
#pragma unroll
        for (int mf = 0; mf < 4; mf++) {
            int row = bm + wm * 64 + mf * 16 + (lane >> 2);
            float x0 = acc[mf][nf][0] + bv.x;
            float x1 = acc[mf][nf][1] + bv.y;
            float x2 = acc[mf][nf][2] + bv.x;
            float x3 = acc[mf][nf][3] + bv.y;
            if (GELU) { x0 = gelu_f(x0); x1 = gelu_f(x1); x2 = gelu_f(x2); x3 = gelu_f(x3); }
            *(float2*)&C[(size_t)row * N + col]       = make_float2(x0, x1);
            *(float2*)&C[(size_t)(row + 8) * N + col] = make_float2(x2, x3);
        }
    }
}

// ---------------------------------------------------------------------------
// am = mean over tokens of adapt (deterministic two-stage reduction)
// ---------------------------------------------------------------------------
__global__ void colsum_part_kernel(const float* __restrict__ adapt, float* __restrict__ part)
{
    const int j = threadIdx.x;
    const int b = blockIdx.x;
    float s = 0.f;
#pragma unroll 8
    for (int r = 0; r < 128; r++) s += adapt[(size_t)(b * 128 + r) * ADIM + j];
    part[b * ADIM + j] = s;
}
__global__ void colsum_fin_kernel(const float* __restrict__ part, float* __restrict__ am)
{
    const int j = threadIdx.x;
    float s = 0.f;
#pragma unroll
    for (int b = 0; b < 32; b++) s += part[b * ADIM + j];
    am[j] = s * (1.0f / (float)NTOK);
}

// ---------------------------------------------------------------------------
// Dynamic weights (float4-vectorized, memory-bound)
// ---------------------------------------------------------------------------
__global__ void dynw_kernel(const float* __restrict__ Wt,  const float* __restrict__ Wt_a, const float* __restrict__ bt_a,
                            const float* __restrict__ Wc,  const float* __restrict__ Wc_a, const float* __restrict__ bc_a,
                            const float* __restrict__ We,  const float* __restrict__ We_a, const float* __restrict__ be_a,
                            const float* __restrict__ am,  float* __restrict__ Wdyn)
{
    __shared__ float ams[ADIM];
    const int tid = threadIdx.x;
    if (tid < ADIM) ams[tid] = am[tid];
    __syncthreads();

    const int idx4 = blockIdx.x * 256 + tid;
    const int k    = idx4 / 384;
    const int c4   = (idx4 - k * 384) * 4;

    const float *Wa, *ba, *base;
    int m;
    if (c4 < 256)      { m = k * 256 + c4;          base = Wt; Wa = Wt_a; ba = bt_a; }
    else if (c4 < 512) { m = k * 256 + (c4 - 256);  base = Wc; Wa = Wc_a; ba = bc_a; }
    else {
        int e  = (c4 - 512) >> 8;
        int jj = (c4 - 512) & 255;
        m = k * 256 + jj;
        base = We + e * 65536;
        Wa   = We_a + (size_t)e * 8388608u;
        ba   = be_a + e * 65536;
    }
    float4 acc = *(const float4*)(base + m);
    float4 b4  = *(const float4*)(ba + m);
    acc.x += b4.x; acc.y += b4.y; acc.z += b4.z; acc.w += b4.w;
#pragma unroll 4
    for (int a = 0; a < ADIM; a++) {
        float s = ams[a];
        float4 w = *(const float4*)(Wa + (size_t)a * 65536 + m);
        acc.x = fmaf(s, w.x, acc.x);
        acc.y = fmaf(s, w.y, acc.y);
        acc.z = fmaf(s, w.z, acc.z);
        acc.w = fmaf(s, w.w, acc.w);
    }
    *(float4*)(Wdyn + (size_t)idx4 * 4) = acc;
}

__global__ void bcat_kernel(const float* __restrict__ bt, const float* __restrict__ bc,
                            const float* __restrict__ be, float* __restrict__ bcat)
{
    int c = blockIdx.x * 256 + threadIdx.x;
    if (c >= DSUM) return;
    if (c < 256)      bcat[c] = bt[c];
    else if (c < 512) bcat[c] = bc[c - 256];
    else              bcat[c] = be[c - 512];
}

// ---------------------------------------------------------------------------
// gate = softmax(adapt @ Wg + bg) — one warp per token
// ---------------------------------------------------------------------------
__global__ void gate_kernel(const float* __restrict__ adapt, const float* __restrict__ Wg,
                            const float* __restrict__ bg, float* __restrict__ gate)
{
    __shared__ float wgs[ADIM * 5];
    __shared__ float bgs[5];
    const int tid = threadIdx.x;
    for (int i = tid; i < ADIM * 5; i += 256) wgs[i] = Wg[i];
    if (tid < 5) bgs[tid] = bg[tid];
    __syncthreads();

    const int warp = tid >> 5, lane = tid & 31;
    const int n = (blockIdx.x << 3) + warp;

    float4 a4 = *(const float4*)(adapt + (size_t)n * ADIM + lane * 4);
    float av[4] = { a4.x, a4.y, a4.z, a4.w };
    float l[5] = { 0, 0, 0, 0, 0 };
#pragma unroll
    for (int q = 0; q < 4; q++) {
        int a = lane * 4 + q;
#pragma unroll
        for (int j = 0; j < 5; j++) l[j] = fmaf(av[q], wgs[a * 5 + j], l[j]);
    }
#pragma unroll
    for (int off = 16; off; off >>= 1)
#pragma unroll
        for (int j = 0; j < 5; j++) l[j] += __shfl_xor_sync(0xffffffffu, l[j], off);

    if (lane == 0) {
#pragma unroll
        for (int j = 0; j < 5; j++) l[j] += bgs[j];
        float mx = fmaxf(fmaxf(fmaxf(l[0], l[1]), fmaxf(l[2], l[3])), l[4]);
        float s = 0.f;
#pragma unroll
        for (int j = 0; j < 5; j++) { l[j] = __expf(l[j] - mx); s += l[j]; }
        float inv = 1.0f / s;
#pragma unroll
        for (int j = 0; j < 5; j++) gate[n * 5 + j] = l[j] * inv;
    }
}

// ---------------------------------------------------------------------------
// KA expert stage-1 partials (FFMA2 path)
// ---------------------------------------------------------------------------
__global__ void __launch_bounds__(256)
ka_part_kernel(const float* __restrict__ xf, const float* __restrict__ Wphi,
               const float* __restrict__ bphi, const float* __restrict__ Wpsi1,
               float* __restrict__ part)
{
    __shared__ float xs[32][65];
    __shared__ float ph[64][68];
    __shared__ float ws[64 * 64];

    const int tid   = threadIdx.x;
    const int ttile = blockIdx.x >> 1;
    const int half  = blockIdx.x & 1;
    const int t0    = ttile << 6;
    const int dbase = half << 7;

    const int tr = (tid >> 4) << 2;
    const int tc = (tid & 15) << 2;
    const int h  = tid & 63;
    const int tg = (tid >> 6) << 4;

    const int xtok = tid >> 2;
    const int xdq  = (tid & 3) << 3;

    ull acc[4][2];
#pragma unroll
    for (int i = 0; i < 4; i++) { acc[i][0] = 0ull; acc[i][1] = 0ull; }

    for (int chunk = 0; chunk < 4; chunk++) {
        const int d0 = dbase + (chunk << 5);
        {
            const float* xp = xf + (size_t)(t0 + xtok) * 256 + d0 + xdq;
            float4 v0 = *(const float4*)(xp);
            float4 v1 = *(const float4*)(xp + 4);
            xs[xdq + 0][xtok] = v0.x; xs[xdq + 1][xtok] = v0.y;
            xs[xdq + 2][xtok] = v0.z; xs[xdq + 3][xtok] = v0.w;
            xs[xdq + 4][xtok] = v1.x; xs[xdq + 5][xtok] = v1.y;
            xs[xdq + 6][xtok] = v1.z; xs[xdq + 7][xtok] = v1.w;
        }
        __syncthreads();

        for (int dd = 0; dd < 32; dd++) {
            const int d = d0 + dd;
            float wp = __ldg(Wphi + (d << 6) + h);
            float bp = __ldg(bphi + (d << 6) + h);
#pragma unroll
            for (int t2 = 0; t2 < 16; t2++) {
                int t = tg + t2;
                ph[h][t] = gelu_f(fmaf(xs[dd][t], wp, bp));
            }
            {
                const float4* wsrc = (const float4*)(Wpsi1 + ((size_t)d << 12));
                float4* wdst = (float4*)ws;
#pragma unroll
                for (int r = 0; r < 4; r++) wdst[tid + (r << 8)] = wsrc[tid + (r << 8)];
            }
            __syncthreads();
#pragma unroll
            for (int hh = 0; hh < 64; hh++) {
                float4 pv = *(const float4*)&ph[hh][tr];
                float4 wv = *(const float4*)&ws[(hh << 6) + tc];
                ull w01 = pack2(wv.x, wv.y);
                ull w23 = pack2(wv.z, wv.w);
                float pa[4] = { pv.x, pv.y, pv.z, pv.w };
#pragma unroll
                for (int i = 0; i < 4; i++) {
                    ull pp = pack2(pa[i], pa[i]);
                    acc[i][0] = ffma2(pp, w01, acc[i][0]);
                    acc[i][1] = ffma2(pp, w23, acc[i][1]);
                }
            }
            __syncthreads();
        }
    }

    float* pout = part + ((size_t)half * NTOK + t0) * HIDD;
#pragma unroll
    for (int i = 0; i < 4; i++) {
        float x0, x1, x2, x3;
        unpack2(acc[i][0], x0, x1);
        unpack2(acc[i][1], x2, x3);
        *(float4*)(pout + (size_t)(tr + i) * HIDD + tc) = make_float4(x0, x1, x2, x3);
    }
}

// tpsi = gelu(part0 + part1 + bpsi1) -> emitted directly as bf16 hi/lo
__global__ void ka_finish_kernel(const float* __restrict__ part,
                                 const float* __restrict__ bpsi1,
                                 __nv_bfloat16* __restrict__ tph,
                                 __nv_bfloat16* __restrict__ tpl)
{
    const int idx = blockIdx.x * 256 + threadIdx.x;   // float4 index, 65536 total
    const int jq = idx & 15;
    float4 a = ((const float4*)part)[idx];
    float4 b = ((const float4*)part)[65536 + idx];
    float4 bb = ((const float4*)bpsi1)[jq];
    float o[4];
    o[0] = gelu_f(a.x + b.x + bb.x);
    o[1] = gelu_f(a.y + b.y + bb.y);
    o[2] = gelu_f(a.z + b.z + bb.z);
    o[3] = gelu_f(a.w + b.w + bb.w);
#pragma unroll
    for (int q = 0; q < 4; q++) split_store(o[q], tph + idx * 4 + q, tpl + idx * 4 + q);
}

// ---------------------------------------------------------------------------
// concat[n] = [tok, chan, moe, lf]; also emits bf16 hi/lo
// ---------------------------------------------------------------------------
__global__ void concat_kernel(const float* __restrict__ mix, const float* __restrict__ gate,
                              const float* __restrict__ ka, const float* __restrict__ lf,
                              float* __restrict__ concat,
                              __nv_bfloat16* __restrict__ cth, __nv_bfloat16* __restrict__ ctl)
{
    const int n = blockIdx.x;
    const int t = threadIdx.x;
    __shared__ float g[5];
    if (t < 5) g[t] = gate[n * 5 + t];
    __syncthreads();

    const float4* mx = (const float4*)(mix + (size_t)n * DSUM);
    float4 out;
    if (t < 128) {
        out = mx[t];
    } else if (t < 192) {
        int dq = t - 128;
        float4 e0 = mx[128 + dq], e1 = mx[192 + dq], e2 = mx[256 + dq], e3 = mx[320 + dq];
        float4 k4 = ((const float4*)(ka + (size_t)n * DDIM))[dq];
        out.x = g[0]*e0.x + g[1]*e1.x + g[2]*e2.x + g[3]*e3.x + g[4]*k4.x;
        out.y = g[0]*e0.y + g[1]*e1.y + g[2]*e2.y + g[3]*e3.y + g[4]*k4.y;
        out.z = g[0]*e0.z + g[1]*e1.z + g[2]*e2.z + g[3]*e3.z + g[4]*k4.z;
        out.w = g[0]*e0.w + g[1]*e1.w + g[2]*e2.w + g[3]*e3.w + g[4]*k4.w;
    } else {
        out = ((const float4*)(lf + (size_t)n * DLF))[t - 192];
    }
    ((float4*)(concat + (size_t)n * DSUM))[t] = out;
    const size_t e = (size_t)n * DSUM + t * 4;
    split_store(out.x, cth + e + 0, ctl + e + 0);
    split_store(out.y, cth + e + 1, ctl + e + 1);
    split_store(out.z, cth + e + 2, ctl + e + 2);
    split_store(out.w, cth + e + 3, ctl + e + 3);
}

// ---------------------------------------------------------------------------
// combine: cw = softmax(h @ W2 + b2); comb = cw[sec]*concat + resid (bf16 out)
// ---------------------------------------------------------------------------
__global__ void combine_kernel(const float* __restrict__ h, const float* __restrict__ W2,
                               const float* __restrict__ b2, const float* __restrict__ concat,
                               const float* __restrict__ resid,
                               __nv_bfloat16* __restrict__ cbh, __nv_bfloat16* __restrict__ cbl)
{
    __shared__ float w2s[256];
    const int tid = threadIdx.x;
    w2s[tid] = W2[tid];
    __syncthreads();

    const int warp = tid >> 5, lane = tid & 31;
    const int n = (blockIdx.x << 3) + warp;

    float2 hv = *(const float2*)(h + (size_t)n * HIDD + lane * 2);
    const int a0 = lane * 2, a1 = lane * 2 + 1;
    float l0 = hv.x * w2s[a0*4+0] + hv.y * w2s[a1*4+0];
    float l1 = hv.x * w2s[a0*4+1] + hv.y * w2s[a1*4+1];
    float l2 = hv.x * w2s[a0*4+2] + hv.y * w2s[a1*4+2];
    float l3 = hv.x * w2s[a0*4+3] + hv.y * w2s[a1*4+3];
#pragma unroll
    for (int off = 16; off; off >>= 1) {
        l0 += __shfl_xor_sync(0xffffffffu, l0, off);
        l1 += __shfl_xor_sync(0xffffffffu, l1, off);
        l2 += __shfl_xor_sync(0xffffffffu, l2, off);
        l3 += __shfl_xor_sync(0xffffffffu, l3, off);
    }
    l0 += __ldg(b2 + 0); l1 += __ldg(b2 + 1); l2 += __ldg(b2 + 2); l3 += __ldg(b2 + 3);
    float mx = fmaxf(fmaxf(l0, l1), fmaxf(l2, l3));
    float e0 = __expf(l0 - mx), e1 = __expf(l1 - mx), e2 = __expf(l2 - mx), e3 = __expf(l3 - mx);
    float inv = 1.0f / (e0 + e1 + e2 + e3);
    float cw0 = e0 * inv, cw1 = e1 * inv, cw2 = e2 * inv, cw3 = e3 * inv;

    const float4* cc = (const float4*)(concat + (size_t)n * DSUM);
    const float4* rr = (const float4*)(resid  + (size_t)n * DSUM);
#pragma unroll
    for (int q = 0; q < 12; q++) {
        int c4 = lane + (q << 5);
        float w = (c4 < 64) ? cw0 : (c4 < 128) ? cw1 : (c4 < 192) ? cw2 : cw3;
        float4 cv = cc[c4], rv = rr[c4];
        float v0 = fmaf(w, cv.x, rv.x), v1 = fmaf(w, cv.y, rv.y);
        float v2 = fmaf(w, cv.z, rv.z), v3 = fmaf(w, cv.w, rv.w);
        const size_t e = (size_t)n * DSUM + c4 * 4;
        split_store(v0, cbh + e + 0, cbl + e + 0);
        split_store(v1, cbh + e + 1, cbl + e + 1);
        split_store(v2, cbh + e + 2, cbl + e + 2);
        split_store(v3, cbh + e + 3, cbl + e + 3);
    }
}

// ---------------------------------------------------------------------------
// Host launcher
// ---------------------------------------------------------------------------
extern "C" void kernel_launch(void* const* d_in, const int* in_sizes, int n_in,
                              void* d_out, int out_size)
{
    (void)in_sizes; (void)n_in; (void)out_size;

    const float* x      = (const float*)d_in[0];
    const float* lf     = (const float*)d_in[1];
    const float* W_feat = (const float*)d_in[2];
    const float* b_feat = (const float*)d_in[3];
    const float* Wt     = (const float*)d_in[4];
    const float* bt     = (const float*)d_in[5];
    const float* Wt_a   = (const float*)d_in[6];
    const float* bt_a   = (const float*)d_in[7];
    const float* Wc     = (const float*)d_in[8];
    const float* bc     = (const float*)d_in[9];
    const float* Wc_a   = (const float*)d_in[10];
    const float* bc_a   = (const float*)d_in[11];
    const float* We     = (const float*)d_in[12];
    const float* be     = (const float*)d_in[13];
    const float* We_a   = (const float*)d_in[14];
    const float* be_a   = (const float*)d_in[15];
    const float* Wg     = (const float*)d_in[16];
    const float* bg     = (const float*)d_in[17];
    const float* Wphi   = (const float*)d_in[18];
    const float* bphi   = (const float*)d_in[19];
    const float* Wpsi1  = (const float*)d_in[20];
    const float* bpsi1  = (const float*)d_in[21];
    const float* Wpsi2  = (const float*)d_in[22];
    const float* bpsi2  = (const float*)d_in[23];
    const float* Wres   = (const float*)d_in[24];
    const float* bres   = (const float*)d_in[25];
    const float* W1     = (const float*)d_in[26];
    const float* b1     = (const float*)d_in[27];
    const float* W2     = (const float*)d_in[28];
    const float* b2     = (const float*)d_in[29];
    const float* Wo     = (const float*)d_in[30];
    const float* bo     = (const float*)d_in[31];
    float* out = (float*)d_out;

    float* s = nullptr;
    cudaGetSymbolAddress((void**)&s, g_scratch);
    float* adapt  = s + OFF_ADAPT;
    float* am     = s + OFF_AM;
    float* part   = s + OFF_PART;
    float* gate   = s + OFF_GATE;
    float* Wdyn   = s + OFF_WDYN;
    float* bcat   = s + OFF_BCAT;
    float* mix    = s + OFF_MIX;
    float* ka     = s + OFF_KA;
    float* concat = s + OFF_CONCAT;
    float* resid  = s + OFF_RESID;
    float* hbuf   = s + OFF_H;
    float* kapart = s + OFF_KAPART;

    __nv_bfloat16* bb = (__nv_bfloat16*)(s + OFF_BF16);
    __nv_bfloat16 *xh = bb + BF_XH,   *xl = bb + BF_XL;
    __nv_bfloat16 *wfh = bb + BF_WFH, *wfl = bb + BF_WFL;
    __nv_bfloat16 *wdh = bb + BF_WDH, *wdl = bb + BF_WDL;
    __nv_bfloat16 *tph = bb + BF_TPH, *tpl = bb + BF_TPL;
    __nv_bfloat16 *wph = bb + BF_WPH, *wpl = bb + BF_WPL;
    __nv_bfloat16 *cth = bb + BF_CATH, *ctl = bb + BF_CATL;
    __nv_bfloat16 *wrh = bb + BF_WRH, *wrl = bb + BF_WRL;
    __nv_bfloat16 *w1h = bb + BF_W1H, *w1l = bb + BF_W1L;
    __nv_bfloat16 *cbh = bb + BF_CBH, *cbl = bb + BF_CBL;
    __nv_bfloat16 *woh = bb + BF_WOH, *wol = bb + BF_WOL;

    const int SM128 = 3 * (16384 + 16384) + 1024;   // 99328
    const int SM64  = 3 * (16384 + 8192) + 1024;    // 74752
    cudaFuncSetAttribute(gemm_hmma<128, false>, cudaFuncAttributeMaxDynamicSharedMemorySize, SM128);
    cudaFuncSetAttribute(gemm_hmma<64, true>,  cudaFuncAttributeMaxDynamicSharedMemorySize, SM64);

    // Launch order arranged so the 4th launch (ncu capture window) is a GEMM.
    // 1. x split
    split_kernel<<<1024, 256>>>(x, xh, xl);
    // 2. W_feat transpose-split
    tsplit_kernel<<<dim3(ADIM/32, DDIM/32), dim3(32,8)>>>(W_feat, wfh, wfl, DDIM, ADIM);
    // 3. Wpsi2 transpose-split
    tsplit_kernel<<<dim3(DDIM/32, HIDD/32), dim3(32,8)>>>(Wpsi2, wph, wpl, HIDD, DDIM);
    // 4. adapt = x @ W_feat + b_feat          [4096,128]   <-- ncu window
    gemm_hmma<128, false><<<dim3(1, 32), 256, SM128>>>(xh, xl, wfh, wfl, b_feat, adapt, NTOK, ADIM, DDIM);
    // 5-7. remaining weight transposes
    tsplit_kernel<<<dim3(DSUM/32, DSUM/32), dim3(32,8)>>>(Wres, wrh, wrl, DSUM, DSUM);
    tsplit_kernel<<<dim3(HIDD/32, DSUM/32), dim3(32,8)>>>(W1, w1h, w1l, DSUM, HIDD);
    tsplit_kernel<<<dim3(DDIM/32, DSUM/32), dim3(32,8)>>>(Wo, woh, wol, DSUM, DDIM);
    // 8-9. am
    colsum_part_kernel<<<32, 128>>>(adapt, part);
    colsum_fin_kernel<<<1, 128>>>(part, am);
    // 10-12. dynamic weights + transpose-split + bias concat
    dynw_kernel<<<384, 256>>>(Wt, Wt_a, bt_a, Wc, Wc_a, bc_a, We, We_a, be_a, am, Wdyn);
    tsplit_kernel<<<dim3(DSUM/32, DDIM/32), dim3(32,8)>>>(Wdyn, wdh, wdl, DDIM, DSUM);
    bcat_kernel<<<6, 256>>>(bt, bc, be, bcat);
    // 13. gate softmax
    gate_kernel<<<NTOK / 8, 256>>>(adapt, Wg, bg, gate);
    // 14. mix = x @ Wdyn + bcat               [4096,1536]
    gemm_hmma<128, false><<<dim3(12, 32), 256, SM128>>>(xh, xl, wdh, wdl, bcat, mix, NTOK, DSUM, DDIM);
    // 15-16. KA stage 1 (finish emits bf16 hi/lo directly)
    ka_part_kernel<<<128, 256>>>(x, Wphi, bphi, Wpsi1, kapart);
    ka_finish_kernel<<<256, 256>>>(kapart, bpsi1, tph, tpl);
    // 17. ka = tpsi @ Wpsi2 + bpsi2           [4096,256]
    gemm_hmma<128, false><<<dim3(2, 32), 256, SM128>>>(tph, tpl, wph, wpl, bpsi2, ka, NTOK, DDIM, HIDD);
    // 18. concat (+ bf16 hi/lo)
    concat_kernel<<<NTOK, 384>>>(mix, gate, ka, lf, concat, cth, ctl);
    // 19. residual = concat @ Wres + bres     [4096,1536]
    gemm_hmma<128, false><<<dim3(12, 32), 256, SM128>>>(cth, ctl, wrh, wrl, bres, resid, NTOK, DSUM, DSUM);
    // 20. h = gelu(concat @ W1 + b1)          [4096,64]
    gemm_hmma<64, true><<<dim3(1, 32), 256, SM64>>>(cth, ctl, w1h, w1l, b1, hbuf, NTOK, HIDD, DSUM);
    // 21. combine (emits bf16 hi/lo only)
    combine_kernel<<<NTOK / 8, 256>>>(hbuf, W2, b2, concat, resid, cbh, cbl);
    // 22. out = comb @ Wo + bo                [4096,256]
    gemm_hmma<128, false><<<dim3(2, 32), 256, SM128>>>(cbh, cbl, woh, wol, bo, out, NTOK, DDIM, DSUM);
}

// round 7
// speedup vs baseline: 2.0493x; 1.0611x over previous
#include <cuda_runtime.h>
#include <cuda_bf16.h>
#include <math.h>
#include <stdint.h>

// ---------------------------------------------------------------------------
// Problem constants
// ---------------------------------------------------------------------------
#define NTOK   4096      // B*S
#define DDIM   256
#define DLF    768
#define ADIM   128
#define DSUM   1536
#define HIDD   64

typedef unsigned long long ull;

// ---------------------------------------------------------------------------
// helpers
// ---------------------------------------------------------------------------
__device__ __forceinline__ ull pack2(float lo, float hi) {
    ull r; asm("mov.b64 %0, {%1,%2};" : "=l"(r) : "f"(lo), "f"(hi)); return r;
}
__device__ __forceinline__ void unpack2(ull p, float& lo, float& hi) {
    asm("mov.b64 {%0,%1}, %2;" : "=f"(lo), "=f"(hi) : "l"(p));
}
__device__ __forceinline__ ull ffma2(ull a, ull b, ull c) {
    ull d; asm("fma.rn.f32x2 %0, %1, %2, %3;" : "=l"(d) : "l"(a), "l"(b), "l"(c)); return d;
}
__device__ __forceinline__ float gelu_f(float v) {
    return 0.5f * v * (1.0f + erff(v * 0.70710678118654752440f));
}
__device__ __forceinline__ uint32_t smem_to_u32(const void* p) {
    uint32_t a;
    asm("{ .reg .u64 t; cvta.to.shared.u64 t, %1; cvt.u32.u64 %0, t; }" : "=r"(a) : "l"(p));
    return a;
}
#define SMEM_SWIZZLE_128B(o) ((o) ^ (((o) >> 3) & 0x70))

__device__ __forceinline__ void cp_async16(uint32_t saddr, const void* gptr) {
    asm volatile("cp.async.cg.shared.global [%0], [%1], 16;" :: "r"(saddr), "l"(gptr));
}
#define CP_COMMIT() asm volatile("cp.async.commit_group;" ::: "memory")
#define CP_WAIT1()  asm volatile("cp.async.wait_group 1;"  ::: "memory")
#define CP_WAIT0()  asm volatile("cp.async.wait_group 0;"  ::: "memory")

__device__ __forceinline__ void ldsm_x4(uint32_t addr, uint32_t& r0, uint32_t& r1,
                                        uint32_t& r2, uint32_t& r3) {
    asm volatile("ldmatrix.sync.aligned.m8n8.x4.shared.b16 {%0,%1,%2,%3}, [%4];"
                 : "=r"(r0), "=r"(r1), "=r"(r2), "=r"(r3) : "r"(addr));
}
__device__ __forceinline__ void ldsm_x2(uint32_t addr, uint32_t& r0, uint32_t& r1) {
    asm volatile("ldmatrix.sync.aligned.m8n8.x2.shared.b16 {%0,%1}, [%2];"
                 : "=r"(r0), "=r"(r1) : "r"(addr));
}
__device__ __forceinline__ void mma16816(float& c0, float& c1, float& c2, float& c3,
                                         uint32_t a0, uint32_t a1, uint32_t a2, uint32_t a3,
                                         uint32_t b0, uint32_t b1) {
    asm volatile("mma.sync.aligned.m16n8k16.row.col.f32.bf16.bf16.f32 "
                 "{%0,%1,%2,%3}, {%4,%5,%6,%7}, {%8,%9}, {%0,%1,%2,%3};"
                 : "+f"(c0), "+f"(c1), "+f"(c2), "+f"(c3)
                 : "r"(a0), "r"(a1), "r"(a2), "r"(a3), "r"(b0), "r"(b1));
}

__device__ __forceinline__ void split_store(float v, __nv_bfloat16* hi, __nv_bfloat16* lo) {
    __nv_bfloat16 h = __float2bfloat16(v);
    *hi = h;
    *lo = __float2bfloat16(v - __bfloat162float(h));
}

// ---------------------------------------------------------------------------
// Scratch (fp32 region then bf16 region)
// ---------------------------------------------------------------------------
#define OFF_ADAPT   0u
#define OFF_AM      524288u
#define OFF_PART    524416u
#define OFF_GATE    528512u
#define OFF_WDYN    548992u
#define OFF_BCAT    942208u
#define OFF_MIX     943744u
#define OFF_KA      7497344u
#define OFF_CONCAT  8545920u
#define OFF_RESID   14837376u
#define OFF_H       21128832u
#define OFF_KAPART  27682432u
#define OFF_BF16    28206720u          // start of bf16 region (float units)

// bf16 offsets (in bf16 elements from bf16 base)
#define BF_XH   0u
#define BF_XL   1048576u
#define BF_WFH  2097152u
#define BF_WFL  2129920u
#define BF_WDH  2162688u
#define BF_WDL  2555904u
#define BF_TPH  2949120u
#define BF_TPL  3211264u
#define BF_WPH  3473408u
#define BF_WPL  3489792u
#define BF_CATH 3506176u
#define BF_CATL 9797632u
#define BF_WRH  16089088u
#define BF_WRL  18448384u
#define BF_W1H  20807680u
#define BF_W1L  20905984u
#define BF_CBH  21004288u
#define BF_CBL  27295744u
#define BF_WOH  33587200u
#define BF_WOL  33980416u

#define SCRATCH_FLOATS (28206720u + 17186816u)
__device__ float g_scratch[SCRATCH_FLOATS];

// ---------------------------------------------------------------------------
// split: fp32 [n] -> bf16 hi, lo
// ---------------------------------------------------------------------------
__global__ void split_kernel(const float* __restrict__ src,
                             __nv_bfloat16* __restrict__ hi,
                             __nv_bfloat16* __restrict__ lo)
{
    const int i = blockIdx.x * 256 + threadIdx.x;
    float4 v = ((const float4*)src)[i];
    __nv_bfloat16 hx = __float2bfloat16(v.x), hy = __float2bfloat16(v.y);
    __nv_bfloat16 hz = __float2bfloat16(v.z), hw = __float2bfloat16(v.w);
    __nv_bfloat162* hp = (__nv_bfloat162*)hi;
    __nv_bfloat162* lp = (__nv_bfloat162*)lo;
    hp[2*i]   = __nv_bfloat162(hx, hy);
    hp[2*i+1] = __nv_bfloat162(hz, hw);
    lp[2*i]   = __nv_bfloat162(__float2bfloat16(v.x - __bfloat162float(hx)),
                               __float2bfloat16(v.y - __bfloat162float(hy)));
    lp[2*i+1] = __nv_bfloat162(__float2bfloat16(v.z - __bfloat162float(hz)),
                               __float2bfloat16(v.w - __bfloat162float(hw)));
}

// ---------------------------------------------------------------------------
// transpose+split: W [K,N] fp32 -> th, tl [N,K] bf16
// ---------------------------------------------------------------------------
__global__ void tsplit_kernel(const float* __restrict__ W,
                              __nv_bfloat16* __restrict__ th,
                              __nv_bfloat16* __restrict__ tl,
                              int K, int N)
{
    __shared__ float t[32][33];
    const int kb = blockIdx.y * 32, nb = blockIdx.x * 32;
    const int tx = threadIdx.x, ty = threadIdx.y;
#pragma unroll
    for (int j = 0; j < 32; j += 8)
        t[ty + j][tx] = W[(size_t)(kb + ty + j) * N + nb + tx];
    __syncthreads();
#pragma unroll
    for (int j = 0; j < 32; j += 8) {
        float v = t[tx][ty + j];
        __nv_bfloat16 h = __float2bfloat16(v);
        th[(size_t)(nb + ty + j) * K + kb + tx] = h;
        tl[(size_t)(nb + ty + j) * K + kb + tx] = __float2bfloat16(v - __bfloat162float(h));
    }
}

// ---------------------------------------------------------------------------
// HMMA bf16 3-split GEMM, 2-stage cp.async double buffer.
// C[M,N] = A[M,K] @ B[K,N] + bias (optional GELU)
// A as (Ahi, Alo) [M,K]; B transposed as (BThi, BTlo) [N,K]. fp32 accumulate.
// Logical chunks: (hi,hi),(hi,lo),(lo,hi) over K in steps of 64.
// CTA = BM x BN, 256 threads = 8 warps arranged (BM/64) x (8/(BM/64)).
// Warp tile = 64 x (BN/warps_n). M%BM==0, N%BN==0, K%64==0.
// ---------------------------------------------------------------------------
template <int BM, int BN, bool GELU>
__global__ void __launch_bounds__(256, 2)
gemm_hmma(const __nv_bfloat16* __restrict__ Ahi, const __nv_bfloat16* __restrict__ Alo,
          const __nv_bfloat16* __restrict__ BThi, const __nv_bfloat16* __restrict__ BTlo,
          const float* __restrict__ bias, float* __restrict__ C,
          int M, int N, int K)
{
    constexpr int ASZ = BM * 128;           // bytes per A chunk tile (BM x 64 bf16)
    constexpr int BSZ = BN * 128;           // bytes per B chunk tile
    constexpr int STG = ASZ + BSZ;
    constexpr int WM  = BM / 64;            // warps in m (1 or 2)
    constexpr int WN  = 8 / WM;             // warps in n (8 or 4)
    constexpr int WTN = BN / WN;            // warp tile N
    constexpr int NF  = WTN / 8;            // n fragments per warp (>=1)

    extern __shared__ char smem_raw[];
    const uint32_t tile0 = (smem_to_u32(smem_raw) + 1023) & ~1023u;

    const int tid = threadIdx.x;
    const int wid = tid >> 5, lane = tid & 31;
    const int wm = (WM == 1) ? 0 : (wid & 1);
    const int wn = (WM == 1) ? wid : (wid >> 1);
    const int bm = blockIdx.y * BM;
    const int bn = blockIdx.x * BN;
    const int KC = K >> 6;
    const int NC = 3 * KC;

    float acc[4][NF][4];
#pragma unroll
    for (int mf = 0; mf < 4; mf++)
#pragma unroll
        for (int nf = 0; nf < NF; nf++)
#pragma unroll
            for (int i = 0; i < 4; i++) acc[mf][nf][i] = 0.f;

    auto stage = [&](int c) {
        const int buf = c & 1;
        const int blk = c / KC;
        const int k0  = (c - blk * KC) << 6;
        const __nv_bfloat16* Asrc = ((blk < 2) ? Ahi : Alo) + (size_t)bm * K + k0;
        const __nv_bfloat16* Bsrc = ((blk == 1) ? BTlo : BThi) + (size_t)bn * K + k0;
        const uint32_t ab = tile0 + buf * STG;
        const uint32_t bb = ab + ASZ;
#pragma unroll
        for (int i = 0; i < BM / 32; i++) {                 // A: BM*8 x 16B
            int u = i * 256 + tid;
            int row = u >> 3, seg = u & 7;
            uint32_t off = row * 128 + seg * 16;
            cp_async16(ab + SMEM_SWIZZLE_128B(off), Asrc + (size_t)row * K + seg * 8);
        }
#pragma unroll
        for (int i = 0; i < BN / 32; i++) {                 // B: BN*8 x 16B
            int u = i * 256 + tid;
            int row = u >> 3, seg = u & 7;
            uint32_t off = row * 128 + seg * 16;
            cp_async16(bb + SMEM_SWIZZLE_128B(off), Bsrc + (size_t)row * K + seg * 8);
        }
    };

    auto compute = [&](int buf) {
        const uint32_t ab = tile0 + buf * STG;
        const uint32_t bb = ab + ASZ;
#pragma unroll
        for (int k16 = 0; k16 < 4; k16++) {
            uint32_t ar[4][4];
#pragma unroll
            for (int mf = 0; mf < 4; mf++) {
                int row = wm * 64 + mf * 16 + (lane & 15);
                uint32_t off = row * 128 + k16 * 32 + ((lane >> 4) << 4);
                ldsm_x4(ab + SMEM_SWIZZLE_128B(off), ar[mf][0], ar[mf][1], ar[mf][2], ar[mf][3]);
            }
            uint32_t br[NF][2];
            if (NF == 1) {
                int n = wn * WTN + (lane & 7);
                uint32_t off = n * 128 + k16 * 32 + (((lane >> 3) & 1) << 4);
                ldsm_x2(bb + SMEM_SWIZZLE_128B(off), br[0][0], br[0][1]);
            } else {
#pragma unroll
                for (int nb = 0; nb < NF / 2; nb++) {
                    int grp = lane >> 3;
                    int n = wn * WTN + nb * 16 + ((grp >> 1) << 3) + (lane & 7);
                    uint32_t off = n * 128 + k16 * 32 + ((grp & 1) << 4);
                    ldsm_x4(bb + SMEM_SWIZZLE_128B(off),
                            br[2*nb][0], br[2*nb][1], br[2*nb+1][0], br[2*nb+1][1]);
                }
            }
#pragma unroll
            for (int mf = 0; mf < 4; mf++)
#pragma unroll
                for (int nf = 0; nf < NF; nf++)
                    mma16816(acc[mf][nf][0], acc[mf][nf][1], acc[mf][nf][2], acc[mf][nf][3],
                             ar[mf][0], ar[mf][1], ar[mf][2], ar[mf][3],
                             br[nf][0], br[nf][1]);
        }
    };

    // 2-stage cp.async double buffer (2 CTAs/SM)
    stage(0); CP_COMMIT();
    stage(1); CP_COMMIT();
    for (int c = 0; c < NC; c++) {
        if (c + 1 < NC) CP_WAIT1(); else CP_WAIT0();
        __syncthreads();
        compute(c & 1);
        if (c + 2 < NC) {
            __syncthreads();
            stage(c + 2);
            CP_COMMIT();
        }
    }

    // epilogue
#pragma unroll
    for (int nf = 0; nf < NF; nf++) {
        int col = bn + wn * WTN + nf * 8 + ((lane & 3) << 1);
        float2 bv = *(const float2*)(bias + col);
#pragma unroll
        for (int mf = 0; mf < 4; mf++) {
            int row = bm + wm * 64 + mf * 16 + (lane >> 2);
            float x0 = acc[mf][nf][0] + bv.x;
            float x1 = acc[mf][nf][1] + bv.y;
            float x2 = acc[mf][nf][2] + bv.x;
            float x3 = acc[mf][nf][3] + bv.y;
            if (GELU) { x0 = gelu_f(x0); x1 = gelu_f(x1); x2 = gelu_f(x2); x3 = gelu_f(x3); }
            *(float2*)&C[(size_t)row * N + col]       = make_float2(x0, x1);
            *(float2*)&C[(size_t)(row + 8) * N + col] = make_float2(x2, x3);
        }
    }
}

// ---------------------------------------------------------------------------
// am = mean over tokens of adapt (deterministic two-stage reduction)
// ---------------------------------------------------------------------------
__global__ void colsum_part_kernel(const float* __restrict__ adapt, float* __restrict__ part)
{
    const int j = threadIdx.x;
    const int b = blockIdx.x;
    float s = 0.f;
#pragma unroll 8
    for (int r = 0; r < 128; r++) s += adapt[(size_t)(b * 128 + r) * ADIM + j];
    part[b * ADIM + j] = s;
}
__global__ void colsum_fin_kernel(const float* __restrict__ part, float* __restrict__ am)
{
    const int j = threadIdx.x;
    float s = 0.f;
#pragma unroll
    for (int b = 0; b < 32; b++) s += part[b * ADIM + j];
    am[j] = s * (1.0f / (float)NTOK);
}

// ---------------------------------------------------------------------------
// Dynamic weights (float4-vectorized, memory-bound)
// ---------------------------------------------------------------------------
__global__ void dynw_kernel(const float* __restrict__ Wt,  const float* __restrict__ Wt_a, const float* __restrict__ bt_a,
                            const float* __restrict__ Wc,  const float* __restrict__ Wc_a, const float* __restrict__ bc_a,
                            const float* __restrict__ We,  const float* __restrict__ We_a, const float* __restrict__ be_a,
                            const float* __restrict__ am,  float* __restrict__ Wdyn)
{
    __shared__ float ams[ADIM];
    const int tid = threadIdx.x;
    if (tid < ADIM) ams[tid] = am[tid];
    __syncthreads();

    const int idx4 = blockIdx.x * 256 + tid;
    const int k    = idx4 / 384;
    const int c4   = (idx4 - k * 384) * 4;

    const float *Wa, *ba, *base;
    int m;
    if (c4 < 256)      { m = k * 256 + c4;          base = Wt; Wa = Wt_a; ba = bt_a; }
    else if (c4 < 512) { m = k * 256 + (c4 - 256);  base = Wc; Wa = Wc_a; ba = bc_a; }
    else {
        int e  = (c4 - 512) >> 8;
        int jj = (c4 - 512) & 255;
        m = k * 256 + jj;
        base = We + e * 65536;
        Wa   = We_a + (size_t)e * 8388608u;
        ba   = be_a + e * 65536;
    }
    float4 acc = *(const float4*)(base + m);
    float4 b4  = *(const float4*)(ba + m);
    acc.x += b4.x; acc.y += b4.y; acc.z += b4.z; acc.w += b4.w;
#pragma unroll 4
    for (int a = 0; a < ADIM; a++) {
        float s = ams[a];
        float4 w = *(const float4*)(Wa + (size_t)a * 65536 + m);
        acc.x = fmaf(s, w.x, acc.x);
        acc.y = fmaf(s, w.y, acc.y);
        acc.z = fmaf(s, w.z, acc.z);
        acc.w = fmaf(s, w.w, acc.w);
    }
    *(float4*)(Wdyn + (size_t)idx4 * 4) = acc;
}

__global__ void bcat_kernel(const float* __restrict__ bt, const float* __restrict__ bc,
                            const float* __restrict__ be, float* __restrict__ bcat)
{
    int c = blockIdx.x * 256 + threadIdx.x;
    if (c >= DSUM) return;
    if (c < 256)      bcat[c] = bt[c];
    else if (c < 512) bcat[c] = bc[c - 256];
    else              bcat[c] = be[c - 512];
}

// ---------------------------------------------------------------------------
// gate = softmax(adapt @ Wg + bg) — one warp per token
// ---------------------------------------------------------------------------
__global__ void gate_kernel(const float* __restrict__ adapt, const float* __restrict__ Wg,
                            const float* __restrict__ bg, float* __restrict__ gate)
{
    __shared__ float wgs[ADIM * 5];
    __shared__ float bgs[5];
    const int tid = threadIdx.x;
    for (int i = tid; i < ADIM * 5; i += 256) wgs[i] = Wg[i];
    if (tid < 5) bgs[tid] = bg[tid];
    __syncthreads();

    const int warp = tid >> 5, lane = tid & 31;
    const int n = (blockIdx.x << 3) + warp;

    float4 a4 = *(const float4*)(adapt + (size_t)n * ADIM + lane * 4);
    float av[4] = { a4.x, a4.y, a4.z, a4.w };
    float l[5] = { 0, 0, 0, 0, 0 };
#pragma unroll
    for (int q = 0; q < 4; q++) {
        int a = lane * 4 + q;
#pragma unroll
        for (int j = 0; j < 5; j++) l[j] = fmaf(av[q], wgs[a * 5 + j], l[j]);
    }
#pragma unroll
    for (int off = 16; off; off >>= 1)
#pragma unroll
        for (int j = 0; j < 5; j++) l[j] += __shfl_xor_sync(0xffffffffu, l[j], off);

    if (lane == 0) {
#pragma unroll
        for (int j = 0; j < 5; j++) l[j] += bgs[j];
        float mx = fmaxf(fmaxf(fmaxf(l[0], l[1]), fmaxf(l[2], l[3])), l[4]);
        float s = 0.f;
#pragma unroll
        for (int j = 0; j < 5; j++) { l[j] = __expf(l[j] - mx); s += l[j]; }
        float inv = 1.0f / s;
#pragma unroll
        for (int j = 0; j < 5; j++) gate[n * 5 + j] = l[j] * inv;
    }
}

// ---------------------------------------------------------------------------
// KA expert stage-1 partials (FFMA2 path)
// ---------------------------------------------------------------------------
__global__ void __launch_bounds__(256)
ka_part_kernel(const float* __restrict__ xf, const float* __restrict__ Wphi,
               const float* __restrict__ bphi, const float* __restrict__ Wpsi1,
               float* __restrict__ part)
{
    __shared__ float xs[32][65];
    __shared__ float ph[64][68];
    __shared__ float ws[64 * 64];

    const int tid   = threadIdx.x;
    const int ttile = blockIdx.x >> 1;
    const int half  = blockIdx.x & 1;
    const int t0    = ttile << 6;
    const int dbase = half << 7;

    const int tr = (tid >> 4) << 2;
    const int tc = (tid & 15) << 2;
    const int h  = tid & 63;
    const int tg = (tid >> 6) << 4;

    const int xtok = tid >> 2;
    const int xdq  = (tid & 3) << 3;

    ull acc[4][2];
#pragma unroll
    for (int i = 0; i < 4; i++) { acc[i][0] = 0ull; acc[i][1] = 0ull; }

    for (int chunk = 0; chunk < 4; chunk++) {
        const int d0 = dbase + (chunk << 5);
        {
            const float* xp = xf + (size_t)(t0 + xtok) * 256 + d0 + xdq;
            float4 v0 = *(const float4*)(xp);
            float4 v1 = *(const float4*)(xp + 4);
            xs[xdq + 0][xtok] = v0.x; xs[xdq + 1][xtok] = v0.y;
            xs[xdq + 2][xtok] = v0.z; xs[xdq + 3][xtok] = v0.w;
            xs[xdq + 4][xtok] = v1.x; xs[xdq + 5][xtok] = v1.y;
            xs[xdq + 6][xtok] = v1.z; xs[xdq + 7][xtok] = v1.w;
        }
        __syncthreads();

        for (int dd = 0; dd < 32; dd++) {
            const int d = d0 + dd;
            float wp = __ldg(Wphi + (d << 6) + h);
            float bp = __ldg(bphi + (d << 6) + h);
#pragma unroll
            for (int t2 = 0; t2 < 16; t2++) {
                int t = tg + t2;
                ph[h][t] = gelu_f(fmaf(xs[dd][t], wp, bp));
            }
            {
                const float4* wsrc = (const float4*)(Wpsi1 + ((size_t)d << 12));
                float4* wdst = (float4*)ws;
#pragma unroll
                for (int r = 0; r < 4; r++) wdst[tid + (r << 8)] = wsrc[tid + (r << 8)];
            }
            __syncthreads();
#pragma unroll
            for (int hh = 0; hh < 64; hh++) {
                float4 pv = *(const float4*)&ph[hh][tr];
                float4 wv = *(const float4*)&ws[(hh << 6) + tc];
                ull w01 = pack2(wv.x, wv.y);
                ull w23 = pack2(wv.z, wv.w);
                float pa[4] = { pv.x, pv.y, pv.z, pv.w };
#pragma unroll
                for (int i = 0; i < 4; i++) {
                    ull pp = pack2(pa[i], pa[i]);
                    acc[i][0] = ffma2(pp, w01, acc[i][0]);
                    acc[i][1] = ffma2(pp, w23, acc[i][1]);
                }
            }
            __syncthreads();
        }
    }

    float* pout = part + ((size_t)half * NTOK + t0) * HIDD;
#pragma unroll
    for (int i = 0; i < 4; i++) {
        float x0, x1, x2, x3;
        unpack2(acc[i][0], x0, x1);
        unpack2(acc[i][1], x2, x3);
        *(float4*)(pout + (size_t)(tr + i) * HIDD + tc) = make_float4(x0, x1, x2, x3);
    }
}

// tpsi = gelu(part0 + part1 + bpsi1) -> emitted directly as bf16 hi/lo
__global__ void ka_finish_kernel(const float* __restrict__ part,
                                 const float* __restrict__ bpsi1,
                                 __nv_bfloat16* __restrict__ tph,
                                 __nv_bfloat16* __restrict__ tpl)
{
    const int idx = blockIdx.x * 256 + threadIdx.x;   // float4 index, 65536 total
    const int jq = idx & 15;
    float4 a = ((const float4*)part)[idx];
    float4 b = ((const float4*)part)[65536 + idx];
    float4 bb = ((const float4*)bpsi1)[jq];
    float o[4];
    o[0] = gelu_f(a.x + b.x + bb.x);
    o[1] = gelu_f(a.y + b.y + bb.y);
    o[2] = gelu_f(a.z + b.z + bb.z);
    o[3] = gelu_f(a.w + b.w + bb.w);
#pragma unroll
    for (int q = 0; q < 4; q++) split_store(o[q], tph + idx * 4 + q, tpl + idx * 4 + q);
}

// ---------------------------------------------------------------------------
// concat[n] = [tok, chan, moe, lf]; also emits bf16 hi/lo
// ---------------------------------------------------------------------------
__global__ void concat_kernel(const float* __restrict__ mix, const float* __restrict__ gate,
                              const float* __restrict__ ka, const float* __restrict__ lf,
                              float* __restrict__ concat,
                              __nv_bfloat16* __restrict__ cth, __nv_bfloat16* __restrict__ ctl)
{
    const int n = blockIdx.x;
    const int t = threadIdx.x;
    __shared__ float g[5];
    if (t < 5) g[t] = gate[n * 5 + t];
    __syncthreads();

    const float4* mx = (const float4*)(mix + (size_t)n * DSUM);
    float4 out;
    if (t < 128) {
        out = mx[t];
    } else if (t < 192) {
        int dq = t - 128;
        float4 e0 = mx[128 + dq], e1 = mx[192 + dq], e2 = mx[256 + dq], e3 = mx[320 + dq];
        float4 k4 = ((const float4*)(ka + (size_t)n * DDIM))[dq];
        out.x = g[0]*e0.x + g[1]*e1.x + g[2]*e2.x + g[3]*e3.x + g[4]*k4.x;
        out.y = g[0]*e0.y + g[1]*e1.y + g[2]*e2.y + g[3]*e3.y + g[4]*k4.y;
        out.z = g[0]*e0.z + g[1]*e1.z + g[2]*e2.z + g[3]*e3.z + g[4]*k4.z;
        out.w = g[0]*e0.w + g[1]*e1.w + g[2]*e2.w + g[3]*e3.w + g[4]*k4.w;
    } else {
        out = ((const float4*)(lf + (size_t)n * DLF))[t - 192];
    }
    ((float4*)(concat + (size_t)n * DSUM))[t] = out;
    const size_t e = (size_t)n * DSUM + t * 4;
    split_store(out.x, cth + e + 0, ctl + e + 0);
    split_store(out.y, cth + e + 1, ctl + e + 1);
    split_store(out.z, cth + e + 2, ctl + e + 2);
    split_store(out.w, cth + e + 3, ctl + e + 3);
}

// ---------------------------------------------------------------------------
// combine: cw = softmax(h @ W2 + b2); comb = cw[sec]*concat + resid (bf16 out)
// ---------------------------------------------------------------------------
__global__ void combine_kernel(const float* __restrict__ h, const float* __restrict__ W2,
                               const float* __restrict__ b2, const float* __restrict__ concat,
                               const float* __restrict__ resid,
                               __nv_bfloat16* __restrict__ cbh, __nv_bfloat16* __restrict__ cbl)
{
    __shared__ float w2s[256];
    const int tid = threadIdx.x;
    w2s[tid] = W2[tid];
    __syncthreads();

    const int warp = tid >> 5, lane = tid & 31;
    const int n = (blockIdx.x << 3) + warp;

    float2 hv = *(const float2*)(h + (size_t)n * HIDD + lane * 2);
    const int a0 = lane * 2, a1 = lane * 2 + 1;
    float l0 = hv.x * w2s[a0*4+0] + hv.y * w2s[a1*4+0];
    float l1 = hv.x * w2s[a0*4+1] + hv.y * w2s[a1*4+1];
    float l2 = hv.x * w2s[a0*4+2] + hv.y * w2s[a1*4+2];
    float l3 = hv.x * w2s[a0*4+3] + hv.y * w2s[a1*4+3];
#pragma unroll
    for (int off = 16; off; off >>= 1) {
        l0 += __shfl_xor_sync(0xffffffffu, l0, off);
        l1 += __shfl_xor_sync(0xffffffffu, l1, off);
        l2 += __shfl_xor_sync(0xffffffffu, l2, off);
        l3 += __shfl_xor_sync(0xffffffffu, l3, off);
    }
    l0 += __ldg(b2 + 0); l1 += __ldg(b2 + 1); l2 += __ldg(b2 + 2); l3 += __ldg(b2 + 3);
    float mx = fmaxf(fmaxf(l0, l1), fmaxf(l2, l3));
    float e0 = __expf(l0 - mx), e1 = __expf(l1 - mx), e2 = __expf(l2 - mx), e3 = __expf(l3 - mx);
    float inv = 1.0f / (e0 + e1 + e2 + e3);
    float cw0 = e0 * inv, cw1 = e1 * inv, cw2 = e2 * inv, cw3 = e3 * inv;

    const float4* cc = (const float4*)(concat + (size_t)n * DSUM);
    const float4* rr = (const float4*)(resid  + (size_t)n * DSUM);
#pragma unroll
    for (int q = 0; q < 12; q++) {
        int c4 = lane + (q << 5);
        float w = (c4 < 64) ? cw0 : (c4 < 128) ? cw1 : (c4 < 192) ? cw2 : cw3;
        float4 cv = cc[c4], rv = rr[c4];
        float v0 = fmaf(w, cv.x, rv.x), v1 = fmaf(w, cv.y, rv.y);
        float v2 = fmaf(w, cv.z, rv.z), v3 = fmaf(w, cv.w, rv.w);
        const size_t e = (size_t)n * DSUM + c4 * 4;
        split_store(v0, cbh + e + 0, cbl + e + 0);
        split_store(v1, cbh + e + 1, cbl + e + 1);
        split_store(v2, cbh + e + 2, cbl + e + 2);
        split_store(v3, cbh + e + 3, cbl + e + 3);
    }
}

// ---------------------------------------------------------------------------
// Host launcher
// ---------------------------------------------------------------------------
extern "C" void kernel_launch(void* const* d_in, const int* in_sizes, int n_in,
                              void* d_out, int out_size)
{
    (void)in_sizes; (void)n_in; (void)out_size;

    const float* x      = (const float*)d_in[0];
    const float* lf     = (const float*)d_in[1];
    const float* W_feat = (const float*)d_in[2];
    const float* b_feat = (const float*)d_in[3];
    const float* Wt     = (const float*)d_in[4];
    const float* bt     = (const float*)d_in[5];
    const float* Wt_a   = (const float*)d_in[6];
    const float* bt_a   = (const float*)d_in[7];
    const float* Wc     = (const float*)d_in[8];
    const float* bc     = (const float*)d_in[9];
    const float* Wc_a   = (const float*)d_in[10];
    const float* bc_a   = (const float*)d_in[11];
    const float* We     = (const float*)d_in[12];
    const float* be     = (const float*)d_in[13];
    const float* We_a   = (const float*)d_in[14];
    const float* be_a   = (const float*)d_in[15];
    const float* Wg     = (const float*)d_in[16];
    const float* bg     = (const float*)d_in[17];
    const float* Wphi   = (const float*)d_in[18];
    const float* bphi   = (const float*)d_in[19];
    const float* Wpsi1  = (const float*)d_in[20];
    const float* bpsi1  = (const float*)d_in[21];
    const float* Wpsi2  = (const float*)d_in[22];
    const float* bpsi2  = (const float*)d_in[23];
    const float* Wres   = (const float*)d_in[24];
    const float* bres   = (const float*)d_in[25];
    const float* W1     = (const float*)d_in[26];
    const float* b1     = (const float*)d_in[27];
    const float* W2     = (const float*)d_in[28];
    const float* b2     = (const float*)d_in[29];
    const float* Wo     = (const float*)d_in[30];
    const float* bo     = (const float*)d_in[31];
    float* out = (float*)d_out;

    float* s = nullptr;
    cudaGetSymbolAddress((void**)&s, g_scratch);
    float* adapt  = s + OFF_ADAPT;
    float* am     = s + OFF_AM;
    float* part   = s + OFF_PART;
    float* gate   = s + OFF_GATE;
    float* Wdyn   = s + OFF_WDYN;
    float* bcat   = s + OFF_BCAT;
    float* mix    = s + OFF_MIX;
    float* ka     = s + OFF_KA;
    float* concat = s + OFF_CONCAT;
    float* resid  = s + OFF_RESID;
    float* hbuf   = s + OFF_H;
    float* kapart = s + OFF_KAPART;

    __nv_bfloat16* bb = (__nv_bfloat16*)(s + OFF_BF16);
    __nv_bfloat16 *xh = bb + BF_XH,   *xl = bb + BF_XL;
    __nv_bfloat16 *wfh = bb + BF_WFH, *wfl = bb + BF_WFL;
    __nv_bfloat16 *wdh = bb + BF_WDH, *wdl = bb + BF_WDL;
    __nv_bfloat16 *tph = bb + BF_TPH, *tpl = bb + BF_TPL;
    __nv_bfloat16 *wph = bb + BF_WPH, *wpl = bb + BF_WPL;
    __nv_bfloat16 *cth = bb + BF_CATH, *ctl = bb + BF_CATL;
    __nv_bfloat16 *wrh = bb + BF_WRH, *wrl = bb + BF_WRL;
    __nv_bfloat16 *w1h = bb + BF_W1H, *w1l = bb + BF_W1L;
    __nv_bfloat16 *cbh = bb + BF_CBH, *cbl = bb + BF_CBL;
    __nv_bfloat16 *woh = bb + BF_WOH, *wol = bb + BF_WOL;

    const int SM_128_128 = 2 * (16384 + 16384) + 1024;  // 66560
    const int SM_64_128  = 2 * (8192  + 16384) + 1024;  // 50176
    const int SM_64_64   = 2 * (8192  + 8192)  + 1024;  // 33792
    cudaFuncSetAttribute(gemm_hmma<128, 128, false>, cudaFuncAttributeMaxDynamicSharedMemorySize, SM_128_128);
    cudaFuncSetAttribute(gemm_hmma<64, 128, false>,  cudaFuncAttributeMaxDynamicSharedMemorySize, SM_64_128);
    cudaFuncSetAttribute(gemm_hmma<64, 64, true>,    cudaFuncAttributeMaxDynamicSharedMemorySize, SM_64_64);

    // Launch order keeps launch #4 = adapt GEMM (ncu capture window).
    // 1. x split
    split_kernel<<<1024, 256>>>(x, xh, xl);
    // 2. W_feat transpose-split
    tsplit_kernel<<<dim3(ADIM/32, DDIM/32), dim3(32,8)>>>(W_feat, wfh, wfl, DDIM, ADIM);
    // 3. Wpsi2 transpose-split
    tsplit_kernel<<<dim3(DDIM/32, HIDD/32), dim3(32,8)>>>(Wpsi2, wph, wpl, HIDD, DDIM);
    // 4. adapt = x @ W_feat + b_feat          [4096,128]   <-- ncu window
    gemm_hmma<64, 128, false><<<dim3(1, 64), 256, SM_64_128>>>(xh, xl, wfh, wfl, b_feat, adapt, NTOK, ADIM, DDIM);
    // 5-7. remaining weight transposes
    tsplit_kernel<<<dim3(DSUM/32, DSUM/32), dim3(32,8)>>>(Wres, wrh, wrl, DSUM, DSUM);
    tsplit_kernel<<<dim3(HIDD/32, DSUM/32), dim3(32,8)>>>(W1, w1h, w1l, DSUM, HIDD);
    tsplit_kernel<<<dim3(DDIM/32, DSUM/32), dim3(32,8)>>>(Wo, woh, wol, DSUM, DDIM);
    // 8-9. am
    colsum_part_kernel<<<32, 128>>>(adapt, part);
    colsum_fin_kernel<<<1, 128>>>(part, am);
    // 10-12. dynamic weights + transpose-split + bias concat
    dynw_kernel<<<384, 256>>>(Wt, Wt_a, bt_a, Wc, Wc_a, bc_a, We, We_a, be_a, am, Wdyn);
    tsplit_kernel<<<dim3(DSUM/32, DDIM/32), dim3(32,8)>>>(Wdyn, wdh, wdl, DDIM, DSUM);
    bcat_kernel<<<6, 256>>>(bt, bc, be, bcat);
    // 13. gate softmax
    gate_kernel<<<NTOK / 8, 256>>>(adapt, Wg, bg, gate);
    // 14. mix = x @ Wdyn + bcat               [4096,1536]
    gemm_hmma<128, 128, false><<<dim3(12, 32), 256, SM_128_128>>>(xh, xl, wdh, wdl, bcat, mix, NTOK, DSUM, DDIM);
    // 15-16. KA stage 1 (finish emits bf16 hi/lo directly)
    ka_part_kernel<<<128, 256>>>(x, Wphi, bphi, Wpsi1, kapart);
    ka_finish_kernel<<<256, 256>>>(kapart, bpsi1, tph, tpl);
    // 17. ka = tpsi @ Wpsi2 + bpsi2           [4096,256]
    gemm_hmma<64, 128, false><<<dim3(2, 64), 256, SM_64_128>>>(tph, tpl, wph, wpl, bpsi2, ka, NTOK, DDIM, HIDD);
    // 18. concat (+ bf16 hi/lo)
    concat_kernel<<<NTOK, 384>>>(mix, gate, ka, lf, concat, cth, ctl);
    // 19. residual = concat @ Wres + bres     [4096,1536]
    gemm_hmma<128, 128, false><<<dim3(12, 32), 256, SM_128_128>>>(cth, ctl, wrh, wrl, bres, resid, NTOK, DSUM, DSUM);
    // 20. h = gelu(concat @ W1 + b1)          [4096,64]
    gemm_hmma<64, 64, true><<<dim3(1, 64), 256, SM_64_64>>>(cth, ctl, w1h, w1l, b1, hbuf, NTOK, HIDD, DSUM);
    // 21. combine (emits bf16 hi/lo only)
    combine_kernel<<<NTOK / 8, 256>>>(hbuf, W2, b2, concat, resid, cbh, cbl);
    // 22. out = comb @ Wo + bo                [4096,256]
    gemm_hmma<64, 128, false><<<dim3(2, 64), 256, SM_64_128>>>(cbh, cbl, woh, wol, bo, out, NTOK, DDIM, DSUM);
}

// round 8
// speedup vs baseline: 2.2850x; 1.1150x over previous
#include <cuda_runtime.h>
#include <cuda_bf16.h>
#include <math.h>
#include <stdint.h>

// ---------------------------------------------------------------------------
// Problem constants
// ---------------------------------------------------------------------------
#define NTOK   4096      // B*S
#define DDIM   256
#define DLF    768
#define ADIM   128
#define DSUM   1536
#define HIDD   64

typedef unsigned long long ull;

// ---------------------------------------------------------------------------
// helpers
// ---------------------------------------------------------------------------
__device__ __forceinline__ ull pack2(float lo, float hi) {
    ull r; asm("mov.b64 %0, {%1,%2};" : "=l"(r) : "f"(lo), "f"(hi)); return r;
}
__device__ __forceinline__ void unpack2(ull p, float& lo, float& hi) {
    asm("mov.b64 {%0,%1}, %2;" : "=f"(lo), "=f"(hi) : "l"(p));
}
__device__ __forceinline__ ull ffma2(ull a, ull b, ull c) {
    ull d; asm("fma.rn.f32x2 %0, %1, %2, %3;" : "=l"(d) : "l"(a), "l"(b), "l"(c)); return d;
}
__device__ __forceinline__ float gelu_f(float v) {
    return 0.5f * v * (1.0f + erff(v * 0.70710678118654752440f));
}
__device__ __forceinline__ uint32_t smem_to_u32(const void* p) {
    uint32_t a;
    asm("{ .reg .u64 t; cvta.to.shared.u64 t, %1; cvt.u32.u64 %0, t; }" : "=r"(a) : "l"(p));
    return a;
}
#define SMEM_SWIZZLE_128B(o) ((o) ^ (((o) >> 3) & 0x70))

__device__ __forceinline__ void cp_async16(uint32_t saddr, const void* gptr) {
    asm volatile("cp.async.cg.shared.global [%0], [%1], 16;" :: "r"(saddr), "l"(gptr));
}
#define CP_COMMIT() asm volatile("cp.async.commit_group;" ::: "memory")
#define CP_WAIT1()  asm volatile("cp.async.wait_group 1;"  ::: "memory")
#define CP_WAIT0()  asm volatile("cp.async.wait_group 0;"  ::: "memory")

__device__ __forceinline__ void ldsm_x4(uint32_t addr, uint32_t& r0, uint32_t& r1,
                                        uint32_t& r2, uint32_t& r3) {
    asm volatile("ldmatrix.sync.aligned.m8n8.x4.shared.b16 {%0,%1,%2,%3}, [%4];"
                 : "=r"(r0), "=r"(r1), "=r"(r2), "=r"(r3) : "r"(addr));
}
__device__ __forceinline__ void ldsm_x2(uint32_t addr, uint32_t& r0, uint32_t& r1) {
    asm volatile("ldmatrix.sync.aligned.m8n8.x2.shared.b16 {%0,%1}, [%2];"
                 : "=r"(r0), "=r"(r1) : "r"(addr));
}
__device__ __forceinline__ void mma16816(float& c0, float& c1, float& c2, float& c3,
                                         uint32_t a0, uint32_t a1, uint32_t a2, uint32_t a3,
                                         uint32_t b0, uint32_t b1) {
    asm volatile("mma.sync.aligned.m16n8k16.row.col.f32.bf16.bf16.f32 "
                 "{%0,%1,%2,%3}, {%4,%5,%6,%7}, {%8,%9}, {%0,%1,%2,%3};"
                 : "+f"(c0), "+f"(c1), "+f"(c2), "+f"(c3)
                 : "r"(a0), "r"(a1), "r"(a2), "r"(a3), "r"(b0), "r"(b1));
}

__device__ __forceinline__ void split_store(float v, __nv_bfloat16* hi, __nv_bfloat16* lo) {
    __nv_bfloat16 h = __float2bfloat16(v);
    *hi = h;
    *lo = __float2bfloat16(v - __bfloat162float(h));
}

// ---------------------------------------------------------------------------
// Scratch (fp32 region then bf16 region)
// ---------------------------------------------------------------------------
#define OFF_ADAPT   0u
#define OFF_AM      524288u
#define OFF_PART    524416u
#define OFF_GATE    528512u
#define OFF_WDYN    548992u
#define OFF_BCAT    942208u
#define OFF_MIX     943744u
#define OFF_KA      7497344u
#define OFF_CONCAT  8545920u
#define OFF_RESID   14837376u
#define OFF_H       21128832u
#define OFF_KAPART  27682432u
#define OFF_BF16    28206720u          // start of bf16 region (float units)

// bf16 offsets (in bf16 elements from bf16 base)
#define BF_XH   0u
#define BF_XL   1048576u
#define BF_WFH  2097152u
#define BF_WFL  2129920u
#define BF_WDH  2162688u
#define BF_WDL  2555904u
#define BF_TPH  2949120u
#define BF_TPL  3211264u
#define BF_WPH  3473408u
#define BF_WPL  3489792u
#define BF_CATH 3506176u
#define BF_CATL 9797632u
#define BF_WRH  16089088u
#define BF_WRL  18448384u
#define BF_W1H  20807680u
#define BF_W1L  20905984u
#define BF_CBH  21004288u
#define BF_CBL  27295744u
#define BF_WOH  33587200u
#define BF_WOL  33980416u

#define SCRATCH_FLOATS (28206720u + 17186816u)
__device__ float g_scratch[SCRATCH_FLOATS];

// ---------------------------------------------------------------------------
// split: fp32 [n] -> bf16 hi, lo
// ---------------------------------------------------------------------------
__global__ void split_kernel(const float* __restrict__ src,
                             __nv_bfloat16* __restrict__ hi,
                             __nv_bfloat16* __restrict__ lo)
{
    const int i = blockIdx.x * 256 + threadIdx.x;
    float4 v = ((const float4*)src)[i];
    __nv_bfloat16 hx = __float2bfloat16(v.x), hy = __float2bfloat16(v.y);
    __nv_bfloat16 hz = __float2bfloat16(v.z), hw = __float2bfloat16(v.w);
    __nv_bfloat162* hp = (__nv_bfloat162*)hi;
    __nv_bfloat162* lp = (__nv_bfloat162*)lo;
    hp[2*i]   = __nv_bfloat162(hx, hy);
    hp[2*i+1] = __nv_bfloat162(hz, hw);
    lp[2*i]   = __nv_bfloat162(__float2bfloat16(v.x - __bfloat162float(hx)),
                               __float2bfloat16(v.y - __bfloat162float(hy)));
    lp[2*i+1] = __nv_bfloat162(__float2bfloat16(v.z - __bfloat162float(hz)),
                               __float2bfloat16(v.w - __bfloat162float(hw)));
}

// ---------------------------------------------------------------------------
// transpose+split: W [K,N] fp32 -> th, tl [N,K] bf16
// ---------------------------------------------------------------------------
__global__ void tsplit_kernel(const float* __restrict__ W,
                              __nv_bfloat16* __restrict__ th,
                              __nv_bfloat16* __restrict__ tl,
                              int K, int N)
{
    __shared__ float t[32][33];
    const int kb = blockIdx.y * 32, nb = blockIdx.x * 32;
    const int tx = threadIdx.x, ty = threadIdx.y;
#pragma unroll
    for (int j = 0; j < 32; j += 8)
        t[ty + j][tx] = W[(size_t)(kb + ty + j) * N + nb + tx];
    __syncthreads();
#pragma unroll
    for (int j = 0; j < 32; j += 8) {
        float v = t[tx][ty + j];
        __nv_bfloat16 h = __float2bfloat16(v);
        th[(size_t)(nb + ty + j) * K + kb + tx] = h;
        tl[(size_t)(nb + ty + j) * K + kb + tx] = __float2bfloat16(v - __bfloat162float(h));
    }
}

// ---------------------------------------------------------------------------
// GEMM body (device function): HMMA bf16 3-split, 2-stage cp.async.
// C[M,N] = A[M,K] @ B[K,N] + bias (optional GELU); bm/bn are tile offsets.
// ---------------------------------------------------------------------------
template <int BM, int BN, bool GELU>
__device__ __forceinline__ void
gemm_body(const __nv_bfloat16* __restrict__ Ahi, const __nv_bfloat16* __restrict__ Alo,
          const __nv_bfloat16* __restrict__ BThi, const __nv_bfloat16* __restrict__ BTlo,
          const float* __restrict__ bias, float* __restrict__ C,
          int M, int N, int K, int bm, int bn, char* smem_raw)
{
    constexpr int ASZ = BM * 128;
    constexpr int BSZ = BN * 128;
    constexpr int STG = ASZ + BSZ;
    constexpr int WM  = BM / 64;
    constexpr int WN  = 8 / WM;
    constexpr int WTN = BN / WN;
    constexpr int NF  = WTN / 8;

    const uint32_t tile0 = (smem_to_u32(smem_raw) + 1023) & ~1023u;

    const int tid = threadIdx.x;
    const int wid = tid >> 5, lane = tid & 31;
    const int wm = (WM == 1) ? 0 : (wid & 1);
    const int wn = (WM == 1) ? wid : (wid >> 1);
    const int KC = K >> 6;
    const int NC = 3 * KC;

    float acc[4][NF][4];
#pragma unroll
    for (int mf = 0; mf < 4; mf++)
#pragma unroll
        for (int nf = 0; nf < NF; nf++)
#pragma unroll
            for (int i = 0; i < 4; i++) acc[mf][nf][i] = 0.f;

    auto stage = [&](int c) {
        const int buf = c & 1;
        const int blk = c / KC;
        const int k0  = (c - blk * KC) << 6;
        const __nv_bfloat16* Asrc = ((blk < 2) ? Ahi : Alo) + (size_t)bm * K + k0;
        const __nv_bfloat16* Bsrc = ((blk == 1) ? BTlo : BThi) + (size_t)bn * K + k0;
        const uint32_t ab = tile0 + buf * STG;
        const uint32_t bb = ab + ASZ;
#pragma unroll
        for (int i = 0; i < BM / 32; i++) {
            int u = i * 256 + tid;
            int row = u >> 3, seg = u & 7;
            uint32_t off = row * 128 + seg * 16;
            cp_async16(ab + SMEM_SWIZZLE_128B(off), Asrc + (size_t)row * K + seg * 8);
        }
#pragma unroll
        for (int i = 0; i < BN / 32; i++) {
            int u = i * 256 + tid;
            int row = u >> 3, seg = u & 7;
            uint32_t off = row * 128 + seg * 16;
            cp_async16(bb + SMEM_SWIZZLE_128B(off), Bsrc + (size_t)row * K + seg * 8);
        }
    };

    auto compute = [&](int buf) {
        const uint32_t ab = tile0 + buf * STG;
        const uint32_t bb = ab + ASZ;
#pragma unroll
        for (int k16 = 0; k16 < 4; k16++) {
            uint32_t ar[4][4];
#pragma unroll
            for (int mf = 0; mf < 4; mf++) {
                int row = wm * 64 + mf * 16 + (lane & 15);
                uint32_t off = row * 128 + k16 * 32 + ((lane >> 4) << 4);
                ldsm_x4(ab + SMEM_SWIZZLE_128B(off), ar[mf][0], ar[mf][1], ar[mf][2], ar[mf][3]);
            }
            uint32_t br[NF][2];
            if (NF == 1) {
                int n = wn * WTN + (lane & 7);
                uint32_t off = n * 128 + k16 * 32 + (((lane >> 3) & 1) << 4);
                ldsm_x2(bb + SMEM_SWIZZLE_128B(off), br[0][0], br[0][1]);
            } else {
#pragma unroll
                for (int nb = 0; nb < NF / 2; nb++) {
                    int grp = lane >> 3;
                    int n = wn * WTN + nb * 16 + ((grp >> 1) << 3) + (lane & 7);
                    uint32_t off = n * 128 + k16 * 32 + ((grp & 1) << 4);
                    ldsm_x4(bb + SMEM_SWIZZLE_128B(off),
                            br[2*nb][0], br[2*nb][1], br[2*nb+1][0], br[2*nb+1][1]);
                }
            }
#pragma unroll
            for (int mf = 0; mf < 4; mf++)
#pragma unroll
                for (int nf = 0; nf < NF; nf++)
                    mma16816(acc[mf][nf][0], acc[mf][nf][1], acc[mf][nf][2], acc[mf][nf][3],
                             ar[mf][0], ar[mf][1], ar[mf][2], ar[mf][3],
                             br[nf][0], br[nf][1]);
        }
    };

    stage(0); CP_COMMIT();
    stage(1); CP_COMMIT();
    for (int c = 0; c < NC; c++) {
        if (c + 1 < NC) CP_WAIT1(); else CP_WAIT0();
        __syncthreads();
        compute(c & 1);
        if (c + 2 < NC) {
            __syncthreads();
            stage(c + 2);
            CP_COMMIT();
        }
    }

#pragma unroll
    for (int nf = 0; nf < NF; nf++) {
        int col = bn + wn * WTN + nf * 8 + ((lane & 3) << 1);
        float2 bv = *(const float2*)(bias + col);
#pragma unroll
        for (int mf = 0; mf < 4; mf++) {
            int row = bm + wm * 64 + mf * 16 + (lane >> 2);
            float x0 = acc[mf][nf][0] + bv.x;
            float x1 = acc[mf][nf][1] + bv.y;
            float x2 = acc[mf][nf][2] + bv.x;
            float x3 = acc[mf][nf][3] + bv.y;
            if (GELU) { x0 = gelu_f(x0); x1 = gelu_f(x1); x2 = gelu_f(x2); x3 = gelu_f(x3); }
            *(float2*)&C[(size_t)row * N + col]       = make_float2(x0, x1);
            *(float2*)&C[(size_t)(row + 8) * N + col] = make_float2(x2, x3);
        }
    }
}

// standalone GEMM kernel wrapper
template <int BM, int BN, bool GELU>
__global__ void __launch_bounds__(256, 2)
gemm_hmma(const __nv_bfloat16* __restrict__ Ahi, const __nv_bfloat16* __restrict__ Alo,
          const __nv_bfloat16* __restrict__ BThi, const __nv_bfloat16* __restrict__ BTlo,
          const float* __restrict__ bias, float* __restrict__ C,
          int M, int N, int K)
{
    extern __shared__ char smem_raw[];
    gemm_body<BM, BN, GELU>(Ahi, Alo, BThi, BTlo, bias, C, M, N, K,
                            blockIdx.y * BM, blockIdx.x * BN, smem_raw);
}

// ---------------------------------------------------------------------------
// KA stage-1 body (FFMA2), smem carved from dynamic buffer.
// block b in [0,128): token tile = b>>1 (64 tokens), d-half = b&1.
// ---------------------------------------------------------------------------
__device__ __forceinline__ void
ka_part_body(const float* __restrict__ xf, const float* __restrict__ Wphi,
             const float* __restrict__ bphi, const float* __restrict__ Wpsi1,
             float* __restrict__ part, int b, char* smem_raw)
{
    float* xs = (float*)smem_raw;          // [32][65]  8320 B
    float* ph = xs + 32 * 65;              // [64][68]  17408 B
    float* ws = ph + 64 * 68;              // [64*64]   16384 B

    const int tid   = threadIdx.x;
    const int ttile = b >> 1;
    const int half  = b & 1;
    const int t0    = ttile << 6;
    const int dbase = half << 7;

    const int tr = (tid >> 4) << 2;
    const int tc = (tid & 15) << 2;
    const int h  = tid & 63;
    const int tg = (tid >> 6) << 4;

    const int xtok = tid >> 2;
    const int xdq  = (tid & 3) << 3;

    ull acc[4][2];
#pragma unroll
    for (int i = 0; i < 4; i++) { acc[i][0] = 0ull; acc[i][1] = 0ull; }

    for (int chunk = 0; chunk < 4; chunk++) {
        const int d0 = dbase + (chunk << 5);
        {
            const float* xp = xf + (size_t)(t0 + xtok) * 256 + d0 + xdq;
            float4 v0 = *(const float4*)(xp);
            float4 v1 = *(const float4*)(xp + 4);
            xs[(xdq + 0) * 65 + xtok] = v0.x; xs[(xdq + 1) * 65 + xtok] = v0.y;
            xs[(xdq + 2) * 65 + xtok] = v0.z; xs[(xdq + 3) * 65 + xtok] = v0.w;
            xs[(xdq + 4) * 65 + xtok] = v1.x; xs[(xdq + 5) * 65 + xtok] = v1.y;
            xs[(xdq + 6) * 65 + xtok] = v1.z; xs[(xdq + 7) * 65 + xtok] = v1.w;
        }
        __syncthreads();

        for (int dd = 0; dd < 32; dd++) {
            const int d = d0 + dd;
            float wp = __ldg(Wphi + (d << 6) + h);
            float bp = __ldg(bphi + (d << 6) + h);
#pragma unroll
            for (int t2 = 0; t2 < 16; t2++) {
                int t = tg + t2;
                ph[h * 68 + t] = gelu_f(fmaf(xs[dd * 65 + t], wp, bp));
            }
            {
                const float4* wsrc = (const float4*)(Wpsi1 + ((size_t)d << 12));
                float4* wdst = (float4*)ws;
#pragma unroll
                for (int r = 0; r < 4; r++) wdst[tid + (r << 8)] = wsrc[tid + (r << 8)];
            }
            __syncthreads();
#pragma unroll
            for (int hh = 0; hh < 64; hh++) {
                float4 pv = *(const float4*)&ph[hh * 68 + tr];
                float4 wv = *(const float4*)&ws[(hh << 6) + tc];
                ull w01 = pack2(wv.x, wv.y);
                ull w23 = pack2(wv.z, wv.w);
                float pa[4] = { pv.x, pv.y, pv.z, pv.w };
#pragma unroll
                for (int i = 0; i < 4; i++) {
                    ull pp = pack2(pa[i], pa[i]);
                    acc[i][0] = ffma2(pp, w01, acc[i][0]);
                    acc[i][1] = ffma2(pp, w23, acc[i][1]);
                }
            }
            __syncthreads();
        }
    }

    float* pout = part + ((size_t)half * NTOK + t0) * HIDD;
#pragma unroll
    for (int i = 0; i < 4; i++) {
        float x0, x1, x2, x3;
        unpack2(acc[i][0], x0, x1);
        unpack2(acc[i][1], x2, x3);
        *(float4*)(pout + (size_t)(tr + i) * HIDD + tc) = make_float4(x0, x1, x2, x3);
    }
}

// ---------------------------------------------------------------------------
// Fused kernels
// ---------------------------------------------------------------------------
// 384 mix-GEMM blocks + 128 KA stage-1 blocks
__global__ void __launch_bounds__(256, 2)
fused_mix_ka(const __nv_bfloat16* __restrict__ xh, const __nv_bfloat16* __restrict__ xl,
             const __nv_bfloat16* __restrict__ wdh, const __nv_bfloat16* __restrict__ wdl,
             const float* __restrict__ bcat, float* __restrict__ mix,
             const float* __restrict__ xf, const float* __restrict__ Wphi,
             const float* __restrict__ bphi, const float* __restrict__ Wpsi1,
             float* __restrict__ kapart)
{
    extern __shared__ char smem_raw[];
    const int bid = blockIdx.x;
    if (bid < 384) {
        gemm_body<128, 128, false>(xh, xl, wdh, wdl, bcat, mix,
                                   NTOK, DSUM, DDIM,
                                   (bid / 12) * 128, (bid % 12) * 128, smem_raw);
    } else {
        ka_part_body(xf, Wphi, bphi, Wpsi1, kapart, bid - 384, smem_raw);
    }
}

// 384 resid-GEMM blocks + 64 h-GEMM blocks
__global__ void __launch_bounds__(256, 2)
fused_resid_h(const __nv_bfloat16* __restrict__ cth, const __nv_bfloat16* __restrict__ ctl,
              const __nv_bfloat16* __restrict__ wrh, const __nv_bfloat16* __restrict__ wrl,
              const float* __restrict__ bres, float* __restrict__ resid,
              const __nv_bfloat16* __restrict__ w1h, const __nv_bfloat16* __restrict__ w1l,
              const float* __restrict__ b1, float* __restrict__ hbuf)
{
    extern __shared__ char smem_raw[];
    const int bid = blockIdx.x;
    if (bid < 384) {
        gemm_body<128, 128, false>(cth, ctl, wrh, wrl, bres, resid,
                                   NTOK, DSUM, DSUM,
                                   (bid / 12) * 128, (bid % 12) * 128, smem_raw);
    } else {
        gemm_body<64, 64, true>(cth, ctl, w1h, w1l, b1, hbuf,
                                NTOK, HIDD, DSUM,
                                (bid - 384) * 64, 0, smem_raw);
    }
}

// ---------------------------------------------------------------------------
// am = mean over tokens of adapt
// ---------------------------------------------------------------------------
__global__ void colsum_part_kernel(const float* __restrict__ adapt, float* __restrict__ part)
{
    const int j = threadIdx.x;
    const int b = blockIdx.x;
    float s = 0.f;
#pragma unroll 8
    for (int r = 0; r < 128; r++) s += adapt[(size_t)(b * 128 + r) * ADIM + j];
    part[b * ADIM + j] = s;
}
__global__ void colsum_fin_kernel(const float* __restrict__ part, float* __restrict__ am)
{
    const int j = threadIdx.x;
    float s = 0.f;
#pragma unroll
    for (int b = 0; b < 32; b++) s += part[b * ADIM + j];
    am[j] = s * (1.0f / (float)NTOK);
}

// ---------------------------------------------------------------------------
// Dynamic weights
// ---------------------------------------------------------------------------
__global__ void dynw_kernel(const float* __restrict__ Wt,  const float* __restrict__ Wt_a, const float* __restrict__ bt_a,
                            const float* __restrict__ Wc,  const float* __restrict__ Wc_a, const float* __restrict__ bc_a,
                            const float* __restrict__ We,  const float* __restrict__ We_a, const float* __restrict__ be_a,
                            const float* __restrict__ am,  float* __restrict__ Wdyn)
{
    __shared__ float ams[ADIM];
    const int tid = threadIdx.x;
    if (tid < ADIM) ams[tid] = am[tid];
    __syncthreads();

    const int idx4 = blockIdx.x * 256 + tid;
    const int k    = idx4 / 384;
    const int c4   = (idx4 - k * 384) * 4;

    const float *Wa, *ba, *base;
    int m;
    if (c4 < 256)      { m = k * 256 + c4;          base = Wt; Wa = Wt_a; ba = bt_a; }
    else if (c4 < 512) { m = k * 256 + (c4 - 256);  base = Wc; Wa = Wc_a; ba = bc_a; }
    else {
        int e  = (c4 - 512) >> 8;
        int jj = (c4 - 512) & 255;
        m = k * 256 + jj;
        base = We + e * 65536;
        Wa   = We_a + (size_t)e * 8388608u;
        ba   = be_a + e * 65536;
    }
    float4 acc = *(const float4*)(base + m);
    float4 b4  = *(const float4*)(ba + m);
    acc.x += b4.x; acc.y += b4.y; acc.z += b4.z; acc.w += b4.w;
#pragma unroll 4
    for (int a = 0; a < ADIM; a++) {
        float s = ams[a];
        float4 w = *(const float4*)(Wa + (size_t)a * 65536 + m);
        acc.x = fmaf(s, w.x, acc.x);
        acc.y = fmaf(s, w.y, acc.y);
        acc.z = fmaf(s, w.z, acc.z);
        acc.w = fmaf(s, w.w, acc.w);
    }
    *(float4*)(Wdyn + (size_t)idx4 * 4) = acc;
}

__global__ void bcat_kernel(const float* __restrict__ bt, const float* __restrict__ bc,
                            const float* __restrict__ be, float* __restrict__ bcat)
{
    int c = blockIdx.x * 256 + threadIdx.x;
    if (c >= DSUM) return;
    if (c < 256)      bcat[c] = bt[c];
    else if (c < 512) bcat[c] = bc[c - 256];
    else              bcat[c] = be[c - 512];
}

// ---------------------------------------------------------------------------
// gate = softmax(adapt @ Wg + bg)
// ---------------------------------------------------------------------------
__global__ void gate_kernel(const float* __restrict__ adapt, const float* __restrict__ Wg,
                            const float* __restrict__ bg, float* __restrict__ gate)
{
    __shared__ float wgs[ADIM * 5];
    __shared__ float bgs[5];
    const int tid = threadIdx.x;
    for (int i = tid; i < ADIM * 5; i += 256) wgs[i] = Wg[i];
    if (tid < 5) bgs[tid] = bg[tid];
    __syncthreads();

    const int warp = tid >> 5, lane = tid & 31;
    const int n = (blockIdx.x << 3) + warp;

    float4 a4 = *(const float4*)(adapt + (size_t)n * ADIM + lane * 4);
    float av[4] = { a4.x, a4.y, a4.z, a4.w };
    float l[5] = { 0, 0, 0, 0, 0 };
#pragma unroll
    for (int q = 0; q < 4; q++) {
        int a = lane * 4 + q;
#pragma unroll
        for (int j = 0; j < 5; j++) l[j] = fmaf(av[q], wgs[a * 5 + j], l[j]);
    }
#pragma unroll
    for (int off = 16; off; off >>= 1)
#pragma unroll
        for (int j = 0; j < 5; j++) l[j] += __shfl_xor_sync(0xffffffffu, l[j], off);

    if (lane == 0) {
#pragma unroll
        for (int j = 0; j < 5; j++) l[j] += bgs[j];
        float mx = fmaxf(fmaxf(fmaxf(l[0], l[1]), fmaxf(l[2], l[3])), l[4]);
        float s = 0.f;
#pragma unroll
        for (int j = 0; j < 5; j++) { l[j] = __expf(l[j] - mx); s += l[j]; }
        float inv = 1.0f / s;
#pragma unroll
        for (int j = 0; j < 5; j++) gate[n * 5 + j] = l[j] * inv;
    }
}

// tpsi = gelu(part0 + part1 + bpsi1) -> bf16 hi/lo
__global__ void ka_finish_kernel(const float* __restrict__ part,
                                 const float* __restrict__ bpsi1,
                                 __nv_bfloat16* __restrict__ tph,
                                 __nv_bfloat16* __restrict__ tpl)
{
    const int idx = blockIdx.x * 256 + threadIdx.x;
    const int jq = idx & 15;
    float4 a = ((const float4*)part)[idx];
    float4 b = ((const float4*)part)[65536 + idx];
    float4 bb = ((const float4*)bpsi1)[jq];
    float o[4];
    o[0] = gelu_f(a.x + b.x + bb.x);
    o[1] = gelu_f(a.y + b.y + bb.y);
    o[2] = gelu_f(a.z + b.z + bb.z);
    o[3] = gelu_f(a.w + b.w + bb.w);
#pragma unroll
    for (int q = 0; q < 4; q++) split_store(o[q], tph + idx * 4 + q, tpl + idx * 4 + q);
}

// ---------------------------------------------------------------------------
// concat[n] = [tok, chan, moe, lf]; also emits bf16 hi/lo
// ---------------------------------------------------------------------------
__global__ void concat_kernel(const float* __restrict__ mix, const float* __restrict__ gate,
                              const float* __restrict__ ka, const float* __restrict__ lf,
                              float* __restrict__ concat,
                              __nv_bfloat16* __restrict__ cth, __nv_bfloat16* __restrict__ ctl)
{
    const int n = blockIdx.x;
    const int t = threadIdx.x;
    __shared__ float g[5];
    if (t < 5) g[t] = gate[n * 5 + t];
    __syncthreads();

    const float4* mx = (const float4*)(mix + (size_t)n * DSUM);
    float4 out;
    if (t < 128) {
        out = mx[t];
    } else if (t < 192) {
        int dq = t - 128;
        float4 e0 = mx[128 + dq], e1 = mx[192 + dq], e2 = mx[256 + dq], e3 = mx[320 + dq];
        float4 k4 = ((const float4*)(ka + (size_t)n * DDIM))[dq];
        out.x = g[0]*e0.x + g[1]*e1.x + g[2]*e2.x + g[3]*e3.x + g[4]*k4.x;
        out.y = g[0]*e0.y + g[1]*e1.y + g[2]*e2.y + g[3]*e3.y + g[4]*k4.y;
        out.z = g[0]*e0.z + g[1]*e1.z + g[2]*e2.z + g[3]*e3.z + g[4]*k4.z;
        out.w = g[0]*e0.w + g[1]*e1.w + g[2]*e2.w + g[3]*e3.w + g[4]*k4.w;
    } else {
        out = ((const float4*)(lf + (size_t)n * DLF))[t - 192];
    }
    ((float4*)(concat + (size_t)n * DSUM))[t] = out;
    const size_t e = (size_t)n * DSUM + t * 4;
    split_store(out.x, cth + e + 0, ctl + e + 0);
    split_store(out.y, cth + e + 1, ctl + e + 1);
    split_store(out.z, cth + e + 2, ctl + e + 2);
    split_store(out.w, cth + e + 3, ctl + e + 3);
}

// ---------------------------------------------------------------------------
// combine: cw = softmax(h @ W2 + b2); comb = cw[sec]*concat + resid (bf16 out)
// ---------------------------------------------------------------------------
__global__ void combine_kernel(const float* __restrict__ h, const float* __restrict__ W2,
                               const float* __restrict__ b2, const float* __restrict__ concat,
                               const float* __restrict__ resid,
                               __nv_bfloat16* __restrict__ cbh, __nv_bfloat16* __restrict__ cbl)
{
    __shared__ float w2s[256];
    const int tid = threadIdx.x;
    w2s[tid] = W2[tid];
    __syncthreads();

    const int warp = tid >> 5, lane = tid & 31;
    const int n = (blockIdx.x << 3) + warp;

    float2 hv = *(const float2*)(h + (size_t)n * HIDD + lane * 2);
    const int a0 = lane * 2, a1 = lane * 2 + 1;
    float l0 = hv.x * w2s[a0*4+0] + hv.y * w2s[a1*4+0];
    float l1 = hv.x * w2s[a0*4+1] + hv.y * w2s[a1*4+1];
    float l2 = hv.x * w2s[a0*4+2] + hv.y * w2s[a1*4+2];
    float l3 = hv.x * w2s[a0*4+3] + hv.y * w2s[a1*4+3];
#pragma unroll
    for (int off = 16; off; off >>= 1) {
        l0 += __shfl_xor_sync(0xffffffffu, l0, off);
        l1 += __shfl_xor_sync(0xffffffffu, l1, off);
        l2 += __shfl_xor_sync(0xffffffffu, l2, off);
        l3 += __shfl_xor_sync(0xffffffffu, l3, off);
    }
    l0 += __ldg(b2 + 0); l1 += __ldg(b2 + 1); l2 += __ldg(b2 + 2); l3 += __ldg(b2 + 3);
    float mx = fmaxf(fmaxf(l0, l1), fmaxf(l2, l3));
    float e0 = __expf(l0 - mx), e1 = __expf(l1 - mx), e2 = __expf(l2 - mx), e3 = __expf(l3 - mx);
    float inv = 1.0f / (e0 + e1 + e2 + e3);
    float cw0 = e0 * inv, cw1 = e1 * inv, cw2 = e2 * inv, cw3 = e3 * inv;

    const float4* cc = (const float4*)(concat + (size_t)n * DSUM);
    const float4* rr = (const float4*)(resid  + (size_t)n * DSUM);
#pragma unroll
    for (int q = 0; q < 12; q++) {
        int c4 = lane + (q << 5);
        float w = (c4 < 64) ? cw0 : (c4 < 128) ? cw1 : (c4 < 192) ? cw2 : cw3;
        float4 cv = cc[c4], rv = rr[c4];
        float v0 = fmaf(w, cv.x, rv.x), v1 = fmaf(w, cv.y, rv.y);
        float v2 = fmaf(w, cv.z, rv.z), v3 = fmaf(w, cv.w, rv.w);
        const size_t e = (size_t)n * DSUM + c4 * 4;
        split_store(v0, cbh + e + 0, cbl + e + 0);
        split_store(v1, cbh + e + 1, cbl + e + 1);
        split_store(v2, cbh + e + 2, cbl + e + 2);
        split_store(v3, cbh + e + 3, cbl + e + 3);
    }
}

// ---------------------------------------------------------------------------
// Host launcher
// ---------------------------------------------------------------------------
extern "C" void kernel_launch(void* const* d_in, const int* in_sizes, int n_in,
                              void* d_out, int out_size)
{
    (void)in_sizes; (void)n_in; (void)out_size;

    const float* x      = (const float*)d_in[0];
    const float* lf     = (const float*)d_in[1];
    const float* W_feat = (const float*)d_in[2];
    const float* b_feat = (const float*)d_in[3];
    const float* Wt     = (const float*)d_in[4];
    const float* bt     = (const float*)d_in[5];
    const float* Wt_a   = (const float*)d_in[6];
    const float* bt_a   = (const float*)d_in[7];
    const float* Wc     = (const float*)d_in[8];
    const float* bc     = (const float*)d_in[9];
    const float* Wc_a   = (const float*)d_in[10];
    const float* bc_a   = (const float*)d_in[11];
    const float* We     = (const float*)d_in[12];
    const float* be     = (const float*)d_in[13];
    const float* We_a   = (const float*)d_in[14];
    const float* be_a   = (const float*)d_in[15];
    const float* Wg     = (const float*)d_in[16];
    const float* bg     = (const float*)d_in[17];
    const float* Wphi   = (const float*)d_in[18];
    const float* bphi   = (const float*)d_in[19];
    const float* Wpsi1  = (const float*)d_in[20];
    const float* bpsi1  = (const float*)d_in[21];
    const float* Wpsi2  = (const float*)d_in[22];
    const float* bpsi2  = (const float*)d_in[23];
    const float* Wres   = (const float*)d_in[24];
    const float* bres   = (const float*)d_in[25];
    const float* W1     = (const float*)d_in[26];
    const float* b1     = (const float*)d_in[27];
    const float* W2     = (const float*)d_in[28];
    const float* b2     = (const float*)d_in[29];
    const float* Wo     = (const float*)d_in[30];
    const float* bo     = (const float*)d_in[31];
    float* out = (float*)d_out;

    float* s = nullptr;
    cudaGetSymbolAddress((void**)&s, g_scratch);
    float* adapt  = s + OFF_ADAPT;
    float* am     = s + OFF_AM;
    float* part   = s + OFF_PART;
    float* gate   = s + OFF_GATE;
    float* Wdyn   = s + OFF_WDYN;
    float* bcat   = s + OFF_BCAT;
    float* mix    = s + OFF_MIX;
    float* ka     = s + OFF_KA;
    float* concat = s + OFF_CONCAT;
    float* resid  = s + OFF_RESID;
    float* hbuf   = s + OFF_H;
    float* kapart = s + OFF_KAPART;

    __nv_bfloat16* bb = (__nv_bfloat16*)(s + OFF_BF16);
    __nv_bfloat16 *xh = bb + BF_XH,   *xl = bb + BF_XL;
    __nv_bfloat16 *wfh = bb + BF_WFH, *wfl = bb + BF_WFL;
    __nv_bfloat16 *wdh = bb + BF_WDH, *wdl = bb + BF_WDL;
    __nv_bfloat16 *tph = bb + BF_TPH, *tpl = bb + BF_TPL;
    __nv_bfloat16 *wph = bb + BF_WPH, *wpl = bb + BF_WPL;
    __nv_bfloat16 *cth = bb + BF_CATH, *ctl = bb + BF_CATL;
    __nv_bfloat16 *wrh = bb + BF_WRH, *wrl = bb + BF_WRL;
    __nv_bfloat16 *w1h = bb + BF_W1H, *w1l = bb + BF_W1L;
    __nv_bfloat16 *cbh = bb + BF_CBH, *cbl = bb + BF_CBL;
    __nv_bfloat16 *woh = bb + BF_WOH, *wol = bb + BF_WOL;

    const int SM_BIG  = 2 * (16384 + 16384) + 1024;  // 66560 (128x128 / fused)
    const int SM_6464 = 2 * (8192  + 8192)  + 1024;  // 33792
    cudaFuncSetAttribute(gemm_hmma<64, 64, false>, cudaFuncAttributeMaxDynamicSharedMemorySize, SM_6464);
    cudaFuncSetAttribute(fused_mix_ka,  cudaFuncAttributeMaxDynamicSharedMemorySize, SM_BIG);
    cudaFuncSetAttribute(fused_resid_h, cudaFuncAttributeMaxDynamicSharedMemorySize, SM_BIG);

    // 1. x split
    split_kernel<<<1024, 256>>>(x, xh, xl);
    // 2. W_feat transpose-split
    tsplit_kernel<<<dim3(ADIM/32, DDIM/32), dim3(32,8)>>>(W_feat, wfh, wfl, DDIM, ADIM);
    // 3. Wpsi2 transpose-split
    tsplit_kernel<<<dim3(DDIM/32, HIDD/32), dim3(32,8)>>>(Wpsi2, wph, wpl, HIDD, DDIM);
    // 4. adapt GEMM  [4096,128]   <-- ncu window
    gemm_hmma<64, 64, false><<<dim3(2, 64), 256, SM_6464>>>(xh, xl, wfh, wfl, b_feat, adapt, NTOK, ADIM, DDIM);
    // 5-7. remaining weight transposes
    tsplit_kernel<<<dim3(DSUM/32, DSUM/32), dim3(32,8)>>>(Wres, wrh, wrl, DSUM, DSUM);
    tsplit_kernel<<<dim3(HIDD/32, DSUM/32), dim3(32,8)>>>(W1, w1h, w1l, DSUM, HIDD);
    tsplit_kernel<<<dim3(DDIM/32, DSUM/32), dim3(32,8)>>>(Wo, woh, wol, DSUM, DDIM);
    // 8-9. am
    colsum_part_kernel<<<32, 128>>>(adapt, part);
    colsum_fin_kernel<<<1, 128>>>(part, am);
    // 10-12. dynamic weights + transpose-split + bias concat
    dynw_kernel<<<384, 256>>>(Wt, Wt_a, bt_a, Wc, Wc_a, bc_a, We, We_a, be_a, am, Wdyn);
    tsplit_kernel<<<dim3(DSUM/32, DDIM/32), dim3(32,8)>>>(Wdyn, wdh, wdl, DDIM, DSUM);
    bcat_kernel<<<6, 256>>>(bt, bc, be, bcat);
    // 13. gate softmax
    gate_kernel<<<NTOK / 8, 256>>>(adapt, Wg, bg, gate);
    // 14. FUSED: mix GEMM (384 blocks) + KA stage 1 (128 blocks)
    fused_mix_ka<<<512, 256, SM_BIG>>>(xh, xl, wdh, wdl, bcat, mix,
                                       x, Wphi, bphi, Wpsi1, kapart);
    // 15. KA finish (bf16 hi/lo)
    ka_finish_kernel<<<256, 256>>>(kapart, bpsi1, tph, tpl);
    // 16. ka = tpsi @ Wpsi2 + bpsi2  [4096,256]
    gemm_hmma<64, 64, false><<<dim3(4, 64), 256, SM_6464>>>(tph, tpl, wph, wpl, bpsi2, ka, NTOK, DDIM, HIDD);
    // 17. concat (+ bf16 hi/lo)
    concat_kernel<<<NTOK, 384>>>(mix, gate, ka, lf, concat, cth, ctl);
    // 18. FUSED: resid GEMM (384 blocks) + h GEMM (64 blocks)
    fused_resid_h<<<448, 256, SM_BIG>>>(cth, ctl, wrh, wrl, bres, resid,
                                        w1h, w1l, b1, hbuf);
    // 19. combine (bf16 hi/lo)
    combine_kernel<<<NTOK / 8, 256>>>(hbuf, W2, b2, concat, resid, cbh, cbl);
    // 20. out = comb @ Wo + bo  [4096,256]
    gemm_hmma<64, 64, false><<<dim3(4, 64), 256, SM_6464>>>(cbh, cbl, woh, wol, bo, out, NTOK, DDIM, DSUM);
}

// round 10
// speedup vs baseline: 2.2964x; 1.0050x over previous
#include <cuda_runtime.h>
#include <cuda_bf16.h>
#include <math.h>
#include <stdint.h>

// ---------------------------------------------------------------------------
// Problem constants
// ---------------------------------------------------------------------------
#define NTOK   4096      // B*S
#define DDIM   256
#define DLF    768
#define ADIM   128
#define DSUM   1536
#define HIDD   64

typedef unsigned long long ull;

// ---------------------------------------------------------------------------
// helpers
// ---------------------------------------------------------------------------
__device__ __forceinline__ ull pack2(float lo, float hi) {
    ull r; asm("mov.b64 %0, {%1,%2};" : "=l"(r) : "f"(lo), "f"(hi)); return r;
}
__device__ __forceinline__ void unpack2(ull p, float& lo, float& hi) {
    asm("mov.b64 {%0,%1}, %2;" : "=f"(lo), "=f"(hi) : "l"(p));
}
__device__ __forceinline__ ull ffma2(ull a, ull b, ull c) {
    ull d; asm("fma.rn.f32x2 %0, %1, %2, %3;" : "=l"(d) : "l"(a), "l"(b), "l"(c)); return d;
}
__device__ __forceinline__ float gelu_f(float v) {
    return 0.5f * v * (1.0f + erff(v * 0.70710678118654752440f));
}
__device__ __forceinline__ uint32_t smem_to_u32(const void* p) {
    uint32_t a;
    asm("{ .reg .u64 t; cvta.to.shared.u64 t, %1; cvt.u32.u64 %0, t; }" : "=r"(a) : "l"(p));
    return a;
}
#define SMEM_SWIZZLE_128B(o) ((o) ^ (((o) >> 3) & 0x70))

__device__ __forceinline__ void cp_async16(uint32_t saddr, const void* gptr) {
    asm volatile("cp.async.cg.shared.global [%0], [%1], 16;" :: "r"(saddr), "l"(gptr));
}
#define CP_COMMIT() asm volatile("cp.async.commit_group;" ::: "memory")
#define CP_WAIT1()  asm volatile("cp.async.wait_group 1;"  ::: "memory")
#define CP_WAIT0()  asm volatile("cp.async.wait_group 0;"  ::: "memory")

__device__ __forceinline__ void ldsm_x4(uint32_t addr, uint32_t& r0, uint32_t& r1,
                                        uint32_t& r2, uint32_t& r3) {
    asm volatile("ldmatrix.sync.aligned.m8n8.x4.shared.b16 {%0,%1,%2,%3}, [%4];"
                 : "=r"(r0), "=r"(r1), "=r"(r2), "=r"(r3) : "r"(addr));
}
__device__ __forceinline__ void ldsm_x2(uint32_t addr, uint32_t& r0, uint32_t& r1) {
    asm volatile("ldmatrix.sync.aligned.m8n8.x2.shared.b16 {%0,%1}, [%2];"
                 : "=r"(r0), "=r"(r1) : "r"(addr));
}
__device__ __forceinline__ void mma16816(float& c0, float& c1, float& c2, float& c3,
                                         uint32_t a0, uint32_t a1, uint32_t a2, uint32_t a3,
                                         uint32_t b0, uint32_t b1) {
    asm volatile("mma.sync.aligned.m16n8k16.row.col.f32.bf16.bf16.f32 "
                 "{%0,%1,%2,%3}, {%4,%5,%6,%7}, {%8,%9}, {%0,%1,%2,%3};"
                 : "+f"(c0), "+f"(c1), "+f"(c2), "+f"(c3)
                 : "r"(a0), "r"(a1), "r"(a2), "r"(a3), "r"(b0), "r"(b1));
}

__device__ __forceinline__ void split_store(float v, __nv_bfloat16* hi, __nv_bfloat16* lo) {
    __nv_bfloat16 h = __float2bfloat16(v);
    *hi = h;
    *lo = __float2bfloat16(v - __bfloat162float(h));
}

// ---------------------------------------------------------------------------
// Scratch (fp32 region then bf16 region)
// ---------------------------------------------------------------------------
#define OFF_ADAPT   0u
#define OFF_AM      524288u
#define OFF_PART    524416u
#define OFF_GATE    528512u
#define OFF_WDYN    548992u
#define OFF_BCAT    942208u
#define OFF_MIX     943744u
#define OFF_KA      7497344u
#define OFF_CONCAT  8545920u
#define OFF_RESID   14837376u
#define OFF_H       21128832u
#define OFF_KAPART  27682432u
#define OFF_BF16    28206720u          // start of bf16 region (float units)

// bf16 offsets (in bf16 elements from bf16 base)
#define BF_XH   0u
#define BF_XL   1048576u
#define BF_WFH  2097152u
#define BF_WFL  2129920u
#define BF_WDH  2162688u
#define BF_WDL  2555904u
#define BF_TPH  2949120u
#define BF_TPL  3211264u
#define BF_WPH  3473408u
#define BF_WPL  3489792u
#define BF_CATH 3506176u
#define BF_CATL 9797632u
#define BF_WRH  16089088u
#define BF_WRL  18448384u
#define BF_W1H  20807680u
#define BF_W1L  20905984u
#define BF_CBH  21004288u
#define BF_CBL  27295744u
#define BF_WOH  33587200u
#define BF_WOL  33980416u

#define SCRATCH_FLOATS (28206720u + 17186816u)
__device__ float g_scratch[SCRATCH_FLOATS];

// ---------------------------------------------------------------------------
// split: fp32 [n] -> bf16 hi, lo
// ---------------------------------------------------------------------------
__global__ void split_kernel(const float* __restrict__ src,
                             __nv_bfloat16* __restrict__ hi,
                             __nv_bfloat16* __restrict__ lo)
{
    const int i = blockIdx.x * 256 + threadIdx.x;
    float4 v = ((const float4*)src)[i];
    __nv_bfloat16 hx = __float2bfloat16(v.x), hy = __float2bfloat16(v.y);
    __nv_bfloat16 hz = __float2bfloat16(v.z), hw = __float2bfloat16(v.w);
    __nv_bfloat162* hp = (__nv_bfloat162*)hi;
    __nv_bfloat162* lp = (__nv_bfloat162*)lo;
    hp[2*i]   = __nv_bfloat162(hx, hy);
    hp[2*i+1] = __nv_bfloat162(hz, hw);
    lp[2*i]   = __nv_bfloat162(__float2bfloat16(v.x - __bfloat162float(hx)),
                               __float2bfloat16(v.y - __bfloat162float(hy)));
    lp[2*i+1] = __nv_bfloat162(__float2bfloat16(v.z - __bfloat162float(hz)),
                               __float2bfloat16(v.w - __bfloat162float(hw)));
}

// ---------------------------------------------------------------------------
// transpose+split body (flat 256 threads): W [K,N] fp32 -> th, tl [N,K] bf16
// ---------------------------------------------------------------------------
__device__ __forceinline__ void
tsplit_body(const float* __restrict__ W, __nv_bfloat16* __restrict__ th,
            __nv_bfloat16* __restrict__ tl, int K, int N, int bid)
{
    __shared__ float t[32][33];
    const int nb = (bid % (N / 32)) * 32;
    const int kb = (bid / (N / 32)) * 32;
    const int tx = threadIdx.x & 31, ty = threadIdx.x >> 5;
#pragma unroll
    for (int j = 0; j < 32; j += 8)
        t[ty + j][tx] = W[(size_t)(kb + ty + j) * N + nb + tx];
    __syncthreads();
#pragma unroll
    for (int j = 0; j < 32; j += 8) {
        float v = t[tx][ty + j];
        __nv_bfloat16 h = __float2bfloat16(v);
        th[(size_t)(nb + ty + j) * K + kb + tx] = h;
        tl[(size_t)(nb + ty + j) * K + kb + tx] = __float2bfloat16(v - __bfloat162float(h));
    }
}

__global__ void tsplit_kernel(const float* __restrict__ W,
                              __nv_bfloat16* __restrict__ th,
                              __nv_bfloat16* __restrict__ tl,
                              int K, int N)
{
    tsplit_body(W, th, tl, K, N, blockIdx.x);
}

// prep2: Wfeat tsplit (32 blocks) + Wpsi2 tsplit (16) + bcat (6)
__global__ void prep2_kernel(const float* __restrict__ W_feat,
                             __nv_bfloat16* __restrict__ wfh, __nv_bfloat16* __restrict__ wfl,
                             const float* __restrict__ Wpsi2,
                             __nv_bfloat16* __restrict__ wph, __nv_bfloat16* __restrict__ wpl,
                             const float* __restrict__ bt, const float* __restrict__ bc,
                             const float* __restrict__ be, float* __restrict__ bcat)
{
    const int bid = blockIdx.x;
    if (bid < 32) {
        tsplit_body(W_feat, wfh, wfl, DDIM, ADIM, bid);
    } else if (bid < 48) {
        tsplit_body(Wpsi2, wph, wpl, HIDD, DDIM, bid - 32);
    } else {
        int c = (bid - 48) * 256 + threadIdx.x;
        if (c < DSUM) {
            if (c < 256)      bcat[c] = bt[c];
            else if (c < 512) bcat[c] = bc[c - 256];
            else              bcat[c] = be[c - 512];
        }
    }
}

// prep3: Wres (2304) + W1 (96) + Wo (384) tsplits
__global__ void prep3_kernel(const float* __restrict__ Wres,
                             __nv_bfloat16* __restrict__ wrh, __nv_bfloat16* __restrict__ wrl,
                             const float* __restrict__ W1,
                             __nv_bfloat16* __restrict__ w1h, __nv_bfloat16* __restrict__ w1l,
                             const float* __restrict__ Wo,
                             __nv_bfloat16* __restrict__ woh, __nv_bfloat16* __restrict__ wol)
{
    const int bid = blockIdx.x;
    if (bid < 2304)      tsplit_body(Wres, wrh, wrl, DSUM, DSUM, bid);
    else if (bid < 2400) tsplit_body(W1, w1h, w1l, DSUM, HIDD, bid - 2304);
    else                 tsplit_body(Wo, woh, wol, DSUM, DDIM, bid - 2400);
}

// ---------------------------------------------------------------------------
// GEMM body: HMMA bf16 3-split, 3-stage cp.async ring, single sync per chunk.
// ---------------------------------------------------------------------------
template <int BM, int BN, bool GELU>
__device__ __forceinline__ void
gemm_body(const __nv_bfloat16* __restrict__ Ahi, const __nv_bfloat16* __restrict__ Alo,
          const __nv_bfloat16* __restrict__ BThi, const __nv_bfloat16* __restrict__ BTlo,
          const float* __restrict__ bias, float* __restrict__ C,
          int M, int N, int K, int bm, int bn, char* smem_raw)
{
    constexpr int ASZ = BM * 128;
    constexpr int BSZ = BN * 128;
    constexpr int STG = ASZ + BSZ;
    constexpr int WM  = BM / 64;
    constexpr int WN  = 8 / WM;
    constexpr int WTN = BN / WN;
    constexpr int NF  = WTN / 8;

    const uint32_t tile0 = (smem_to_u32(smem_raw) + 1023) & ~1023u;

    const int tid = threadIdx.x;
    const int wid = tid >> 5, lane = tid & 31;
    const int wm = (WM == 1) ? 0 : (wid & 1);
    const int wn = (WM == 1) ? wid : (wid >> 1);
    const int KC = K >> 6;
    const int NC = 3 * KC;

    float acc[4][NF][4];
#pragma unroll
    for (int mf = 0; mf < 4; mf++)
#pragma unroll
        for (int nf = 0; nf < NF; nf++)
#pragma unroll
            for (int i = 0; i < 4; i++) acc[mf][nf][i] = 0.f;

    auto stage = [&](int c) {
        const int buf = c % 3;
        const int blk = c / KC;
        const int k0  = (c - blk * KC) << 6;
        const __nv_bfloat16* Asrc = ((blk < 2) ? Ahi : Alo) + (size_t)bm * K + k0;
        const __nv_bfloat16* Bsrc = ((blk == 1) ? BTlo : BThi) + (size_t)bn * K + k0;
        const uint32_t ab = tile0 + buf * STG;
        const uint32_t bb = ab + ASZ;
#pragma unroll
        for (int i = 0; i < BM / 32; i++) {
            int u = i * 256 + tid;
            int row = u >> 3, seg = u & 7;
            uint32_t off = row * 128 + seg * 16;
            cp_async16(ab + SMEM_SWIZZLE_128B(off), Asrc + (size_t)row * K + seg * 8);
        }
#pragma unroll
        for (int i = 0; i < BN / 32; i++) {
            int u = i * 256 + tid;
            int row = u >> 3, seg = u & 7;
            uint32_t off = row * 128 + seg * 16;
            cp_async16(bb + SMEM_SWIZZLE_128B(off), Bsrc + (size_t)row * K + seg * 8);
        }
    };

    auto compute = [&](int buf) {
        const uint32_t ab = tile0 + buf * STG;
        const uint32_t bb = ab + ASZ;
#pragma unroll
        for (int k16 = 0; k16 < 4; k16++) {
            uint32_t ar[4][4];
#pragma unroll
            for (int mf = 0; mf < 4; mf++) {
                int row = wm * 64 + mf * 16 + (lane & 15);
                uint32_t off = row * 128 + k16 * 32 + ((lane >> 4) << 4);
                ldsm_x4(ab + SMEM_SWIZZLE_128B(off), ar[mf][0], ar[mf][1], ar[mf][2], ar[mf][3]);
            }
            uint32_t br[NF][2];
            if (NF == 1) {
                int n = wn * WTN + (lane & 7);
                uint32_t off = n * 128 + k16 * 32 + (((lane >> 3) & 1) << 4);
                ldsm_x2(bb + SMEM_SWIZZLE_128B(off), br[0][0], br[0][1]);
            } else {
#pragma unroll
                for (int nb = 0; nb < NF / 2; nb++) {
                    int grp = lane >> 3;
                    int n = wn * WTN + nb * 16 + ((grp >> 1) << 3) + (lane & 7);
                    uint32_t off = n * 128 + k16 * 32 + ((grp & 1) << 4);
                    ldsm_x4(bb + SMEM_SWIZZLE_128B(off),
                            br[2*nb][0], br[2*nb][1], br[2*nb+1][0], br[2*nb+1][1]);
                }
            }
#pragma unroll
            for (int mf = 0; mf < 4; mf++)
#pragma unroll
                for (int nf = 0; nf < NF; nf++)
                    mma16816(acc[mf][nf][0], acc[mf][nf][1], acc[mf][nf][2], acc[mf][nf][3],
                             ar[mf][0], ar[mf][1], ar[mf][2], ar[mf][3],
                             br[nf][0], br[nf][1]);
        }
    };

    // 3-stage ring, prefetch-before-compute, one sync per chunk
    stage(0); CP_COMMIT();
    if (NC > 1) { stage(1); CP_COMMIT(); }
    for (int c = 0; c < NC; c++) {
        if (c + 1 < NC) CP_WAIT1(); else CP_WAIT0();
        __syncthreads();
        if (c + 2 < NC) { stage(c + 2); CP_COMMIT(); }
        compute(c % 3);
    }

#pragma unroll
    for (int nf = 0; nf < NF; nf++) {
        int col = bn + wn * WTN + nf * 8 + ((lane & 3) << 1);
        float2 bv = *(const float2*)(bias + col);
#pragma unroll
        for (int mf = 0; mf < 4; mf++) {
            int row = bm + wm * 64 + mf * 16 + (lane >> 2);
            float x0 = acc[mf][nf][0] + bv.x;
            float x1 = acc[mf][nf][1] + bv.y;
            float x2 = acc[mf][nf][2] + bv.x;
            float x3 = acc[mf][nf][3] + bv.y;
            if (GELU) { x0 = gelu_f(x0); x1 = gelu_f(x1); x2 = gelu_f(x2); x3 = gelu_f(x3); }
            *(float2*)&C[(size_t)row * N + col]       = make_float2(x0, x1);
            *(float2*)&C[(size_t)(row + 8) * N + col] = make_float2(x2, x3);
        }
    }
}

// standalone GEMM kernel wrapper
template <int BM, int BN, bool GELU>
__global__ void __launch_bounds__(256, 2)
gemm_hmma(const __nv_bfloat16* __restrict__ Ahi, const __nv_bfloat16* __restrict__ Alo,
          const __nv_bfloat16* __restrict__ BThi, const __nv_bfloat16* __restrict__ BTlo,
          const float* __restrict__ bias, float* __restrict__ C,
          int M, int N, int K)
{
    extern __shared__ char smem_raw[];
    gemm_body<BM, BN, GELU>(Ahi, Alo, BThi, BTlo, bias, C, M, N, K,
                            blockIdx.y * BM, blockIdx.x * BN, smem_raw);
}

// ---------------------------------------------------------------------------
// KA stage-1 body (FFMA2), smem carved from dynamic buffer.
// ---------------------------------------------------------------------------
__device__ __forceinline__ void
ka_part_body(const float* __restrict__ xf, const float* __restrict__ Wphi,
             const float* __restrict__ bphi, const float* __restrict__ Wpsi1,
             float* __restrict__ part, int b, char* smem_raw)
{
    float* xs = (float*)smem_raw;          // [32][65]
    float* ph = xs + 32 * 65;              // [64][68]
    float* ws = ph + 64 * 68;              // [64*64]

    const int tid   = threadIdx.x;
    const int ttile = b >> 1;
    const int half  = b & 1;
    const int t0    = ttile << 6;
    const int dbase = half << 7;

    const int tr = (tid >> 4) << 2;
    const int tc = (tid & 15) << 2;
    const int h  = tid & 63;
    const int tg = (tid >> 6) << 4;

    const int xtok = tid >> 2;
    const int xdq  = (tid & 3) << 3;

    ull acc[4][2];
#pragma unroll
    for (int i = 0; i < 4; i++) { acc[i][0] = 0ull; acc[i][1] = 0ull; }

    for (int chunk = 0; chunk < 4; chunk++) {
        const int d0 = dbase + (chunk << 5);
        {
            const float* xp = xf + (size_t)(t0 + xtok) * 256 + d0 + xdq;
            float4 v0 = *(const float4*)(xp);
            float4 v1 = *(const float4*)(xp + 4);
            xs[(xdq + 0) * 65 + xtok] = v0.x; xs[(xdq + 1) * 65 + xtok] = v0.y;
            xs[(xdq + 2) * 65 + xtok] = v0.z; xs[(xdq + 3) * 65 + xtok] = v0.w;
            xs[(xdq + 4) * 65 + xtok] = v1.x; xs[(xdq + 5) * 65 + xtok] = v1.y;
            xs[(xdq + 6) * 65 + xtok] = v1.z; xs[(xdq + 7) * 65 + xtok] = v1.w;
        }
        __syncthreads();

        for (int dd = 0; dd < 32; dd++) {
            const int d = d0 + dd;
            float wp = __ldg(Wphi + (d << 6) + h);
            float bp = __ldg(bphi + (d << 6) + h);
#pragma unroll
            for (int t2 = 0; t2 < 16; t2++) {
                int t = tg + t2;
                ph[h * 68 + t] = gelu_f(fmaf(xs[dd * 65 + t], wp, bp));
            }
            {
                const float4* wsrc = (const float4*)(Wpsi1 + ((size_t)d << 12));
                float4* wdst = (float4*)ws;
#pragma unroll
                for (int r = 0; r < 4; r++) wdst[tid + (r << 8)] = wsrc[tid + (r << 8)];
            }
            __syncthreads();
#pragma unroll
            for (int hh = 0; hh < 64; hh++) {
                float4 pv = *(const float4*)&ph[hh * 68 + tr];
                float4 wv = *(const float4*)&ws[(hh << 6) + tc];
                ull w01 = pack2(wv.x, wv.y);
                ull w23 = pack2(wv.z, wv.w);
                float pa[4] = { pv.x, pv.y, pv.z, pv.w };
#pragma unroll
                for (int i = 0; i < 4; i++) {
                    ull pp = pack2(pa[i], pa[i]);
                    acc[i][0] = ffma2(pp, w01, acc[i][0]);
                    acc[i][1] = ffma2(pp, w23, acc[i][1]);
                }
            }
            __syncthreads();
        }
    }

    float* pout = part + ((size_t)half * NTOK + t0) * HIDD;
#pragma unroll
    for (int i = 0; i < 4; i++) {
        float x0, x1, x2, x3;
        unpack2(acc[i][0], x0, x1);
        unpack2(acc[i][1], x2, x3);
        *(float4*)(pout + (size_t)(tr + i) * HIDD + tc) = make_float4(x0, x1, x2, x3);
    }
}

// ---------------------------------------------------------------------------
// Fused kernels
// ---------------------------------------------------------------------------
__global__ void __launch_bounds__(256, 2)
fused_mix_ka(const __nv_bfloat16* __restrict__ xh, const __nv_bfloat16* __restrict__ xl,
             const __nv_bfloat16* __restrict__ wdh, const __nv_bfloat16* __restrict__ wdl,
             const float* __restrict__ bcat, float* __restrict__ mix,
             const float* __restrict__ xf, const float* __restrict__ Wphi,
             const float* __restrict__ bphi, const float* __restrict__ Wpsi1,
             float* __restrict__ kapart)
{
    extern __shared__ char smem_raw[];
    const int bid = blockIdx.x;
    if (bid < 384) {
        gemm_body<128, 128, false>(xh, xl, wdh, wdl, bcat, mix,
                                   NTOK, DSUM, DDIM,
                                   (bid / 12) * 128, (bid % 12) * 128, smem_raw);
    } else {
        ka_part_body(xf, Wphi, bphi, Wpsi1, kapart, bid - 384, smem_raw);
    }
}

__global__ void __launch_bounds__(256, 2)
fused_resid_h(const __nv_bfloat16* __restrict__ cth, const __nv_bfloat16* __restrict__ ctl,
              const __nv_bfloat16* __restrict__ wrh, const __nv_bfloat16* __restrict__ wrl,
              const float* __restrict__ bres, float* __restrict__ resid,
              const __nv_bfloat16* __restrict__ w1h, const __nv_bfloat16* __restrict__ w1l,
              const float* __restrict__ b1, float* __restrict__ hbuf)
{
    extern __shared__ char smem_raw[];
    const int bid = blockIdx.x;
    if (bid < 384) {
        gemm_body<128, 128, false>(cth, ctl, wrh, wrl, bres, resid,
                                   NTOK, DSUM, DSUM,
                                   (bid / 12) * 128, (bid % 12) * 128, smem_raw);
    } else {
        gemm_body<64, 64, true>(cth, ctl, w1h, w1l, b1, hbuf,
                                NTOK, HIDD, DSUM,
                                (bid - 384) * 64, 0, smem_raw);
    }
}

// ---------------------------------------------------------------------------
// am = mean over tokens of adapt
// ---------------------------------------------------------------------------
__global__ void colsum_part_kernel(const float* __restrict__ adapt, float* __restrict__ part)
{
    const int j = threadIdx.x;
    const int b = blockIdx.x;
    float s = 0.f;
#pragma unroll 8
    for (int r = 0; r < 128; r++) s += adapt[(size_t)(b * 128 + r) * ADIM + j];
    part[b * ADIM + j] = s;
}
__global__ void colsum_fin_kernel(const float* __restrict__ part, float* __restrict__ am)
{
    const int j = threadIdx.x;
    float s = 0.f;
#pragma unroll
    for (int b = 0; b < 32; b++) s += part[b * ADIM + j];
    am[j] = s * (1.0f / (float)NTOK);
}

// ---------------------------------------------------------------------------
// Dynamic weights
// ---------------------------------------------------------------------------
__global__ void dynw_kernel(const float* __restrict__ Wt,  const float* __restrict__ Wt_a, const float* __restrict__ bt_a,
                            const float* __restrict__ Wc,  const float* __restrict__ Wc_a, const float* __restrict__ bc_a,
                            const float* __restrict__ We,  const float* __restrict__ We_a, const float* __restrict__ be_a,
                            const float* __restrict__ am,  float* __restrict__ Wdyn)
{
    __shared__ float ams[ADIM];
    const int tid = threadIdx.x;
    if (tid < ADIM) ams[tid] = am[tid];
    __syncthreads();

    const int idx4 = blockIdx.x * 256 + tid;
    const int k    = idx4 / 384;
    const int c4   = (idx4 - k * 384) * 4;

    const float *Wa, *ba, *base;
    int m;
    if (c4 < 256)      { m = k * 256 + c4;          base = Wt; Wa = Wt_a; ba = bt_a; }
    else if (c4 < 512) { m = k * 256 + (c4 - 256);  base = Wc; Wa = Wc_a; ba = bc_a; }
    else {
        int e  = (c4 - 512) >> 8;
        int jj = (c4 - 512) & 255;
        m = k * 256 + jj;
        base = We + e * 65536;
        Wa   = We_a + (size_t)e * 8388608u;
        ba   = be_a + e * 65536;
    }
    float4 acc = *(const float4*)(base + m);
    float4 b4  = *(const float4*)(ba + m);
    acc.x += b4.x; acc.y += b4.y; acc.z += b4.z; acc.w += b4.w;
#pragma unroll 4
    for (int a = 0; a < ADIM; a++) {
        float s = ams[a];
        float4 w = *(const float4*)(Wa + (size_t)a * 65536 + m);
        acc.x = fmaf(s, w.x, acc.x);
        acc.y = fmaf(s, w.y, acc.y);
        acc.z = fmaf(s, w.z, acc.z);
        acc.w = fmaf(s, w.w, acc.w);
    }
    *(float4*)(Wdyn + (size_t)idx4 * 4) = acc;
}

// ---------------------------------------------------------------------------
// gate = softmax(adapt @ Wg + bg)
// ---------------------------------------------------------------------------
__global__ void gate_kernel(const float* __restrict__ adapt, const float* __restrict__ Wg,
                            const float* __restrict__ bg, float* __restrict__ gate)
{
    __shared__ float wgs[ADIM * 5];
    __shared__ float bgs[5];
    const int tid = threadIdx.x;
    for (int i = tid; i < ADIM * 5; i += 256) wgs[i] = Wg[i];
    if (tid < 5) bgs[tid] = bg[tid];
    __syncthreads();

    const int warp = tid >> 5, lane = tid & 31;
    const int n = (blockIdx.x << 3) + warp;

    float4 a4 = *(const float4*)(adapt + (size_t)n * ADIM + lane * 4);
    float av[4] = { a4.x, a4.y, a4.z, a4.w };
    float l[5] = { 0, 0, 0, 0, 0 };
#pragma unroll
    for (int q = 0; q < 4; q++) {
        int a = lane * 4 + q;
#pragma unroll
        for (int j = 0; j < 5; j++) l[j] = fmaf(av[q], wgs[a * 5 + j], l[j]);
    }
#pragma unroll
    for (int off = 16; off; off >>= 1)
#pragma unroll
        for (int j = 0; j < 5; j++) l[j] += __shfl_xor_sync(0xffffffffu, l[j], off);

    if (lane == 0) {
#pragma unroll
        for (int j = 0; j < 5; j++) l[j] += bgs[j];
        float mx = fmaxf(fmaxf(fmaxf(l[0], l[1]), fmaxf(l[2], l[3])), l[4]);
        float s = 0.f;
#pragma unroll
        for (int j = 0; j < 5; j++) { l[j] = __expf(l[j] - mx); s += l[j]; }
        float inv = 1.0f / s;
#pragma unroll
        for (int j = 0; j < 5; j++) gate[n * 5 + j] = l[j] * inv;
    }
}

// tpsi = gelu(part0 + part1 + bpsi1) -> bf16 hi/lo
__global__ void ka_finish_kernel(const float* __restrict__ part,
                                 const float* __restrict__ bpsi1,
                                 __nv_bfloat16* __restrict__ tph,
                                 __nv_bfloat16* __restrict__ tpl)
{
    const int idx = blockIdx.x * 256 + threadIdx.x;
    const int jq = idx & 15;
    float4 a = ((const float4*)part)[idx];
    float4 b = ((const float4*)part)[65536 + idx];
    float4 bb = ((const float4*)bpsi1)[jq];
    float o[4];
    o[0] = gelu_f(a.x + b.x + bb.x);
    o[1] = gelu_f(a.y + b.y + bb.y);
    o[2] = gelu_f(a.z + b.z + bb.z);
    o[3] = gelu_f(a.w + b.w + bb.w);
#pragma unroll
    for (int q = 0; q < 4; q++) split_store(o[q], tph + idx * 4 + q, tpl + idx * 4 + q);
}

// ---------------------------------------------------------------------------
// concat[n] = [tok, chan, moe, lf]; also emits bf16 hi/lo
// ---------------------------------------------------------------------------
__global__ void concat_kernel(const float* __restrict__ mix, const float* __restrict__ gate,
                              const float* __restrict__ ka, const float* __restrict__ lf,
                              float* __restrict__ concat,
                              __nv_bfloat16* __restrict__ cth, __nv_bfloat16* __restrict__ ctl)
{
    const int n = blockIdx.x;
    const int t = threadIdx.x;
    __shared__ float g[5];
    if (t < 5) g[t] = gate[n * 5 + t];
    __syncthreads();

    const float4* mx = (const float4*)(mix + (size_t)n * DSUM);
    float4 out;
    if (t < 128) {
        out = mx[t];
    } else if (t < 192) {
        int dq = t - 128;
        float4 e0 = mx[128 + dq], e1 = mx[192 + dq], e2 = mx[256 + dq], e3 = mx[320 + dq];
        float4 k4 = ((const float4*)(ka + (size_t)n * DDIM))[dq];
        out.x = g[0]*e0.x + g[1]*e1.x + g[2]*e2.x + g[3]*e3.x + g[4]*k4.x;
        out.y = g[0]*e0.y + g[1]*e1.y + g[2]*e2.y + g[3]*e3.y + g[4]*k4.y;
        out.z = g[0]*e0.z + g[1]*e1.z + g[2]*e2.z + g[3]*e3.z + g[4]*k4.z;
        out.w = g[0]*e0.w + g[1]*e1.w + g[2]*e2.w + g[3]*e3.w + g[4]*k4.w;
    } else {
        out = ((const float4*)(lf + (size_t)n * DLF))[t - 192];
    }
    ((float4*)(concat + (size_t)n * DSUM))[t] = out;
    const size_t e = (size_t)n * DSUM + t * 4;
    split_store(out.x, cth + e + 0, ctl + e + 0);
    split_store(out.y, cth + e + 1, ctl + e + 1);
    split_store(out.z, cth + e + 2, ctl + e + 2);
    split_store(out.w, cth + e + 3, ctl + e + 3);
}

// ---------------------------------------------------------------------------
// combine: cw = softmax(h @ W2 + b2); comb = cw[sec]*concat + resid (bf16 out)
// ---------------------------------------------------------------------------
__global__ void combine_kernel(const float* __restrict__ h, const float* __restrict__ W2,
                               const float* __restrict__ b2, const float* __restrict__ concat,
                               const float* __restrict__ resid,
                               __nv_bfloat16* __restrict__ cbh, __nv_bfloat16* __restrict__ cbl)
{
    __shared__ float w2s[256];
    const int tid = threadIdx.x;
    w2s[tid] = W2[tid];
    __syncthreads();

    const int warp = tid >> 5, lane = tid & 31;
    const int n = (blockIdx.x << 3) + warp;

    float2 hv = *(const float2*)(h + (size_t)n * HIDD + lane * 2);
    const int a0 = lane * 2, a1 = lane * 2 + 1;
    float l0 = hv.x * w2s[a0*4+0] + hv.y * w2s[a1*4+0];
    float l1 = hv.x * w2s[a0*4+1] + hv.y * w2s[a1*4+1];
    float l2 = hv.x * w2s[a0*4+2] + hv.y * w2s[a1*4+2];
    float l3 = hv.x * w2s[a0*4+3] + hv.y * w2s[a1*4+3];
#pragma unroll
    for (int off = 16; off; off >>= 1) {
        l0 += __shfl_xor_sync(0xffffffffu, l0, off);
        l1 += __shfl_xor_sync(0xffffffffu, l1, off);
        l2 += __shfl_xor_sync(0xffffffffu, l2, off);
        l3 += __shfl_xor_sync(0xffffffffu, l3, off);
    }
    l0 += __ldg(b2 + 0); l1 += __ldg(b2 + 1); l2 += __ldg(b2 + 2); l3 += __ldg(b2 + 3);
    float mx = fmaxf(fmaxf(l0, l1), fmaxf(l2, l3));
    float e0 = __expf(l0 - mx), e1 = __expf(l1 - mx), e2 = __expf(l2 - mx), e3 = __expf(l3 - mx);
    float inv = 1.0f / (e0 + e1 + e2 + e3);
    float cw0 = e0 * inv, cw1 = e1 * inv, cw2 = e2 * inv, cw3 = e3 * inv;

    const float4* cc = (const float4*)(concat + (size_t)n * DSUM);
    const float4* rr = (const float4*)(resid  + (size_t)n * DSUM);
#pragma unroll
    for (int q = 0; q < 12; q++) {
        int c4 = lane + (q << 5);
        float w = (c4 < 64) ? cw0 : (c4 < 128) ? cw1 : (c4 < 192) ? cw2 : cw3;
        float4 cv = cc[c4], rv = rr[c4];
        float v0 = fmaf(w, cv.x, rv.x), v1 = fmaf(w, cv.y, rv.y);
        float v2 = fmaf(w, cv.z, rv.z), v3 = fmaf(w, cv.w, rv.w);
        const size_t e = (size_t)n * DSUM + c4 * 4;
        split_store(v0, cbh + e + 0, cbl + e + 0);
        split_store(v1, cbh + e + 1, cbl + e + 1);
        split_store(v2, cbh + e + 2, cbl + e + 2);
        split_store(v3, cbh + e + 3, cbl + e + 3);
    }
}

// ---------------------------------------------------------------------------
// Host launcher
// ---------------------------------------------------------------------------
extern "C" void kernel_launch(void* const* d_in, const int* in_sizes, int n_in,
                              void* d_out, int out_size)
{
    (void)in_sizes; (void)n_in; (void)out_size;

    const float* x      = (const float*)d_in[0];
    const float* lf     = (const float*)d_in[1];
    const float* W_feat = (const float*)d_in[2];
    const float* b_feat = (const float*)d_in[3];
    const float* Wt     = (const float*)d_in[4];
    const float* bt     = (const float*)d_in[5];
    const float* Wt_a   = (const float*)d_in[6];
    const float* bt_a   = (const float*)d_in[7];
    const float* Wc     = (const float*)d_in[8];
    const float* bc     = (const float*)d_in[9];
    const float* Wc_a   = (const float*)d_in[10];
    const float* bc_a   = (const float*)d_in[11];
    const float* We     = (const float*)d_in[12];
    const float* be     = (const float*)d_in[13];
    const float* We_a   = (const float*)d_in[14];
    const float* be_a   = (const float*)d_in[15];
    const float* Wg     = (const float*)d_in[16];
    const float* bg     = (const float*)d_in[17];
    const float* Wphi   = (const float*)d_in[18];
    const float* bphi   = (const float*)d_in[19];
    const float* Wpsi1  = (const float*)d_in[20];
    const float* bpsi1  = (const float*)d_in[21];
    const float* Wpsi2  = (const float*)d_in[22];
    const float* bpsi2  = (const float*)d_in[23];
    const float* Wres   = (const float*)d_in[24];
    const float* bres   = (const float*)d_in[25];
    const float* W1     = (const float*)d_in[26];
    const float* b1     = (const float*)d_in[27];
    const float* W2     = (const float*)d_in[28];
    const float* b2     = (const float*)d_in[29];
    const float* Wo     = (const float*)d_in[30];
    const float* bo     = (const float*)d_in[31];
    float* out = (float*)d_out;

    float* s = nullptr;
    cudaGetSymbolAddress((void**)&s, g_scratch);
    float* adapt  = s + OFF_ADAPT;
    float* am     = s + OFF_AM;
    float* part   = s + OFF_PART;
    float* gate   = s + OFF_GATE;
    float* Wdyn   = s + OFF_WDYN;
    float* bcat   = s + OFF_BCAT;
    float* mix    = s + OFF_MIX;
    float* ka     = s + OFF_KA;
    float* concat = s + OFF_CONCAT;
    float* resid  = s + OFF_RESID;
    float* hbuf   = s + OFF_H;
    float* kapart = s + OFF_KAPART;

    __nv_bfloat16* bb = (__nv_bfloat16*)(s + OFF_BF16);
    __nv_bfloat16 *xh = bb + BF_XH,   *xl = bb + BF_XL;
    __nv_bfloat16 *wfh = bb + BF_WFH, *wfl = bb + BF_WFL;
    __nv_bfloat16 *wdh = bb + BF_WDH, *wdl = bb + BF_WDL;
    __nv_bfloat16 *tph = bb + BF_TPH, *tpl = bb + BF_TPL;
    __nv_bfloat16 *wph = bb + BF_WPH, *wpl = bb + BF_WPL;
    __nv_bfloat16 *cth = bb + BF_CATH, *ctl = bb + BF_CATL;
    __nv_bfloat16 *wrh = bb + BF_WRH, *wrl = bb + BF_WRL;
    __nv_bfloat16 *w1h = bb + BF_W1H, *w1l = bb + BF_W1L;
    __nv_bfloat16 *cbh = bb + BF_CBH, *cbl = bb + BF_CBL;
    __nv_bfloat16 *woh = bb + BF_WOH, *wol = bb + BF_WOL;

    const int SM_BIG  = 3 * (16384 + 16384) + 1024;  // 99328 (128x128 / fused)
    const int SM_6464 = 3 * (8192  + 8192)  + 1024;  // 50176
    cudaFuncSetAttribute(gemm_hmma<64, 64, false>, cudaFuncAttributeMaxDynamicSharedMemorySize, SM_6464);
    cudaFuncSetAttribute(fused_mix_ka,  cudaFuncAttributeMaxDynamicSharedMemorySize, SM_BIG);
    cudaFuncSetAttribute(fused_resid_h, cudaFuncAttributeMaxDynamicSharedMemorySize, SM_BIG);

    // 1. x split
    split_kernel<<<1024, 256>>>(x, xh, xl);
    // 2. W_feat + Wpsi2 tsplit + bcat
    prep2_kernel<<<54, 256>>>(W_feat, wfh, wfl, Wpsi2, wph, wpl, bt, bc, be, bcat);
    // 3. Wres + W1 + Wo tsplit
    prep3_kernel<<<2784, 256>>>(Wres, wrh, wrl, W1, w1h, w1l, Wo, woh, wol);
    // 4. adapt GEMM  [4096,128]   <-- ncu window (3-stage variant)
    gemm_hmma<64, 64, false><<<dim3(2, 64), 256, SM_6464>>>(xh, xl, wfh, wfl, b_feat, adapt, NTOK, ADIM, DDIM);
    // 5-6. am
    colsum_part_kernel<<<32, 128>>>(adapt, part);
    colsum_fin_kernel<<<1, 128>>>(part, am);
    // 7-8. dynamic weights + transpose-split (FIX: 384 blocks = (1536/32)*(256/32))
    dynw_kernel<<<384, 256>>>(Wt, Wt_a, bt_a, Wc, Wc_a, bc_a, We, We_a, be_a, am, Wdyn);
    tsplit_kernel<<<384, 256>>>(Wdyn, wdh, wdl, DDIM, DSUM);
    // 9. gate softmax
    gate_kernel<<<NTOK / 8, 256>>>(adapt, Wg, bg, gate);
    // 10. FUSED: mix GEMM (384) + KA stage 1 (128)
    fused_mix_ka<<<512, 256, SM_BIG>>>(xh, xl, wdh, wdl, bcat, mix,
                                       x, Wphi, bphi, Wpsi1, kapart);
    // 11. KA finish (bf16 hi/lo)
    ka_finish_kernel<<<256, 256>>>(kapart, bpsi1, tph, tpl);
    // 12. ka = tpsi @ Wpsi2 + bpsi2  [4096,256]
    gemm_hmma<64, 64, false><<<dim3(4, 64), 256, SM_6464>>>(tph, tpl, wph, wpl, bpsi2, ka, NTOK, DDIM, HIDD);
    // 13. concat (+ bf16 hi/lo)
    concat_kernel<<<NTOK, 384>>>(mix, gate, ka, lf, concat, cth, ctl);
    // 14. FUSED: resid GEMM (384) + h GEMM (64)
    fused_resid_h<<<448, 256, SM_BIG>>>(cth, ctl, wrh, wrl, bres, resid,
                                        w1h, w1l, b1, hbuf);
    // 15. combine (bf16 hi/lo)
    combine_kernel<<<NTOK / 8, 256>>>(hbuf, W2, b2, concat, resid, cbh, cbl);
    // 16. out = comb @ Wo + bo  [4096,256]
    gemm_hmma<64, 64, false><<<dim3(4, 64), 256, SM_6464>>>(cbh, cbl, woh, wol, bo, out, NTOK, DDIM, DSUM);
}

// round 11
// speedup vs baseline: 3.2816x; 1.4290x over previous
#include <cuda_runtime.h>
#include <cuda_bf16.h>
#include <math.h>
#include <stdint.h>

// ---------------------------------------------------------------------------
// Problem constants
// ---------------------------------------------------------------------------
#define NTOK   4096      // B*S
#define DDIM   256
#define DLF    768
#define ADIM   128
#define DSUM   1536
#define HIDD   64

typedef unsigned long long ull;

// ---------------------------------------------------------------------------
// helpers
// ---------------------------------------------------------------------------
__device__ __forceinline__ float gelu_f(float v) {
    return 0.5f * v * (1.0f + erff(v * 0.70710678118654752440f));
}
__device__ __forceinline__ uint32_t smem_to_u32(const void* p) {
    uint32_t a;
    asm("{ .reg .u64 t; cvta.to.shared.u64 t, %1; cvt.u32.u64 %0, t; }" : "=r"(a) : "l"(p));
    return a;
}
#define SMEM_SWIZZLE_128B(o) ((o) ^ (((o) >> 3) & 0x70))

__device__ __forceinline__ void cp_async16(uint32_t saddr, const void* gptr) {
    asm volatile("cp.async.cg.shared.global [%0], [%1], 16;" :: "r"(saddr), "l"(gptr));
}
#define CP_COMMIT() asm volatile("cp.async.commit_group;" ::: "memory")
#define CP_WAIT1()  asm volatile("cp.async.wait_group 1;"  ::: "memory")
#define CP_WAIT0()  asm volatile("cp.async.wait_group 0;"  ::: "memory")

__device__ __forceinline__ void ldsm_x4(uint32_t addr, uint32_t& r0, uint32_t& r1,
                                        uint32_t& r2, uint32_t& r3) {
    asm volatile("ldmatrix.sync.aligned.m8n8.x4.shared.b16 {%0,%1,%2,%3}, [%4];"
                 : "=r"(r0), "=r"(r1), "=r"(r2), "=r"(r3) : "r"(addr));
}
__device__ __forceinline__ void ldsm_x2(uint32_t addr, uint32_t& r0, uint32_t& r1) {
    asm volatile("ldmatrix.sync.aligned.m8n8.x2.shared.b16 {%0,%1}, [%2];"
                 : "=r"(r0), "=r"(r1) : "r"(addr));
}
__device__ __forceinline__ void mma16816(float& c0, float& c1, float& c2, float& c3,
                                         uint32_t a0, uint32_t a1, uint32_t a2, uint32_t a3,
                                         uint32_t b0, uint32_t b1) {
    asm volatile("mma.sync.aligned.m16n8k16.row.col.f32.bf16.bf16.f32 "
                 "{%0,%1,%2,%3}, {%4,%5,%6,%7}, {%8,%9}, {%0,%1,%2,%3};"
                 : "+f"(c0), "+f"(c1), "+f"(c2), "+f"(c3)
                 : "r"(a0), "r"(a1), "r"(a2), "r"(a3), "r"(b0), "r"(b1));
}

__device__ __forceinline__ void split_store(float v, __nv_bfloat16* hi, __nv_bfloat16* lo) {
    __nv_bfloat16 h = __float2bfloat16(v);
    *hi = h;
    *lo = __float2bfloat16(v - __bfloat162float(h));
}

// ---------------------------------------------------------------------------
// Scratch (fp32 region then bf16 region)
// ---------------------------------------------------------------------------
#define OFF_ADAPT   0u
#define OFF_AM      524288u
#define OFF_PART    524416u
#define OFF_GATE    528512u
#define OFF_WDYN    548992u
#define OFF_BCAT    942208u
#define OFF_MIX     943744u
#define OFF_KA      7497344u
#define OFF_CONCAT  8545920u
#define OFF_RESID   14837376u
#define OFF_H       21128832u
#define OFF_KAPART  27682432u          // 4 slices x 4096 x 64 = 1048576 floats
#define OFF_BF16    28731008u          // start of bf16 region (float units)

// bf16 offsets (in bf16 elements from bf16 base)
#define BF_XH    0u
#define BF_XL    1048576u
#define BF_WFH   2097152u
#define BF_WFL   2129920u
#define BF_WDH   2162688u
#define BF_WDL   2555904u
#define BF_TPH   2949120u
#define BF_TPL   3211264u
#define BF_WPH   3473408u
#define BF_WPL   3489792u
#define BF_CATH  3506176u
#define BF_CATL  9797632u
#define BF_WRH   16089088u
#define BF_WRL   18448384u
#define BF_W1H   20807680u
#define BF_W1L   20905984u
#define BF_CBH   21004288u
#define BF_CBL   27295744u
#define BF_WOH   33587200u
#define BF_WOL   33980416u
#define BF_WP1H  34373632u             // Wpsi1^T hi [64][16384]
#define BF_WP1L  35422208u             // Wpsi1^T lo

#define SCRATCH_FLOATS (28731008u + 18235392u)
__device__ float g_scratch[SCRATCH_FLOATS];

// ---------------------------------------------------------------------------
// split: fp32 [n] -> bf16 hi, lo
// ---------------------------------------------------------------------------
__global__ void split_kernel(const float* __restrict__ src,
                             __nv_bfloat16* __restrict__ hi,
                             __nv_bfloat16* __restrict__ lo)
{
    const int i = blockIdx.x * 256 + threadIdx.x;
    float4 v = ((const float4*)src)[i];
    __nv_bfloat16 hx = __float2bfloat16(v.x), hy = __float2bfloat16(v.y);
    __nv_bfloat16 hz = __float2bfloat16(v.z), hw = __float2bfloat16(v.w);
    __nv_bfloat162* hp = (__nv_bfloat162*)hi;
    __nv_bfloat162* lp = (__nv_bfloat162*)lo;
    hp[2*i]   = __nv_bfloat162(hx, hy);
    hp[2*i+1] = __nv_bfloat162(hz, hw);
    lp[2*i]   = __nv_bfloat162(__float2bfloat16(v.x - __bfloat162float(hx)),
                               __float2bfloat16(v.y - __bfloat162float(hy)));
    lp[2*i+1] = __nv_bfloat162(__float2bfloat16(v.z - __bfloat162float(hz)),
                               __float2bfloat16(v.w - __bfloat162float(hw)));
}

// ---------------------------------------------------------------------------
// transpose+split body (flat 256 threads): W [K,N] fp32 -> th, tl [N,K] bf16
// ---------------------------------------------------------------------------
__device__ __forceinline__ void
tsplit_body(const float* __restrict__ W, __nv_bfloat16* __restrict__ th,
            __nv_bfloat16* __restrict__ tl, int K, int N, int bid)
{
    __shared__ float t[32][33];
    const int nb = (bid % (N / 32)) * 32;
    const int kb = (bid / (N / 32)) * 32;
    const int tx = threadIdx.x & 31, ty = threadIdx.x >> 5;
#pragma unroll
    for (int j = 0; j < 32; j += 8)
        t[ty + j][tx] = W[(size_t)(kb + ty + j) * N + nb + tx];
    __syncthreads();
#pragma unroll
    for (int j = 0; j < 32; j += 8) {
        float v = t[tx][ty + j];
        __nv_bfloat16 h = __float2bfloat16(v);
        th[(size_t)(nb + ty + j) * K + kb + tx] = h;
        tl[(size_t)(nb + ty + j) * K + kb + tx] = __float2bfloat16(v - __bfloat162float(h));
    }
}

__global__ void tsplit_kernel(const float* __restrict__ W,
                              __nv_bfloat16* __restrict__ th,
                              __nv_bfloat16* __restrict__ tl,
                              int K, int N)
{
    tsplit_body(W, th, tl, K, N, blockIdx.x);
}

// prep2: Wfeat tsplit (32 blocks) + Wpsi2 tsplit (16) + bcat (6)
__global__ void prep2_kernel(const float* __restrict__ W_feat,
                             __nv_bfloat16* __restrict__ wfh, __nv_bfloat16* __restrict__ wfl,
                             const float* __restrict__ Wpsi2,
                             __nv_bfloat16* __restrict__ wph, __nv_bfloat16* __restrict__ wpl,
                             const float* __restrict__ bt, const float* __restrict__ bc,
                             const float* __restrict__ be, float* __restrict__ bcat)
{
    const int bid = blockIdx.x;
    if (bid < 32) {
        tsplit_body(W_feat, wfh, wfl, DDIM, ADIM, bid);
    } else if (bid < 48) {
        tsplit_body(Wpsi2, wph, wpl, HIDD, DDIM, bid - 32);
    } else {
        int c = (bid - 48) * 256 + threadIdx.x;
        if (c < DSUM) {
            if (c < 256)      bcat[c] = bt[c];
            else if (c < 512) bcat[c] = bc[c - 256];
            else              bcat[c] = be[c - 512];
        }
    }
}

// prep3: Wres (2304) + W1 (96) + Wo (384) + Wpsi1^T (1024) tsplits
__global__ void prep3_kernel(const float* __restrict__ Wres,
                             __nv_bfloat16* __restrict__ wrh, __nv_bfloat16* __restrict__ wrl,
                             const float* __restrict__ W1,
                             __nv_bfloat16* __restrict__ w1h, __nv_bfloat16* __restrict__ w1l,
                             const float* __restrict__ Wo,
                             __nv_bfloat16* __restrict__ woh, __nv_bfloat16* __restrict__ wol,
                             const float* __restrict__ Wpsi1,
                             __nv_bfloat16* __restrict__ wp1h, __nv_bfloat16* __restrict__ wp1l)
{
    const int bid = blockIdx.x;
    if (bid < 2304)      tsplit_body(Wres, wrh, wrl, DSUM, DSUM, bid);
    else if (bid < 2400) tsplit_body(W1, w1h, w1l, DSUM, HIDD, bid - 2304);
    else if (bid < 2784) tsplit_body(Wo, woh, wol, DSUM, DDIM, bid - 2400);
    else                 tsplit_body(Wpsi1, wp1h, wp1l, 16384, HIDD, bid - 2784);
}

// ---------------------------------------------------------------------------
// GEMM body: HMMA bf16 3-split, 3-stage cp.async ring, single sync per chunk.
// ---------------------------------------------------------------------------
template <int BM, int BN, bool GELU>
__device__ __forceinline__ void
gemm_body(const __nv_bfloat16* __restrict__ Ahi, const __nv_bfloat16* __restrict__ Alo,
          const __nv_bfloat16* __restrict__ BThi, const __nv_bfloat16* __restrict__ BTlo,
          const float* __restrict__ bias, float* __restrict__ C,
          int M, int N, int K, int bm, int bn, char* smem_raw)
{
    constexpr int ASZ = BM * 128;
    constexpr int BSZ = BN * 128;
    constexpr int STG = ASZ + BSZ;
    constexpr int WM  = BM / 64;
    constexpr int WN  = 8 / WM;
    constexpr int WTN = BN / WN;
    constexpr int NF  = WTN / 8;

    const uint32_t tile0 = (smem_to_u32(smem_raw) + 1023) & ~1023u;

    const int tid = threadIdx.x;
    const int wid = tid >> 5, lane = tid & 31;
    const int wm = (WM == 1) ? 0 : (wid & 1);
    const int wn = (WM == 1) ? wid : (wid >> 1);
    const int KC = K >> 6;
    const int NC = 3 * KC;

    float acc[4][NF][4];
#pragma unroll
    for (int mf = 0; mf < 4; mf++)
#pragma unroll
        for (int nf = 0; nf < NF; nf++)
#pragma unroll
            for (int i = 0; i < 4; i++) acc[mf][nf][i] = 0.f;

    auto stage = [&](int c) {
        const int buf = c % 3;
        const int blk = c / KC;
        const int k0  = (c - blk * KC) << 6;
        const __nv_bfloat16* Asrc = ((blk < 2) ? Ahi : Alo) + (size_t)bm * K + k0;
        const __nv_bfloat16* Bsrc = ((blk == 1) ? BTlo : BThi) + (size_t)bn * K + k0;
        const uint32_t ab = tile0 + buf * STG;
        const uint32_t bb = ab + ASZ;
#pragma unroll
        for (int i = 0; i < BM / 32; i++) {
            int u = i * 256 + tid;
            int row = u >> 3, seg = u & 7;
            uint32_t off = row * 128 + seg * 16;
            cp_async16(ab + SMEM_SWIZZLE_128B(off), Asrc + (size_t)row * K + seg * 8);
        }
#pragma unroll
        for (int i = 0; i < BN / 32; i++) {
            int u = i * 256 + tid;
            int row = u >> 3, seg = u & 7;
            uint32_t off = row * 128 + seg * 16;
            cp_async16(bb + SMEM_SWIZZLE_128B(off), Bsrc + (size_t)row * K + seg * 8);
        }
    };

    auto compute = [&](int buf) {
        const uint32_t ab = tile0 + buf * STG;
        const uint32_t bb = ab + ASZ;
#pragma unroll
        for (int k16 = 0; k16 < 4; k16++) {
            uint32_t ar[4][4];
#pragma unroll
            for (int mf = 0; mf < 4; mf++) {
                int row = wm * 64 + mf * 16 + (lane & 15);
                uint32_t off = row * 128 + k16 * 32 + ((lane >> 4) << 4);
                ldsm_x4(ab + SMEM_SWIZZLE_128B(off), ar[mf][0], ar[mf][1], ar[mf][2], ar[mf][3]);
            }
            uint32_t br[NF][2];
            if (NF == 1) {
                int n = wn * WTN + (lane & 7);
                uint32_t off = n * 128 + k16 * 32 + (((lane >> 3) & 1) << 4);
                ldsm_x2(bb + SMEM_SWIZZLE_128B(off), br[0][0], br[0][1]);
            } else {
#pragma unroll
                for (int nb = 0; nb < NF / 2; nb++) {
                    int grp = lane >> 3;
                    int n = wn * WTN + nb * 16 + ((grp >> 1) << 3) + (lane & 7);
                    uint32_t off = n * 128 + k16 * 32 + ((grp & 1) << 4);
                    ldsm_x4(bb + SMEM_SWIZZLE_128B(off),
                            br[2*nb][0], br[2*nb][1], br[2*nb+1][0], br[2*nb+1][1]);
                }
            }
#pragma unroll
            for (int mf = 0; mf < 4; mf++)
#pragma unroll
                for (int nf = 0; nf < NF; nf++)
                    mma16816(acc[mf][nf][0], acc[mf][nf][1], acc[mf][nf][2], acc[mf][nf][3],
                             ar[mf][0], ar[mf][1], ar[mf][2], ar[mf][3],
                             br[nf][0], br[nf][1]);
        }
    };

    stage(0); CP_COMMIT();
    if (NC > 1) { stage(1); CP_COMMIT(); }
    for (int c = 0; c < NC; c++) {
        if (c + 1 < NC) CP_WAIT1(); else CP_WAIT0();
        __syncthreads();
        if (c + 2 < NC) { stage(c + 2); CP_COMMIT(); }
        compute(c % 3);
    }

#pragma unroll
    for (int nf = 0; nf < NF; nf++) {
        int col = bn + wn * WTN + nf * 8 + ((lane & 3) << 1);
        float2 bv = *(const float2*)(bias + col);
#pragma unroll
        for (int mf = 0; mf < 4; mf++) {
            int row = bm + wm * 64 + mf * 16 + (lane >> 2);
            float x0 = acc[mf][nf][0] + bv.x;
            float x1 = acc[mf][nf][1] + bv.y;
            float x2 = acc[mf][nf][2] + bv.x;
            float x3 = acc[mf][nf][3] + bv.y;
            if (GELU) { x0 = gelu_f(x0); x1 = gelu_f(x1); x2 = gelu_f(x2); x3 = gelu_f(x3); }
            *(float2*)&C[(size_t)row * N + col]       = make_float2(x0, x1);
            *(float2*)&C[(size_t)(row + 8) * N + col] = make_float2(x2, x3);
        }
    }
}

// standalone GEMM kernel wrapper
template <int BM, int BN, bool GELU>
__global__ void __launch_bounds__(256, 2)
gemm_hmma(const __nv_bfloat16* __restrict__ Ahi, const __nv_bfloat16* __restrict__ Alo,
          const __nv_bfloat16* __restrict__ BThi, const __nv_bfloat16* __restrict__ BTlo,
          const float* __restrict__ bias, float* __restrict__ C,
          int M, int N, int K)
{
    extern __shared__ char smem_raw[];
    gemm_body<BM, BN, GELU>(Ahi, Alo, BThi, BTlo, bias, C, M, N, K,
                            blockIdx.y * BM, blockIdx.x * BN, smem_raw);
}

// ---------------------------------------------------------------------------
// KA stage-1, HMMA version. Block b in [0,256): slice s = b&3 (64 d each),
// token tile = b>>2 (64 tokens). Computes partial tpsi (no bias/gelu) into
// kapart[s]. phi tiles generated in smem as bf16 hi/lo; 3-split accumulate.
// smem (from tile0): B bufs 2x(8K hi + 8K lo) = 32K | phi hi 8K | phi lo 8K |
//                    xs fp32 64x65 = 16.25K | wps 16K | bps 16K  (~96.3KB)
// ---------------------------------------------------------------------------
__device__ __forceinline__ void
ka_hmma_body(const float* __restrict__ xf, const float* __restrict__ Wphi,
             const float* __restrict__ bphi,
             const __nv_bfloat16* __restrict__ wp1h, const __nv_bfloat16* __restrict__ wp1l,
             float* __restrict__ kapart, int b, char* smem_raw)
{
    const uint32_t base = smem_to_u32(smem_raw);
    const uint32_t tile0 = (base + 1023) & ~1023u;
    char* cbase = smem_raw + (tile0 - base);

    const uint32_t PH = 32768, PL = 40960;
    float* xs  = (float*)(cbase + 49152);   // [64][65]
    float* wps = (float*)(cbase + 65792);   // [64][64]
    float* bps = (float*)(cbase + 82176);   // [64][64]

    const int tid = threadIdx.x;
    const int s   = b & 3;
    const int t0  = (b >> 2) << 6;

    // ---- init loads ----
    {
        int tok = tid >> 2, dq = (tid & 3) << 4;
        const float* xp = xf + (size_t)(t0 + tok) * 256 + (s << 6) + dq;
#pragma unroll
        for (int j = 0; j < 16; j += 4) {
            float4 v = *(const float4*)(xp + j);
            xs[(dq + j + 0) * 65 + tok] = v.x;
            xs[(dq + j + 1) * 65 + tok] = v.y;
            xs[(dq + j + 2) * 65 + tok] = v.z;
            xs[(dq + j + 3) * 65 + tok] = v.w;
        }
        const float4* wsrc = (const float4*)(Wphi + (s << 12));
        const float4* bsrc = (const float4*)(bphi + (s << 12));
        float4* wdst = (float4*)wps;
        float4* bdst = (float4*)bps;
#pragma unroll
        for (int r = 0; r < 4; r++) {
            wdst[tid + (r << 8)] = wsrc[tid + (r << 8)];
            bdst[tid + (r << 8)] = bsrc[tid + (r << 8)];
        }
    }

    auto stageB = [&](int d) {
        const uint32_t dsth = tile0 + (d & 1) * 16384;
        const uint32_t dstl = dsth + 8192;
        const __nv_bfloat16* sh = wp1h + (s << 12) + (d << 6);
        const __nv_bfloat16* sl = wp1l + (s << 12) + (d << 6);
#pragma unroll
        for (int i = 0; i < 2; i++) {
            int u = i * 256 + tid;
            int row = u >> 3, seg = u & 7;
            uint32_t off = SMEM_SWIZZLE_128B((uint32_t)(row * 128 + seg * 16));
            cp_async16(dsth + off, sh + (size_t)row * 16384 + seg * 8);
            cp_async16(dstl + off, sl + (size_t)row * 16384 + seg * 8);
        }
    };

    stageB(0); CP_COMMIT();
    __syncthreads();                       // xs/wps/bps visible

    const int wid = tid >> 5, lane = tid & 31;
    const int wm = wid & 1, wn = wid >> 1;
    const int ptok = tid & 63, hq = tid >> 6;

    float acc[2][2][4];
#pragma unroll
    for (int mf = 0; mf < 2; mf++)
#pragma unroll
        for (int nf = 0; nf < 2; nf++)
#pragma unroll
            for (int i = 0; i < 4; i++) acc[mf][nf][i] = 0.f;

    for (int d = 0; d < 64; d++) {
        if (d + 1 < 64) { stageB(d + 1); CP_COMMIT(); }
        // ---- phi generation (exact gelu, bf16 hi/lo split) ----
        {
            float xv = xs[d * 65 + ptok];
            const float* wr = wps + (d << 6);
            const float* br2 = bps + (d << 6);
#pragma unroll
            for (int j = 0; j < 16; j += 2) {
                int h = (hq << 4) + j;
                float v0 = gelu_f(fmaf(xv, wr[h],     br2[h]));
                float v1 = gelu_f(fmaf(xv, wr[h + 1], br2[h + 1]));
                __nv_bfloat16 h0 = __float2bfloat16(v0);
                __nv_bfloat16 h1 = __float2bfloat16(v1);
                __nv_bfloat162 hp(h0, h1);
                __nv_bfloat162 lp(__float2bfloat16(v0 - __bfloat162float(h0)),
                                  __float2bfloat16(v1 - __bfloat162float(h1)));
                uint32_t off = SMEM_SWIZZLE_128B((uint32_t)(ptok * 128 + h * 2));
                *(__nv_bfloat162*)(cbase + PH + off) = hp;
                *(__nv_bfloat162*)(cbase + PL + off) = lp;
            }
        }
        if (d + 1 < 64) CP_WAIT1(); else CP_WAIT0();
        __syncthreads();                   // phi + B(d) ready
        // ---- 3-split MMA ----
        {
            const uint32_t bh = tile0 + (d & 1) * 16384;
            const uint32_t bl = bh + 8192;
            const uint32_t ah = tile0 + PH, al = tile0 + PL;
#pragma unroll
            for (int k16 = 0; k16 < 4; k16++) {
                uint32_t Ah[2][4], Al[2][4], Bh[2][2], Bl[2][2];
#pragma unroll
                for (int mf = 0; mf < 2; mf++) {
                    int row = wm * 32 + mf * 16 + (lane & 15);
                    uint32_t off = SMEM_SWIZZLE_128B(
                        (uint32_t)(row * 128 + k16 * 32 + ((lane >> 4) << 4)));
                    ldsm_x4(ah + off, Ah[mf][0], Ah[mf][1], Ah[mf][2], Ah[mf][3]);
                    ldsm_x4(al + off, Al[mf][0], Al[mf][1], Al[mf][2], Al[mf][3]);
                }
                {
                    int grp = lane >> 3;
                    int n = wn * 16 + ((grp >> 1) << 3) + (lane & 7);
                    uint32_t off = SMEM_SWIZZLE_128B(
                        (uint32_t)(n * 128 + k16 * 32 + ((grp & 1) << 4)));
                    ldsm_x4(bh + off, Bh[0][0], Bh[0][1], Bh[1][0], Bh[1][1]);
                    ldsm_x4(bl + off, Bl[0][0], Bl[0][1], Bl[1][0], Bl[1][1]);
                }
#pragma unroll
                for (int mf = 0; mf < 2; mf++)
#pragma unroll
                    for (int nf = 0; nf < 2; nf++) {
                        mma16816(acc[mf][nf][0], acc[mf][nf][1], acc[mf][nf][2], acc[mf][nf][3],
                                 Ah[mf][0], Ah[mf][1], Ah[mf][2], Ah[mf][3],
                                 Bh[nf][0], Bh[nf][1]);
                        mma16816(acc[mf][nf][0], acc[mf][nf][1], acc[mf][nf][2], acc[mf][nf][3],
                                 Al[mf][0], Al[mf][1], Al[mf][2], Al[mf][3],
                                 Bh[nf][0], Bh[nf][1]);
                        mma16816(acc[mf][nf][0], acc[mf][nf][1], acc[mf][nf][2], acc[mf][nf][3],
                                 Ah[mf][0], Ah[mf][1], Ah[mf][2], Ah[mf][3],
                                 Bl[nf][0], Bl[nf][1]);
                    }
            }
        }
        __syncthreads();                   // mma done before phi/B overwrite
    }

    // ---- epilogue: partial (no bias) ----
    float* pout = kapart + (size_t)s * (NTOK * HIDD) + (size_t)t0 * HIDD;
#pragma unroll
    for (int mf = 0; mf < 2; mf++)
#pragma unroll
        for (int nf = 0; nf < 2; nf++) {
            int row = wm * 32 + mf * 16 + (lane >> 2);
            int col = wn * 16 + nf * 8 + ((lane & 3) << 1);
            *(float2*)&pout[(size_t)row * HIDD + col] =
                make_float2(acc[mf][nf][0], acc[mf][nf][1]);
            *(float2*)&pout[(size_t)(row + 8) * HIDD + col] =
                make_float2(acc[mf][nf][2], acc[mf][nf][3]);
        }
}

// ---------------------------------------------------------------------------
// Fused kernels
// ---------------------------------------------------------------------------
__global__ void __launch_bounds__(256, 2)
fused_mix_ka(const __nv_bfloat16* __restrict__ xh, const __nv_bfloat16* __restrict__ xl,
             const __nv_bfloat16* __restrict__ wdh, const __nv_bfloat16* __restrict__ wdl,
             const float* __restrict__ bcat, float* __restrict__ mix,
             const float* __restrict__ xf, const float* __restrict__ Wphi,
             const float* __restrict__ bphi,
             const __nv_bfloat16* __restrict__ wp1h, const __nv_bfloat16* __restrict__ wp1l,
             float* __restrict__ kapart)
{
    extern __shared__ char smem_raw[];
    const int bid = blockIdx.x;
    if (bid < 384) {
        gemm_body<128, 128, false>(xh, xl, wdh, wdl, bcat, mix,
                                   NTOK, DSUM, DDIM,
                                   (bid / 12) * 128, (bid % 12) * 128, smem_raw);
    } else {
        ka_hmma_body(xf, Wphi, bphi, wp1h, wp1l, kapart, bid - 384, smem_raw);
    }
}

__global__ void __launch_bounds__(256, 2)
fused_resid_h(const __nv_bfloat16* __restrict__ cth, const __nv_bfloat16* __restrict__ ctl,
              const __nv_bfloat16* __restrict__ wrh, const __nv_bfloat16* __restrict__ wrl,
              const float* __restrict__ bres, float* __restrict__ resid,
              const __nv_bfloat16* __restrict__ w1h, const __nv_bfloat16* __restrict__ w1l,
              const float* __restrict__ b1, float* __restrict__ hbuf)
{
    extern __shared__ char smem_raw[];
    const int bid = blockIdx.x;
    if (bid < 384) {
        gemm_body<128, 128, false>(cth, ctl, wrh, wrl, bres, resid,
                                   NTOK, DSUM, DSUM,
                                   (bid / 12) * 128, (bid % 12) * 128, smem_raw);
    } else {
        gemm_body<64, 64, true>(cth, ctl, w1h, w1l, b1, hbuf,
                                NTOK, HIDD, DSUM,
                                (bid - 384) * 64, 0, smem_raw);
    }
}

// ---------------------------------------------------------------------------
// am = mean over tokens of adapt
// ---------------------------------------------------------------------------
__global__ void colsum_part_kernel(const float* __restrict__ adapt, float* __restrict__ part)
{
    const int j = threadIdx.x;
    const int b = blockIdx.x;
    float s = 0.f;
#pragma unroll 8
    for (int r = 0; r < 128; r++) s += adapt[(size_t)(b * 128 + r) * ADIM + j];
    part[b * ADIM + j] = s;
}
__global__ void colsum_fin_kernel(const float* __restrict__ part, float* __restrict__ am)
{
    const int j = threadIdx.x;
    float s = 0.f;
#pragma unroll
    for (int b = 0; b < 32; b++) s += part[b * ADIM + j];
    am[j] = s * (1.0f / (float)NTOK);
}

// ---------------------------------------------------------------------------
// Dynamic weights
// ---------------------------------------------------------------------------
__global__ void dynw_kernel(const float* __restrict__ Wt,  const float* __restrict__ Wt_a, const float* __restrict__ bt_a,
                            const float* __restrict__ Wc,  const float* __restrict__ Wc_a, const float* __restrict__ bc_a,
                            const float* __restrict__ We,  const float* __restrict__ We_a, const float* __restrict__ be_a,
                            const float* __restrict__ am,  float* __restrict__ Wdyn)
{
    __shared__ float ams[ADIM];
    const int tid = threadIdx.x;
    if (tid < ADIM) ams[tid] = am[tid];
    __syncthreads();

    const int idx4 = blockIdx.x * 256 + tid;
    const int k    = idx4 / 384;
    const int c4   = (idx4 - k * 384) * 4;

    const float *Wa, *ba, *base;
    int m;
    if (c4 < 256)      { m = k * 256 + c4;          base = Wt; Wa = Wt_a; ba = bt_a; }
    else if (c4 < 512) { m = k * 256 + (c4 - 256);  base = Wc; Wa = Wc_a; ba = bc_a; }
    else {
        int e  = (c4 - 512) >> 8;
        int jj = (c4 - 512) & 255;
        m = k * 256 + jj;
        base = We + e * 65536;
        Wa   = We_a + (size_t)e * 8388608u;
        ba   = be_a + e * 65536;
    }
    float4 acc = *(const float4*)(base + m);
    float4 b4  = *(const float4*)(ba + m);
    acc.x += b4.x; acc.y += b4.y; acc.z += b4.z; acc.w += b4.w;
#pragma unroll 4
    for (int a = 0; a < ADIM; a++) {
        float s = ams[a];
        float4 w = *(const float4*)(Wa + (size_t)a * 65536 + m);
        acc.x = fmaf(s, w.x, acc.x);
        acc.y = fmaf(s, w.y, acc.y);
        acc.z = fmaf(s, w.z, acc.z);
        acc.w = fmaf(s, w.w, acc.w);
    }
    *(float4*)(Wdyn + (size_t)idx4 * 4) = acc;
}

// ---------------------------------------------------------------------------
// gate = softmax(adapt @ Wg + bg)
// ---------------------------------------------------------------------------
__global__ void gate_kernel(const float* __restrict__ adapt, const float* __restrict__ Wg,
                            const float* __restrict__ bg, float* __restrict__ gate)
{
    __shared__ float wgs[ADIM * 5];
    __shared__ float bgs[5];
    const int tid = threadIdx.x;
    for (int i = tid; i < ADIM * 5; i += 256) wgs[i] = Wg[i];
    if (tid < 5) bgs[tid] = bg[tid];
    __syncthreads();

    const int warp = tid >> 5, lane = tid & 31;
    const int n = (blockIdx.x << 3) + warp;

    float4 a4 = *(const float4*)(adapt + (size_t)n * ADIM + lane * 4);
    float av[4] = { a4.x, a4.y, a4.z, a4.w };
    float l[5] = { 0, 0, 0, 0, 0 };
#pragma unroll
    for (int q = 0; q < 4; q++) {
        int a = lane * 4 + q;
#pragma unroll
        for (int j = 0; j < 5; j++) l[j] = fmaf(av[q], wgs[a * 5 + j], l[j]);
    }
#pragma unroll
    for (int off = 16; off; off >>= 1)
#pragma unroll
        for (int j = 0; j < 5; j++) l[j] += __shfl_xor_sync(0xffffffffu, l[j], off);

    if (lane == 0) {
#pragma unroll
        for (int j = 0; j < 5; j++) l[j] += bgs[j];
        float mx = fmaxf(fmaxf(fmaxf(l[0], l[1]), fmaxf(l[2], l[3])), l[4]);
        float s = 0.f;
#pragma unroll
        for (int j = 0; j < 5; j++) { l[j] = __expf(l[j] - mx); s += l[j]; }
        float inv = 1.0f / s;
#pragma unroll
        for (int j = 0; j < 5; j++) gate[n * 5 + j] = l[j] * inv;
    }
}

// tpsi = gelu(sum of 4 partials + bpsi1) -> bf16 hi/lo
__global__ void ka_finish_kernel(const float* __restrict__ part,
                                 const float* __restrict__ bpsi1,
                                 __nv_bfloat16* __restrict__ tph,
                                 __nv_bfloat16* __restrict__ tpl)
{
    const int idx = blockIdx.x * 256 + threadIdx.x;     // float4 idx, 65536 total
    const int jq = idx & 15;
    const float4* p = (const float4*)part;
    float4 a = p[idx];
    float4 b = p[65536 + idx];
    float4 c = p[131072 + idx];
    float4 d = p[196608 + idx];
    float4 bb = ((const float4*)bpsi1)[jq];
    float o[4];
    o[0] = gelu_f(a.x + b.x + c.x + d.x + bb.x);
    o[1] = gelu_f(a.y + b.y + c.y + d.y + bb.y);
    o[2] = gelu_f(a.z + b.z + c.z + d.z + bb.z);
    o[3] = gelu_f(a.w + b.w + c.w + d.w + bb.w);
#pragma unroll
    for (int q = 0; q < 4; q++) split_store(o[q], tph + idx * 4 + q, tpl + idx * 4 + q);
}

// ---------------------------------------------------------------------------
// concat[n] = [tok, chan, moe, lf]; also emits bf16 hi/lo
// ---------------------------------------------------------------------------
__global__ void concat_kernel(const float* __restrict__ mix, const float* __restrict__ gate,
                              const float* __restrict__ ka, const float* __restrict__ lf,
                              float* __restrict__ concat,
                              __nv_bfloat16* __restrict__ cth, __nv_bfloat16* __restrict__ ctl)
{
    const int n = blockIdx.x;
    const int t = threadIdx.x;
    __shared__ float g[5];
    if (t < 5) g[t] = gate[n * 5 + t];
    __syncthreads();

    const float4* mx = (const float4*)(mix + (size_t)n * DSUM);
    float4 out;
    if (t < 128) {
        out = mx[t];
    } else if (t < 192) {
        int dq = t - 128;
        float4 e0 = mx[128 + dq], e1 = mx[192 + dq], e2 = mx[256 + dq], e3 = mx[320 + dq];
        float4 k4 = ((const float4*)(ka + (size_t)n * DDIM))[dq];
        out.x = g[0]*e0.x + g[1]*e1.x + g[2]*e2.x + g[3]*e3.x + g[4]*k4.x;
        out.y = g[0]*e0.y + g[1]*e1.y + g[2]*e2.y + g[3]*e3.y + g[4]*k4.y;
        out.z = g[0]*e0.z + g[1]*e1.z + g[2]*e2.z + g[3]*e3.z + g[4]*k4.z;
        out.w = g[0]*e0.w + g[1]*e1.w + g[2]*e2.w + g[3]*e3.w + g[4]*k4.w;
    } else {
        out = ((const float4*)(lf + (size_t)n * DLF))[t - 192];
    }
    ((float4*)(concat + (size_t)n * DSUM))[t] = out;
    const size_t e = (size_t)n * DSUM + t * 4;
    split_store(out.x, cth + e + 0, ctl + e + 0);
    split_store(out.y, cth + e + 1, ctl + e + 1);
    split_store(out.z, cth + e + 2, ctl + e + 2);
    split_store(out.w, cth + e + 3, ctl + e + 3);
}

// ---------------------------------------------------------------------------
// combine: cw = softmax(h @ W2 + b2); comb = cw[sec]*concat + resid (bf16 out)
// ---------------------------------------------------------------------------
__global__ void combine_kernel(const float* __restrict__ h, const float* __restrict__ W2,
                               const float* __restrict__ b2, const float* __restrict__ concat,
                               const float* __restrict__ resid,
                               __nv_bfloat16* __restrict__ cbh, __nv_bfloat16* __restrict__ cbl)
{
    __shared__ float w2s[256];
    const int tid = threadIdx.x;
    w2s[tid] = W2[tid];
    __syncthreads();

    const int warp = tid >> 5, lane = tid & 31;
    const int n = (blockIdx.x << 3) + warp;

    float2 hv = *(const float2*)(h + (size_t)n * HIDD + lane * 2);
    const int a0 = lane * 2, a1 = lane * 2 + 1;
    float l0 = hv.x * w2s[a0*4+0] + hv.y * w2s[a1*4+0];
    float l1 = hv.x * w2s[a0*4+1] + hv.y * w2s[a1*4+1];
    float l2 = hv.x * w2s[a0*4+2] + hv.y * w2s[a1*4+2];
    float l3 = hv.x * w2s[a0*4+3] + hv.y * w2s[a1*4+3];
#pragma unroll
    for (int off = 16; off; off >>= 1) {
        l0 += __shfl_xor_sync(0xffffffffu, l0, off);
        l1 += __shfl_xor_sync(0xffffffffu, l1, off);
        l2 += __shfl_xor_sync(0xffffffffu, l2, off);
        l3 += __shfl_xor_sync(0xffffffffu, l3, off);
    }
    l0 += __ldg(b2 + 0); l1 += __ldg(b2 + 1); l2 += __ldg(b2 + 2); l3 += __ldg(b2 + 3);
    float mx = fmaxf(fmaxf(l0, l1), fmaxf(l2, l3));
    float e0 = __expf(l0 - mx), e1 = __expf(l1 - mx), e2 = __expf(l2 - mx), e3 = __expf(l3 - mx);
    float inv = 1.0f / (e0 + e1 + e2 + e3);
    float cw0 = e0 * inv, cw1 = e1 * inv, cw2 = e2 * inv, cw3 = e3 * inv;

    const float4* cc = (const float4*)(concat + (size_t)n * DSUM);
    const float4* rr = (const float4*)(resid  + (size_t)n * DSUM);
#pragma unroll
    for (int q = 0; q < 12; q++) {
        int c4 = lane + (q << 5);
        float w = (c4 < 64) ? cw0 : (c4 < 128) ? cw1 : (c4 < 192) ? cw2 : cw3;
        float4 cv = cc[c4], rv = rr[c4];
        float v0 = fmaf(w, cv.x, rv.x), v1 = fmaf(w, cv.y, rv.y);
        float v2 = fmaf(w, cv.z, rv.z), v3 = fmaf(w, cv.w, rv.w);
        const size_t e = (size_t)n * DSUM + c4 * 4;
        split_store(v0, cbh + e + 0, cbl + e + 0);
        split_store(v1, cbh + e + 1, cbl + e + 1);
        split_store(v2, cbh + e + 2, cbl + e + 2);
        split_store(v3, cbh + e + 3, cbl + e + 3);
    }
}

// ---------------------------------------------------------------------------
// Host launcher
// ---------------------------------------------------------------------------
extern "C" void kernel_launch(void* const* d_in, const int* in_sizes, int n_in,
                              void* d_out, int out_size)
{
    (void)in_sizes; (void)n_in; (void)out_size;

    const float* x      = (const float*)d_in[0];
    const float* lf     = (const float*)d_in[1];
    const float* W_feat = (const float*)d_in[2];
    const float* b_feat = (const float*)d_in[3];
    const float* Wt     = (const float*)d_in[4];
    const float* bt     = (const float*)d_in[5];
    const float* Wt_a   = (const float*)d_in[6];
    const float* bt_a   = (const float*)d_in[7];
    const float* Wc     = (const float*)d_in[8];
    const float* bc     = (const float*)d_in[9];
    const float* Wc_a   = (const float*)d_in[10];
    const float* bc_a   = (const float*)d_in[11];
    const float* We     = (const float*)d_in[12];
    const float* be     = (const float*)d_in[13];
    const float* We_a   = (const float*)d_in[14];
    const float* be_a   = (const float*)d_in[15];
    const float* Wg     = (const float*)d_in[16];
    const float* bg     = (const float*)d_in[17];
    const float* Wphi   = (const float*)d_in[18];
    const float* bphi   = (const float*)d_in[19];
    const float* Wpsi1  = (const float*)d_in[20];
    const float* bpsi1  = (const float*)d_in[21];
    const float* Wpsi2  = (const float*)d_in[22];
    const float* bpsi2  = (const float*)d_in[23];
    const float* Wres   = (const float*)d_in[24];
    const float* bres   = (const float*)d_in[25];
    const float* W1     = (const float*)d_in[26];
    const float* b1     = (const float*)d_in[27];
    const float* W2     = (const float*)d_in[28];
    const float* b2     = (const float*)d_in[29];
    const float* Wo     = (const float*)d_in[30];
    const float* bo     = (const float*)d_in[31];
    float* out = (float*)d_out;

    float* s = nullptr;
    cudaGetSymbolAddress((void**)&s, g_scratch);
    float* adapt  = s + OFF_ADAPT;
    float* am     = s + OFF_AM;
    float* part   = s + OFF_PART;
    float* gate   = s + OFF_GATE;
    float* Wdyn   = s + OFF_WDYN;
    float* bcat   = s + OFF_BCAT;
    float* mix    = s + OFF_MIX;
    float* ka     = s + OFF_KA;
    float* concat = s + OFF_CONCAT;
    float* resid  = s + OFF_RESID;
    float* hbuf   = s + OFF_H;
    float* kapart = s + OFF_KAPART;

    __nv_bfloat16* bb = (__nv_bfloat16*)(s + OFF_BF16);
    __nv_bfloat16 *xh = bb + BF_XH,   *xl = bb + BF_XL;
    __nv_bfloat16 *wfh = bb + BF_WFH, *wfl = bb + BF_WFL;
    __nv_bfloat16 *wdh = bb + BF_WDH, *wdl = bb + BF_WDL;
    __nv_bfloat16 *tph = bb + BF_TPH, *tpl = bb + BF_TPL;
    __nv_bfloat16 *wph = bb + BF_WPH, *wpl = bb + BF_WPL;
    __nv_bfloat16 *cth = bb + BF_CATH, *ctl = bb + BF_CATL;
    __nv_bfloat16 *wrh = bb + BF_WRH, *wrl = bb + BF_WRL;
    __nv_bfloat16 *w1h = bb + BF_W1H, *w1l = bb + BF_W1L;
    __nv_bfloat16 *cbh = bb + BF_CBH, *cbl = bb + BF_CBL;
    __nv_bfloat16 *woh = bb + BF_WOH, *wol = bb + BF_WOL;
    __nv_bfloat16 *wp1h = bb + BF_WP1H, *wp1l = bb + BF_WP1L;

    const int SM_BIG   = 3 * (16384 + 16384) + 1024;  // 99328 (128x128 / fused_resid_h)
    const int SM_FUSED = 100352;                       // fused_mix_ka (ka needs 98.5K)
    const int SM_6464  = 3 * (8192 + 8192) + 1024;     // 50176
    cudaFuncSetAttribute(gemm_hmma<64, 64, false>, cudaFuncAttributeMaxDynamicSharedMemorySize, SM_6464);
    cudaFuncSetAttribute(fused_mix_ka,  cudaFuncAttributeMaxDynamicSharedMemorySize, SM_FUSED);
    cudaFuncSetAttribute(fused_resid_h, cudaFuncAttributeMaxDynamicSharedMemorySize, SM_BIG);

    // 1. x split
    split_kernel<<<1024, 256>>>(x, xh, xl);
    // 2. W_feat + Wpsi2 tsplit + bcat
    prep2_kernel<<<54, 256>>>(W_feat, wfh, wfl, Wpsi2, wph, wpl, bt, bc, be, bcat);
    // 3. Wres + W1 + Wo + Wpsi1^T tsplit
    prep3_kernel<<<3808, 256>>>(Wres, wrh, wrl, W1, w1h, w1l, Wo, woh, wol,
                                Wpsi1, wp1h, wp1l);
    // 4. adapt GEMM  [4096,128]   <-- ncu window
    gemm_hmma<64, 64, false><<<dim3(2, 64), 256, SM_6464>>>(xh, xl, wfh, wfl, b_feat, adapt, NTOK, ADIM, DDIM);
    // 5-6. am
    colsum_part_kernel<<<32, 128>>>(adapt, part);
    colsum_fin_kernel<<<1, 128>>>(part, am);
    // 7-8. dynamic weights + transpose-split
    dynw_kernel<<<384, 256>>>(Wt, Wt_a, bt_a, Wc, Wc_a, bc_a, We, We_a, be_a, am, Wdyn);
    tsplit_kernel<<<384, 256>>>(Wdyn, wdh, wdl, DDIM, DSUM);
    // 9. gate softmax
    gate_kernel<<<NTOK / 8, 256>>>(adapt, Wg, bg, gate);
    // 10. FUSED: mix GEMM (384) + KA stage 1 HMMA (256 blocks, 4-way k-split)
    fused_mix_ka<<<640, 256, SM_FUSED>>>(xh, xl, wdh, wdl, bcat, mix,
                                         x, Wphi, bphi, wp1h, wp1l, kapart);
    // 11. KA finish (sum 4 partials, gelu, bf16 hi/lo)
    ka_finish_kernel<<<256, 256>>>(kapart, bpsi1, tph, tpl);
    // 12. ka = tpsi @ Wpsi2 + bpsi2  [4096,256]
    gemm_hmma<64, 64, false><<<dim3(4, 64), 256, SM_6464>>>(tph, tpl, wph, wpl, bpsi2, ka, NTOK, DDIM, HIDD);
    // 13. concat (+ bf16 hi/lo)
    concat_kernel<<<NTOK, 384>>>(mix, gate, ka, lf, concat, cth, ctl);
    // 14. FUSED: resid GEMM (384) + h GEMM (64)
    fused_resid_h<<<448, 256, SM_BIG>>>(cth, ctl, wrh, wrl, bres, resid,
                                        w1h, w1l, b1, hbuf);
    // 15. combine (bf16 hi/lo)
    combine_kernel<<<NTOK / 8, 256>>>(hbuf, W2, b2, concat, resid, cbh, cbl);
    // 16. out = comb @ Wo + bo  [4096,256]
    gemm_hmma<64, 64, false><<<dim3(4, 64), 256, SM_6464>>>(cbh, cbl, woh, wol, bo, out, NTOK, DDIM, DSUM);
}